// round 12
// baseline (speedup 1.0000x reference)
#include <cuda_runtime.h>
#include <cuda_bf16.h>
#include <math.h>
#include <stdint.h>

// Problem constants
#define BB 2
#define LL 2048
#define DD 2048
#define NHEADS 16
#define KHEADS 8
#define HDIM 128
#define TOK (BB * LL)        // 4096
#define EPSV 1e-6f
#define QKVW 4096            // concatenated qkv col space (q:0..2047, k:..3071, v:..4095)

// ---------------------------------------------------------------------------
// Scratch (device globals — no runtime allocation allowed)
// ---------------------------------------------------------------------------
__device__ __align__(16) __nv_bfloat16 g_xhi[(size_t)TOK * DD];
__device__ __align__(16) __nv_bfloat16 g_xlo[(size_t)TOK * DD];
__device__ __align__(16) __nv_bfloat16 g_qhi[(size_t)TOK * DD];     // normed/rope'd/pre-scaled q
__device__ __align__(16) __nv_bfloat16 g_qlo[(size_t)TOK * DD];
__device__ __align__(16) __nv_bfloat16 g_khi[(size_t)TOK * KHEADS * HDIM];
__device__ __align__(16) __nv_bfloat16 g_klo[(size_t)TOK * KHEADS * HDIM];
__device__ __align__(16) __nv_bfloat16 g_vhi[(size_t)TOK * KHEADS * HDIM];
__device__ __align__(16) __nv_bfloat16 g_vlo[(size_t)TOK * KHEADS * HDIM];
__device__ __align__(16) __nv_bfloat16 g_ohi[(size_t)TOK * DD];     // attention out
__device__ __align__(16) __nv_bfloat16 g_olo[(size_t)TOK * DD];
__device__ __align__(16) __nv_bfloat16 g_wthi[(size_t)QKVW * DD];   // [n][k] qkv weights
__device__ __align__(16) __nv_bfloat16 g_wtlo[(size_t)QKVW * DD];
__device__ __align__(16) __nv_bfloat16 g_wothi[(size_t)DD * DD];    // [n][k] wo
__device__ __align__(16) __nv_bfloat16 g_wotlo[(size_t)DD * DD];
__device__ __align__(16) float g_rsin[(size_t)TOK * 64];            // rope tables
__device__ __align__(16) float g_rcos[(size_t)TOK * 64];

extern __shared__ char dyn_smem[];

// ---------------------------------------------------------------------------
// PTX helpers (family-portable: cp.async / ldmatrix / mma.sync)
// ---------------------------------------------------------------------------
__device__ __forceinline__ uint32_t smem_u32(const void* p) {
    uint32_t a;
    asm("{ .reg .u64 t; cvta.to.shared.u64 t, %1; cvt.u32.u64 %0, t; }"
        : "=r"(a) : "l"(p));
    return a;
}

__device__ __forceinline__ void cp16(uint32_t dst, const void* src) {
    asm volatile("cp.async.cg.shared.global [%0], [%1], 16;" :: "r"(dst), "l"(src));
}
#define CP_COMMIT() asm volatile("cp.async.commit_group;" ::: "memory")
#define CP_WAIT(N)  asm volatile("cp.async.wait_group %0;" :: "n"(N) : "memory")

__device__ __forceinline__ void ldsm4(uint32_t* r, uint32_t a) {
    asm volatile("ldmatrix.sync.aligned.m8n8.x4.shared.b16 {%0,%1,%2,%3}, [%4];"
        : "=r"(r[0]), "=r"(r[1]), "=r"(r[2]), "=r"(r[3]) : "r"(a));
}
__device__ __forceinline__ void ldsm4t(uint32_t* r, uint32_t a) {
    asm volatile("ldmatrix.sync.aligned.m8n8.x4.trans.shared.b16 {%0,%1,%2,%3}, [%4];"
        : "=r"(r[0]), "=r"(r[1]), "=r"(r[2]), "=r"(r[3]) : "r"(a));
}

__device__ __forceinline__ void mma_bf16(float* c, const uint32_t* a, const uint32_t* b) {
    asm volatile(
        "mma.sync.aligned.m16n8k16.row.col.f32.bf16.bf16.f32 "
        "{%0,%1,%2,%3}, {%4,%5,%6,%7}, {%8,%9}, {%0,%1,%2,%3};"
        : "+f"(c[0]), "+f"(c[1]), "+f"(c[2]), "+f"(c[3])
        : "r"(a[0]), "r"(a[1]), "r"(a[2]), "r"(a[3]), "r"(b[0]), "r"(b[1]));
}

__device__ __forceinline__ uint32_t pack_bf2(float x, float y) {
    __nv_bfloat162 t;
    t.x = __float2bfloat16(x);
    t.y = __float2bfloat16(y);
    return *(uint32_t*)&t;
}

// ---------------------------------------------------------------------------
// Conversion / table kernels
// ---------------------------------------------------------------------------
__global__ void __launch_bounds__(256) transpose_convert_all_kernel(
    const float* __restrict__ wq, const float* __restrict__ wk,
    const float* __restrict__ wv, const float* __restrict__ wo)
{
    const int z = blockIdx.z;
    const float* src;
    int C, row_off;
    __nv_bfloat16 *dhi, *dlo;
    if (z == 0)      { src = wq; C = 2048; row_off = 0;    dhi = g_wthi;  dlo = g_wtlo;  }
    else if (z == 1) { if (blockIdx.x >= 32) return;
                       src = wk; C = 1024; row_off = 2048; dhi = g_wthi;  dlo = g_wtlo;  }
    else if (z == 2) { if (blockIdx.x >= 32) return;
                       src = wv; C = 1024; row_off = 3072; dhi = g_wthi;  dlo = g_wtlo;  }
    else             { src = wo; C = 2048; row_off = 0;    dhi = g_wothi; dlo = g_wotlo; }

    __shared__ float t[32][33];
    const int c0 = blockIdx.x * 32;
    const int r0 = blockIdx.y * 32;
    const int tx = threadIdx.x;
    const int ty = threadIdx.y;

#pragma unroll
    for (int j = 0; j < 4; j++)
        t[ty + j * 8][tx] = src[(size_t)(r0 + ty + j * 8) * C + c0 + tx];
    __syncthreads();

#pragma unroll
    for (int j = 0; j < 4; j++) {
        const int i = ty + j * 8;
        const float v = t[tx][i];
        const __nv_bfloat16 h = __float2bfloat16(v);
        const __nv_bfloat16 l = __float2bfloat16(v - __bfloat162float(h));
        const size_t off = (size_t)(row_off + c0 + i) * DD + r0 + tx;
        dhi[off] = h;
        dlo[off] = l;
    }
}

__global__ void __launch_bounds__(256) convert_split_x_kernel(const float* __restrict__ src)
{
    const size_t i = (size_t)blockIdx.x * blockDim.x + threadIdx.x;
    const size_t n4 = (size_t)TOK * DD / 4;
    if (i >= n4) return;
    const float4 v = ((const float4*)src)[i];
    __nv_bfloat16 h0 = __float2bfloat16(v.x);
    __nv_bfloat16 h1 = __float2bfloat16(v.y);
    __nv_bfloat16 h2 = __float2bfloat16(v.z);
    __nv_bfloat16 h3 = __float2bfloat16(v.w);
    uint2 hp, lp;
    hp.x = pack_bf2(v.x, v.y);
    hp.y = pack_bf2(v.z, v.w);
    lp.x = pack_bf2(v.x - __bfloat162float(h0), v.y - __bfloat162float(h1));
    lp.y = pack_bf2(v.z - __bfloat162float(h2), v.w - __bfloat162float(h3));
    ((uint2*)g_xhi)[i] = hp;
    ((uint2*)g_xlo)[i] = lp;
}

// RoPE tables: sin/cos per (token, freq-pair). One-time, full-precision.
__global__ void __launch_bounds__(256) rope_table_kernel(const int* __restrict__ pos_ids)
{
    const int idx = blockIdx.x * 256 + threadIdx.x;
    if (idx >= TOK * 64) return;
    const int token = idx >> 6;
    const int p = idx & 63;
    const double L2T = 19.931568569324174;   // log2(1e6)
    const float inv_ts = exp2f((float)(-(double)p * L2T / 64.0));
    const float ang = (float)pos_ids[token] * inv_ts;
    float sv, cv;
    sincosf(ang, &sv, &cv);
    g_rsin[idx] = sv;
    g_rcos[idx] = cv;
}

// ---------------------------------------------------------------------------
// split-bf16 warp-MMA GEMM (R9 tile, PERSISTENT CTAs): C = A * B^T
//   CTA tile 128x128, BK=32, 256 threads, 8 warps (2m x 4n), warp tile 64x32.
//   XOR-swizzled 64B pitch, 3-stage cp.async ring, 2 CTAs/SM, product-major.
//   Grid = 2 x numSMs; each CTA loops over tiles (kills wave-tail loss).
// ---------------------------------------------------------------------------
#define BK 32
#define PITCH 64
#define MAT_BYTES (128 * PITCH)           // 8192 per split
#define STAGE_BYTES (4 * MAT_BYTES)       // 32768
#define GEMM_SMEM_BYTES (3 * STAGE_BYTES) // 98304 (x2 CTAs = 196KB)
#define EPI_PITCH 132                     // fp32 words per row in epilogue buffer

__device__ __forceinline__ uint32_t gswz(int r, int c) {
    return (uint32_t)(r * PITCH + ((c ^ ((r >> 1) & 3)) << 4));
}

__device__ __forceinline__ void prefetch_stage(
    uint32_t sbase,
    const __nv_bfloat16* __restrict__ Ahi, const __nv_bfloat16* __restrict__ Alo,
    const __nv_bfloat16* __restrict__ Bhi, const __nv_bfloat16* __restrict__ Blo,
    int m0, int n0, int k0, int ldA, int ldB, int tid)
{
#pragma unroll
    for (int j = 0; j < 2; j++) {
        const int id = tid * 2 + j;
        const int r = id >> 2;
        const int c = id & 3;
        const uint32_t soff = gswz(r, c);
        const size_t ga = (size_t)(m0 + r) * ldA + k0 + c * 8;
        const size_t gb = (size_t)(n0 + r) * ldB + k0 + c * 8;
        cp16(sbase + soff,                 Ahi + ga);
        cp16(sbase + MAT_BYTES + soff,     Alo + ga);
        cp16(sbase + 2 * MAT_BYTES + soff, Bhi + gb);
        cp16(sbase + 3 * MAT_BYTES + soff, Blo + gb);
    }
}

template <int FUSED, int NTX, int NTILES>
__device__ __forceinline__ void gemm_bf16x3_body(
    const __nv_bfloat16* __restrict__ Ahi, const __nv_bfloat16* __restrict__ Alo,
    const __nv_bfloat16* __restrict__ Bhi, const __nv_bfloat16* __restrict__ Blo,
    float* __restrict__ Cc, int ldC,
    const float* __restrict__ qnw, const float* __restrict__ knw)
{
    const int tid  = threadIdx.x;             // 256 threads
    const int lane = tid & 31;
    const int wid  = tid >> 5;                // 0..7
    const int wm   = wid & 1;
    const int wn   = wid >> 1;
    const uint32_t smem_base = smem_u32(dyn_smem);

    const int a_row  = wm * 64 + (lane & 15);
    const int a_swz  = (a_row >> 1) & 3;
    const uint32_t a_base = (uint32_t)(a_row * PITCH);
    const int a_c0   = lane >> 4;
    const int b_row  = wn * 32 + (lane & 7) + ((lane >> 4) << 3);
    const int b_swz  = (b_row >> 1) & 3;
    const uint32_t b_base = (uint32_t)(b_row * PITCH);
    const int b_c0   = (lane >> 3) & 1;
    const int gr = lane >> 2;
    const int gc = (lane & 3) * 2;

    for (int t = blockIdx.x; t < NTILES; t += gridDim.x) {
        const int m0 = (t / NTX) * 128;
        const int n0 = (t % NTX) * 128;

        __syncthreads();   // previous tile's smem reads complete

        float c[4][4][4];
#pragma unroll
        for (int i = 0; i < 4; i++)
#pragma unroll
            for (int j = 0; j < 4; j++)
#pragma unroll
                for (int k = 0; k < 4; k++) c[i][j][k] = 0.f;

        const int nk = DD / BK;

        prefetch_stage(smem_base, Ahi, Alo, Bhi, Blo, m0, n0, 0, DD, DD, tid);
        CP_COMMIT();
        prefetch_stage(smem_base + STAGE_BYTES, Ahi, Alo, Bhi, Blo, m0, n0, BK, DD, DD, tid);
        CP_COMMIT();

        int slot = 0;
        for (int it = 0; it < nk; it++) {
            if (it < nk - 1) { CP_WAIT(1); } else { CP_WAIT(0); }
            __syncthreads();

            if (it + 2 < nk) {
                int ps = slot + 2;
                if (ps >= 3) ps -= 3;
                prefetch_stage(smem_base + ps * STAGE_BYTES,
                               Ahi, Alo, Bhi, Blo, m0, n0, (it + 2) * BK, DD, DD, tid);
                CP_COMMIT();
            }

            const uint32_t sA = smem_base + slot * STAGE_BYTES;
            const uint32_t sB = sA + 2 * MAT_BYTES;

#pragma unroll
            for (int kf = 0; kf < 2; kf++) {
                uint32_t b[2][2][4];
                const uint32_t a_coff = (uint32_t)(((a_c0 + kf * 2) ^ a_swz) << 4);
                const uint32_t b_coff = (uint32_t)(((b_c0 + kf * 2) ^ b_swz) << 4);
#pragma unroll
                for (int nf2 = 0; nf2 < 2; nf2++) {
                    const uint32_t bd = sB + b_base + nf2 * (16 * PITCH) + b_coff;
                    ldsm4(b[0][nf2], bd);
                    ldsm4(b[1][nf2], bd + MAT_BYTES);
                }
#pragma unroll
                for (int mf = 0; mf < 4; mf++) {
                    uint32_t ah[4], al[4];
                    const uint32_t ad = sA + a_base + mf * (16 * PITCH) + a_coff;
                    ldsm4(ah, ad);
                    ldsm4(al, ad + MAT_BYTES);
#pragma unroll
                    for (int nf = 0; nf < 4; nf++)
                        mma_bf16(c[mf][nf], ah, &b[0][nf >> 1][(nf & 1) * 2]);
#pragma unroll
                    for (int nf = 0; nf < 4; nf++)
                        mma_bf16(c[mf][nf], ah, &b[1][nf >> 1][(nf & 1) * 2]);
#pragma unroll
                    for (int nf = 0; nf < 4; nf++)
                        mma_bf16(c[mf][nf], al, &b[0][nf >> 1][(nf & 1) * 2]);
                }
            }

            if (++slot == 3) slot = 0;
        }

        if (FUSED == 0) {
            const int row0 = m0 + wm * 64;
            const int col0 = n0 + wn * 32;
#pragma unroll
            for (int mf = 0; mf < 4; mf++)
#pragma unroll
                for (int nf = 0; nf < 4; nf++) {
                    float* cc = c[mf][nf];
                    const int r = row0 + mf * 16 + gr;
                    const int cl = col0 + nf * 8 + gc;
                    *(float2*)&Cc[(size_t)r * ldC + cl]       = make_float2(cc[0], cc[1]);
                    *(float2*)&Cc[(size_t)(r + 8) * ldC + cl] = make_float2(cc[2], cc[3]);
                }
            continue;
        }

        // --- FUSED epilogue: SMEM bounce + RMSNorm + RoPE + hi/lo split ---
        float* Sb = (float*)dyn_smem;
        __syncthreads();
        {
            const int row0 = wm * 64;
            const int col0 = wn * 32;
#pragma unroll
            for (int mf = 0; mf < 4; mf++)
#pragma unroll
                for (int nf = 0; nf < 4; nf++) {
                    float* cc = c[mf][nf];
                    const int r = row0 + mf * 16 + gr;
                    const int cl = col0 + nf * 8 + gc;
                    *(float2*)&Sb[r * EPI_PITCH + cl]       = make_float2(cc[0], cc[1]);
                    *(float2*)&Sb[(r + 8) * EPI_PITCH + cl] = make_float2(cc[2], cc[3]);
                }
        }
        __syncthreads();

        const bool isq = (n0 < 2048);
        const bool isv = (n0 >= 3072);
        __nv_bfloat16 *dhi, *dlo;
        int colbase, ldd;
        if (isq)              { dhi = g_qhi; dlo = g_qlo; colbase = n0;        ldd = 2048; }
        else if (n0 < 3072)   { dhi = g_khi; dlo = g_klo; colbase = n0 - 2048; ldd = 1024; }
        else                  { dhi = g_vhi; dlo = g_vlo; colbase = n0 - 3072; ldd = 1024; }

        const float QS = isq ? 0.08838834764831845f * 1.4426950408889634f : 1.0f;
        const bool firsthalf = lane < 16;
        const int pbase = (lane & 15) * 4;

        float4 w4 = make_float4(1.f, 1.f, 1.f, 1.f);
        if (!isv) {
            const float* nw = isq ? qnw : knw;
            w4 = *(const float4*)&nw[lane * 4];
        }

#pragma unroll 1
        for (int i = 0; i < 16; i++) {
            const int row = wid * 16 + i;
            const int token = m0 + row;
            float4 xv = *(float4*)&Sb[row * EPI_PITCH + lane * 4];
            float r0, r1, r2, r3;
            if (!isv) {
                float ss = xv.x * xv.x + xv.y * xv.y + xv.z * xv.z + xv.w * xv.w;
#pragma unroll
                for (int m = 16; m; m >>= 1) ss += __shfl_xor_sync(0xffffffffu, ss, m);
                const float rinv = rsqrtf(ss * (1.0f / HDIM) + EPSV);
                const float nn0 = xv.x * w4.x * rinv;
                const float nn1 = xv.y * w4.y * rinv;
                const float nn2 = xv.z * w4.z * rinv;
                const float nn3 = xv.w * w4.w * rinv;
                const float pp0 = __shfl_xor_sync(0xffffffffu, nn0, 16);
                const float pp1 = __shfl_xor_sync(0xffffffffu, nn1, 16);
                const float pp2 = __shfl_xor_sync(0xffffffffu, nn2, 16);
                const float pp3 = __shfl_xor_sync(0xffffffffu, nn3, 16);
                const float4 sn = *(const float4*)&g_rsin[(size_t)token * 64 + pbase];
                const float4 cs = *(const float4*)&g_rcos[(size_t)token * 64 + pbase];
                if (firsthalf) {
                    r0 = (nn0 * cs.x - pp0 * sn.x) * QS;
                    r1 = (nn1 * cs.y - pp1 * sn.y) * QS;
                    r2 = (nn2 * cs.z - pp2 * sn.z) * QS;
                    r3 = (nn3 * cs.w - pp3 * sn.w) * QS;
                } else {
                    r0 = (nn0 * cs.x + pp0 * sn.x) * QS;
                    r1 = (nn1 * cs.y + pp1 * sn.y) * QS;
                    r2 = (nn2 * cs.z + pp2 * sn.z) * QS;
                    r3 = (nn3 * cs.w + pp3 * sn.w) * QS;
                }
            } else {
                r0 = xv.x; r1 = xv.y; r2 = xv.z; r3 = xv.w;
            }
            const __nv_bfloat16 h0 = __float2bfloat16(r0);
            const __nv_bfloat16 h1 = __float2bfloat16(r1);
            const __nv_bfloat16 h2 = __float2bfloat16(r2);
            const __nv_bfloat16 h3 = __float2bfloat16(r3);
            uint2 hp, lp;
            hp.x = pack_bf2(r0, r1);
            hp.y = pack_bf2(r2, r3);
            lp.x = pack_bf2(r0 - __bfloat162float(h0), r1 - __bfloat162float(h1));
            lp.y = pack_bf2(r2 - __bfloat162float(h2), r3 - __bfloat162float(h3));
            const size_t off = (size_t)token * ldd + colbase + lane * 4;
            *(uint2*)&dhi[off] = hp;
            *(uint2*)&dlo[off] = lp;
        }
    }
}

__global__ void __launch_bounds__(256, 2) gemm_qkv_kernel(
    const float* __restrict__ qnw, const float* __restrict__ knw) {
    gemm_bf16x3_body<1, 32, 1024>(g_xhi, g_xlo, g_wthi, g_wtlo, nullptr, 0, qnw, knw);
}
__global__ void __launch_bounds__(256, 2) gemm_out_kernel(float* __restrict__ out) {
    gemm_bf16x3_body<0, 16, 512>(g_ohi, g_olo, g_wothi, g_wotlo, out, DD,
                                 nullptr, nullptr);
}

// ---------------------------------------------------------------------------
// Flash attention (mma.sync bf16, split x3). R12: software-pipelined —
// QK(it+1) issued between softmax(it) and PV(it) (double score buffer),
// K+V in one commit group per stage, 3-stage ring, Q in registers.
//   Block: 128 q-rows x (head, batch). 8 warps, warp = 16 q-rows.
//   Stage layout per 69632B stage: Khi | Klo | Vhi | Vlo (17408B each).
//   KV(j) lives in stage (1+j)%3; Q staged through stage 0 then extracted.
// ---------------------------------------------------------------------------
#define FLP 272
#define FL_KVSZ (64 * FLP)          // 17408
#define FL_STAGE (4 * FL_KVSZ)      // 69632
#define FL_SMEM (3 * FL_STAGE)      // 208896

__device__ __forceinline__ void fl_prefetch_kv(
    uint32_t sbase, int b, int kvh, int kv0, int tid)
{
#pragma unroll
    for (int u = 0; u < 16; u++) {
        const int mtx = u >> 2;                      // 0:Khi 1:Klo 2:Vhi 3:Vlo
        const int row = ((u & 3) << 4) + (tid >> 4); // 0..63
        const int ch = tid & 15;
        const __nv_bfloat16* g;
        if (mtx == 0)      g = g_khi;
        else if (mtx == 1) g = g_klo;
        else if (mtx == 2) g = g_vhi;
        else               g = g_vlo;
        g += (size_t)(b * LL + kv0 + row) * 1024 + kvh * HDIM + ch * 8;
        cp16(sbase + mtx * FL_KVSZ + row * FLP + ch * 16, g);
    }
}

// S = Q K^T for one 128x64 kv tile (Q from registers, product-major)
__device__ __forceinline__ void fl_qk(
    float (&s)[8][4],
    const uint32_t (&qh)[8][4], const uint32_t (&ql)[8][4],
    uint32_t sK, uint32_t bk_off)
{
#pragma unroll
    for (int i = 0; i < 8; i++)
#pragma unroll
        for (int j = 0; j < 4; j++) s[i][j] = 0.f;
#pragma unroll
    for (int kf = 0; kf < 8; kf++) {
        uint32_t bh[4][4], bl[4][4];
#pragma unroll
        for (int p2 = 0; p2 < 4; p2++) {
            ldsm4(bh[p2], sK + bk_off + p2 * 16 * FLP + kf * 32);
            ldsm4(bl[p2], sK + FL_KVSZ + bk_off + p2 * 16 * FLP + kf * 32);
        }
#pragma unroll
        for (int p2 = 0; p2 < 4; p2++) {
            mma_bf16(s[2 * p2],     qh[kf], bh[p2]);
            mma_bf16(s[2 * p2 + 1], qh[kf], bh[p2] + 2);
        }
#pragma unroll
        for (int p2 = 0; p2 < 4; p2++) {
            mma_bf16(s[2 * p2],     qh[kf], bl[p2]);
            mma_bf16(s[2 * p2 + 1], qh[kf], bl[p2] + 2);
        }
#pragma unroll
        for (int p2 = 0; p2 < 4; p2++) {
            mma_bf16(s[2 * p2],     ql[kf], bh[p2]);
            mma_bf16(s[2 * p2 + 1], ql[kf], bh[p2] + 2);
        }
    }
}

// O += P V for one kv tile (P from cur score buffer, split on the fly)
__device__ __forceinline__ void fl_pv(
    float (&acc)[16][4], const float (&p)[8][4], uint32_t sVhi, uint32_t v_off)
{
    const uint32_t sVlo = sVhi + FL_KVSZ;
#pragma unroll
    for (int j = 0; j < 4; j++) {
        uint32_t ph[4], pl[4];
#pragma unroll
        for (int q = 0; q < 4; q++) {
            const int nf = 2 * j + (q >> 1);
            const int rb = (q & 1) * 2;
            const float v0 = p[nf][rb], v1 = p[nf][rb + 1];
            const __nv_bfloat16 h0 = __float2bfloat16(v0);
            const __nv_bfloat16 h1 = __float2bfloat16(v1);
            ph[q] = pack_bf2(v0, v1);
            pl[q] = pack_bf2(v0 - __bfloat162float(h0), v1 - __bfloat162float(h1));
        }
#pragma unroll
        for (int t2 = 0; t2 < 4; t2++) {
            uint32_t vh0[4], vl0[4], vh1[4], vl1[4];
            const uint32_t vb = sVhi + v_off + j * 16 * FLP;
            const uint32_t lb = sVlo + v_off + j * 16 * FLP;
            ldsm4t(vh0, vb + (2 * t2) * 32);
            ldsm4t(vl0, lb + (2 * t2) * 32);
            ldsm4t(vh1, vb + (2 * t2 + 1) * 32);
            ldsm4t(vl1, lb + (2 * t2 + 1) * 32);
            float* a0 = acc[4 * t2];
            float* a1 = acc[4 * t2 + 1];
            float* a2 = acc[4 * t2 + 2];
            float* a3 = acc[4 * t2 + 3];
            mma_bf16(a0, ph, vh0); mma_bf16(a1, ph, vh0 + 2);
            mma_bf16(a2, ph, vh1); mma_bf16(a3, ph, vh1 + 2);
            mma_bf16(a0, ph, vl0); mma_bf16(a1, ph, vl0 + 2);
            mma_bf16(a2, ph, vl1); mma_bf16(a3, ph, vl1 + 2);
            mma_bf16(a0, pl, vh0); mma_bf16(a1, pl, vh0 + 2);
            mma_bf16(a2, pl, vh1); mma_bf16(a3, pl, vh1 + 2);
        }
    }
}

// mask + online softmax on cur buffer
__device__ __forceinline__ void fl_softmax(
    float (&sfr)[8][4], float (&acc)[16][4], float (&m2)[2], float (&lsum)[2],
    int it, int m0, int wid, int lane)
{
    const int rbase = m0 + wid * 16 + (lane >> 2);
    if (it * 64 + 63 > m0 + wid * 16) {
#pragma unroll
        for (int nf = 0; nf < 8; nf++) {
            const int cg = it * 64 + nf * 8 + 2 * (lane & 3);
#pragma unroll
            for (int rg = 0; rg < 4; rg++) {
                const int row = rbase + (rg >> 1) * 8;
                const int col = cg + (rg & 1);
                if (col > row) sfr[nf][rg] = -1e30f;
            }
        }
    }
#pragma unroll
    for (int h = 0; h < 2; h++) {
        float tm = -1e30f;
#pragma unroll
        for (int nf = 0; nf < 8; nf++)
            tm = fmaxf(tm, fmaxf(sfr[nf][2 * h], sfr[nf][2 * h + 1]));
        tm = fmaxf(tm, __shfl_xor_sync(0xffffffffu, tm, 1));
        tm = fmaxf(tm, __shfl_xor_sync(0xffffffffu, tm, 2));
        const float mn = fmaxf(m2[h], tm);
        const float corr = exp2f(m2[h] - mn);
        m2[h] = mn;
        float rs = 0.f;
#pragma unroll
        for (int nf = 0; nf < 8; nf++) {
            const float e0 = exp2f(sfr[nf][2 * h] - mn);
            const float e1 = exp2f(sfr[nf][2 * h + 1] - mn);
            sfr[nf][2 * h] = e0;
            sfr[nf][2 * h + 1] = e1;
            rs += e0 + e1;
        }
        rs += __shfl_xor_sync(0xffffffffu, rs, 1);
        rs += __shfl_xor_sync(0xffffffffu, rs, 2);
        lsum[h] = lsum[h] * corr + rs;
#pragma unroll
        for (int nf = 0; nf < 16; nf++) {
            acc[nf][2 * h] *= corr;
            acc[nf][2 * h + 1] *= corr;
        }
    }
}

__global__ void __launch_bounds__(256, 1) flash_kernel()
{
    const int tid = threadIdx.x;
    const int lane = tid & 31;
    const int wid = tid >> 5;
    const int b = blockIdx.z;
    const int n = blockIdx.y;
    const int mt = (int)gridDim.x - 1 - (int)blockIdx.x;  // big tiles launch first
    const int kvh = n >> 1;
    const int m0 = mt * 128;

    const uint32_t sb = smem_u32(dyn_smem);

    // group 0: Q (hi at stage0+0, lo at stage0+34816)
#pragma unroll
    for (int u = 0; u < 16; u++) {
        const int mtx = u >> 3;
        const int row = ((u & 7) << 4) + (tid >> 4);
        const int ch = tid & 15;
        const __nv_bfloat16* g = (mtx ? g_qlo : g_qhi) +
            (size_t)(b * LL + m0 + row) * 2048 + n * HDIM + ch * 8;
        cp16(sb + mtx * 34816 + row * FLP + ch * 16, g);
    }
    CP_COMMIT();
    fl_prefetch_kv(sb + 1 * FL_STAGE, b, kvh, 0, tid);   // group 1: KV0
    CP_COMMIT();
    fl_prefetch_kv(sb + 2 * FL_STAGE, b, kvh, 64, tid);  // group 2: KV1
    CP_COMMIT();

    const uint32_t a_off = (uint32_t)((wid * 16 + (lane & 15)) * FLP + (lane >> 4) * 16);
    const uint32_t bk_off = (uint32_t)(((lane & 7) + ((lane >> 4) << 3)) * FLP +
                                       ((lane >> 3) & 1) * 16);
    const uint32_t v_off = (uint32_t)(((lane & 7) + ((lane >> 3) & 1) * 8) * FLP +
                                      (lane >> 4) * 16);

    CP_WAIT(1);          // Q + KV0 landed
    __syncthreads();
    uint32_t qh[8][4], ql[8][4];
#pragma unroll
    for (int kf = 0; kf < 8; kf++) {
        ldsm4(qh[kf], sb + a_off + kf * 32);
        ldsm4(ql[kf], sb + 34816 + a_off + kf * 32);
    }

    float acc[16][4];
#pragma unroll
    for (int i = 0; i < 16; i++)
#pragma unroll
        for (int j = 0; j < 4; j++) acc[i][j] = 0.f;
    float m2[2] = {-1e30f, -1e30f};
    float lsum[2] = {0.f, 0.f};

    float sA[8][4], sB[8][4];
    const int nkv = 2 * (mt + 1);    // always even

    // prologue: QK(0) from stage 1
    fl_qk(sA, qh, ql, sb + 1 * FL_STAGE, bk_off);

#define FL_ITER(IT, CUR, NXT)                                                  \
    {                                                                          \
        CP_WAIT(0);          /* KV(IT+1) landed */                             \
        __syncthreads();     /* visibility + stage (IT)%3 free for refill */   \
        if ((IT) + 2 < nkv) {                                                  \
            fl_prefetch_kv(sb + ((IT) % 3) * FL_STAGE, b, kvh,                 \
                           ((IT) + 2) * 64, tid);                              \
            CP_COMMIT();                                                       \
        }                                                                      \
        fl_softmax(CUR, acc, m2, lsum, (IT), m0, wid, lane);                   \
        if ((IT) + 1 < nkv)                                                    \
            fl_qk(NXT, qh, ql, sb + (((IT) + 2) % 3) * FL_STAGE, bk_off);      \
        fl_pv(acc, CUR, sb + (((IT) + 1) % 3) * FL_STAGE + 2 * FL_KVSZ,        \
              v_off);                                                          \
    }

    for (int it = 0; it < nkv; it += 2) {
        FL_ITER(it, sA, sB);
        FL_ITER(it + 1, sB, sA);
    }
#undef FL_ITER

    // --- finalize: /l, split to bf16 hi/lo, store ---
#pragma unroll
    for (int h = 0; h < 2; h++) {
        const float inv = 1.0f / lsum[h];
        const int row = m0 + wid * 16 + (lane >> 2) + h * 8;
        const size_t base = (size_t)(b * LL + row) * 2048 + n * HDIM + 2 * (lane & 3);
#pragma unroll
        for (int nf = 0; nf < 16; nf++) {
            const float v0 = acc[nf][2 * h] * inv;
            const float v1 = acc[nf][2 * h + 1] * inv;
            const __nv_bfloat16 h0 = __float2bfloat16(v0);
            const __nv_bfloat16 h1 = __float2bfloat16(v1);
            *(uint32_t*)&g_ohi[base + nf * 8] = pack_bf2(v0, v1);
            *(uint32_t*)&g_olo[base + nf * 8] =
                pack_bf2(v0 - __bfloat162float(h0), v1 - __bfloat162float(h1));
        }
    }
}

// ---------------------------------------------------------------------------
// Launch
// ---------------------------------------------------------------------------
extern "C" void kernel_launch(void* const* d_in, const int* in_sizes, int n_in,
                              void* d_out, int out_size)
{
    const float* x   = (const float*)d_in[0];
    const int*   pos = (const int*)d_in[1];
    // d_in[2] = attn_mask (causal tril) — implied analytically, unused
    const float* wq  = (const float*)d_in[3];
    const float* wk  = (const float*)d_in[4];
    const float* wv  = (const float*)d_in[5];
    const float* wo  = (const float*)d_in[6];
    const float* qnw = (const float*)d_in[7];
    const float* knw = (const float*)d_in[8];
    float* out = (float*)d_out;

    cudaFuncSetAttribute(gemm_qkv_kernel,
                         cudaFuncAttributeMaxDynamicSharedMemorySize, GEMM_SMEM_BYTES);
    cudaFuncSetAttribute(gemm_out_kernel,
                         cudaFuncAttributeMaxDynamicSharedMemorySize, GEMM_SMEM_BYTES);
    cudaFuncSetAttribute(flash_kernel,
                         cudaFuncAttributeMaxDynamicSharedMemorySize, FL_SMEM);

    int dev = 0, sms = 148;
    cudaGetDevice(&dev);
    cudaDeviceGetAttribute(&sms, cudaDevAttrMultiProcessorCount, dev);
    const int pgrid = sms * 2;   // persistent grid (2 CTAs/SM)

    // 1. weights -> transposed bf16 hi/lo + rope tables + split X
    transpose_convert_all_kernel<<<dim3(64, 64, 4), dim3(32, 8)>>>(wq, wk, wv, wo);
    rope_table_kernel<<<(TOK * 64 + 255) / 256, 256>>>(pos);
    convert_split_x_kernel<<<(TOK * DD / 4 + 255) / 256, 256>>>(x);

    // 2. QKV projection (persistent) with fused RMSNorm+RoPE+split
    gemm_qkv_kernel<<<pgrid, 256, GEMM_SMEM_BYTES>>>(qnw, knw);

    // 3. Flash attention (software-pipelined QK/PV)
    flash_kernel<<<dim3(LL / 128, NHEADS, BB), 256, FL_SMEM>>>();

    // 4. output projection (persistent)
    gemm_out_kernel<<<pgrid, 256, GEMM_SMEM_BYTES>>>(out);
}

// round 13
// speedup vs baseline: 1.0108x; 1.0108x over previous
#include <cuda_runtime.h>
#include <cuda_bf16.h>
#include <math.h>
#include <stdint.h>

// Problem constants
#define BB 2
#define LL 2048
#define DD 2048
#define NHEADS 16
#define KHEADS 8
#define HDIM 128
#define TOK (BB * LL)        // 4096
#define EPSV 1e-6f
#define QKVW 4096            // concatenated qkv col space (q:0..2047, k:..3071, v:..4095)

// ---------------------------------------------------------------------------
// Scratch (device globals — no runtime allocation allowed)
// ---------------------------------------------------------------------------
__device__ __align__(16) __nv_bfloat16 g_xhi[(size_t)TOK * DD];
__device__ __align__(16) __nv_bfloat16 g_xlo[(size_t)TOK * DD];
__device__ __align__(16) __nv_bfloat16 g_qhi[(size_t)TOK * DD];     // normed/rope'd/pre-scaled q
__device__ __align__(16) __nv_bfloat16 g_qlo[(size_t)TOK * DD];
__device__ __align__(16) __nv_bfloat16 g_khi[(size_t)TOK * KHEADS * HDIM];
__device__ __align__(16) __nv_bfloat16 g_klo[(size_t)TOK * KHEADS * HDIM];
__device__ __align__(16) __nv_bfloat16 g_vhi[(size_t)TOK * KHEADS * HDIM];
__device__ __align__(16) __nv_bfloat16 g_vlo[(size_t)TOK * KHEADS * HDIM];
__device__ __align__(16) __nv_bfloat16 g_ohi[(size_t)TOK * DD];     // attention out
__device__ __align__(16) __nv_bfloat16 g_olo[(size_t)TOK * DD];
__device__ __align__(16) __nv_bfloat16 g_wthi[(size_t)QKVW * DD];   // [n][k] qkv weights
__device__ __align__(16) __nv_bfloat16 g_wtlo[(size_t)QKVW * DD];
__device__ __align__(16) __nv_bfloat16 g_wothi[(size_t)DD * DD];    // [n][k] wo
__device__ __align__(16) __nv_bfloat16 g_wotlo[(size_t)DD * DD];
__device__ __align__(16) float g_rsin[(size_t)TOK * 64];            // rope tables
__device__ __align__(16) float g_rcos[(size_t)TOK * 64];

extern __shared__ char dyn_smem[];

// ---------------------------------------------------------------------------
// PTX helpers (family-portable: cp.async / ldmatrix / mma.sync)
// ---------------------------------------------------------------------------
__device__ __forceinline__ uint32_t smem_u32(const void* p) {
    uint32_t a;
    asm("{ .reg .u64 t; cvta.to.shared.u64 t, %1; cvt.u32.u64 %0, t; }"
        : "=r"(a) : "l"(p));
    return a;
}

__device__ __forceinline__ void cp16(uint32_t dst, const void* src) {
    asm volatile("cp.async.cg.shared.global [%0], [%1], 16;" :: "r"(dst), "l"(src));
}
#define CP_COMMIT() asm volatile("cp.async.commit_group;" ::: "memory")
#define CP_WAIT(N)  asm volatile("cp.async.wait_group %0;" :: "n"(N) : "memory")

__device__ __forceinline__ void ldsm4(uint32_t* r, uint32_t a) {
    asm volatile("ldmatrix.sync.aligned.m8n8.x4.shared.b16 {%0,%1,%2,%3}, [%4];"
        : "=r"(r[0]), "=r"(r[1]), "=r"(r[2]), "=r"(r[3]) : "r"(a));
}
__device__ __forceinline__ void ldsm4t(uint32_t* r, uint32_t a) {
    asm volatile("ldmatrix.sync.aligned.m8n8.x4.trans.shared.b16 {%0,%1,%2,%3}, [%4];"
        : "=r"(r[0]), "=r"(r[1]), "=r"(r[2]), "=r"(r[3]) : "r"(a));
}

__device__ __forceinline__ void mma_bf16(float* c, const uint32_t* a, const uint32_t* b) {
    asm volatile(
        "mma.sync.aligned.m16n8k16.row.col.f32.bf16.bf16.f32 "
        "{%0,%1,%2,%3}, {%4,%5,%6,%7}, {%8,%9}, {%0,%1,%2,%3};"
        : "+f"(c[0]), "+f"(c[1]), "+f"(c[2]), "+f"(c[3])
        : "r"(a[0]), "r"(a[1]), "r"(a[2]), "r"(a[3]), "r"(b[0]), "r"(b[1]));
}

__device__ __forceinline__ uint32_t pack_bf2(float x, float y) {
    __nv_bfloat162 t;
    t.x = __float2bfloat16(x);
    t.y = __float2bfloat16(y);
    return *(uint32_t*)&t;
}

// ---------------------------------------------------------------------------
// Conversion / table kernels
// ---------------------------------------------------------------------------
__global__ void __launch_bounds__(256) transpose_convert_all_kernel(
    const float* __restrict__ wq, const float* __restrict__ wk,
    const float* __restrict__ wv, const float* __restrict__ wo)
{
    const int z = blockIdx.z;
    const float* src;
    int C, row_off;
    __nv_bfloat16 *dhi, *dlo;
    if (z == 0)      { src = wq; C = 2048; row_off = 0;    dhi = g_wthi;  dlo = g_wtlo;  }
    else if (z == 1) { if (blockIdx.x >= 32) return;
                       src = wk; C = 1024; row_off = 2048; dhi = g_wthi;  dlo = g_wtlo;  }
    else if (z == 2) { if (blockIdx.x >= 32) return;
                       src = wv; C = 1024; row_off = 3072; dhi = g_wthi;  dlo = g_wtlo;  }
    else             { src = wo; C = 2048; row_off = 0;    dhi = g_wothi; dlo = g_wotlo; }

    __shared__ float t[32][33];
    const int c0 = blockIdx.x * 32;
    const int r0 = blockIdx.y * 32;
    const int tx = threadIdx.x;
    const int ty = threadIdx.y;

#pragma unroll
    for (int j = 0; j < 4; j++)
        t[ty + j * 8][tx] = src[(size_t)(r0 + ty + j * 8) * C + c0 + tx];
    __syncthreads();

#pragma unroll
    for (int j = 0; j < 4; j++) {
        const int i = ty + j * 8;
        const float v = t[tx][i];
        const __nv_bfloat16 h = __float2bfloat16(v);
        const __nv_bfloat16 l = __float2bfloat16(v - __bfloat162float(h));
        const size_t off = (size_t)(row_off + c0 + i) * DD + r0 + tx;
        dhi[off] = h;
        dlo[off] = l;
    }
}

__global__ void __launch_bounds__(256) convert_split_x_kernel(const float* __restrict__ src)
{
    const size_t i = (size_t)blockIdx.x * blockDim.x + threadIdx.x;
    const size_t n4 = (size_t)TOK * DD / 4;
    if (i >= n4) return;
    const float4 v = ((const float4*)src)[i];
    __nv_bfloat16 h0 = __float2bfloat16(v.x);
    __nv_bfloat16 h1 = __float2bfloat16(v.y);
    __nv_bfloat16 h2 = __float2bfloat16(v.z);
    __nv_bfloat16 h3 = __float2bfloat16(v.w);
    uint2 hp, lp;
    hp.x = pack_bf2(v.x, v.y);
    hp.y = pack_bf2(v.z, v.w);
    lp.x = pack_bf2(v.x - __bfloat162float(h0), v.y - __bfloat162float(h1));
    lp.y = pack_bf2(v.z - __bfloat162float(h2), v.w - __bfloat162float(h3));
    ((uint2*)g_xhi)[i] = hp;
    ((uint2*)g_xlo)[i] = lp;
}

// RoPE tables: sin/cos per (token, freq-pair). One-time, full-precision.
__global__ void __launch_bounds__(256) rope_table_kernel(const int* __restrict__ pos_ids)
{
    const int idx = blockIdx.x * 256 + threadIdx.x;
    if (idx >= TOK * 64) return;
    const int token = idx >> 6;
    const int p = idx & 63;
    const double L2T = 19.931568569324174;   // log2(1e6)
    const float inv_ts = exp2f((float)(-(double)p * L2T / 64.0));
    const float ang = (float)pos_ids[token] * inv_ts;
    float sv, cv;
    sincosf(ang, &sv, &cv);
    g_rsin[idx] = sv;
    g_rcos[idx] = cv;
}

// ---------------------------------------------------------------------------
// split-bf16 warp-MMA GEMM (R9 exact, wave-launched): C = A * B^T
//   CTA tile 128x128, BK=32, 256 threads, 8 warps (2m x 4n), warp tile 64x32.
//   XOR-swizzled 64B pitch, 3-stage cp.async ring, 2 CTAs/SM, product-major.
//   FUSED=1 (qkv): epilogue does RMSNorm+RoPE+split in-SMEM.
// ---------------------------------------------------------------------------
#define BK 32
#define PITCH 64
#define MAT_BYTES (128 * PITCH)           // 8192 per split
#define STAGE_BYTES (4 * MAT_BYTES)       // 32768
#define GEMM_SMEM_BYTES (3 * STAGE_BYTES) // 98304 (x2 CTAs = 196KB)
#define EPI_PITCH 132                     // fp32 words per row in epilogue buffer

__device__ __forceinline__ uint32_t gswz(int r, int c) {
    return (uint32_t)(r * PITCH + ((c ^ ((r >> 1) & 3)) << 4));
}

__device__ __forceinline__ void prefetch_stage(
    uint32_t sbase,
    const __nv_bfloat16* __restrict__ Ahi, const __nv_bfloat16* __restrict__ Alo,
    const __nv_bfloat16* __restrict__ Bhi, const __nv_bfloat16* __restrict__ Blo,
    int m0, int n0, int k0, int ldA, int ldB, int tid)
{
#pragma unroll
    for (int j = 0; j < 2; j++) {
        const int id = tid * 2 + j;
        const int r = id >> 2;
        const int c = id & 3;
        const uint32_t soff = gswz(r, c);
        const size_t ga = (size_t)(m0 + r) * ldA + k0 + c * 8;
        const size_t gb = (size_t)(n0 + r) * ldB + k0 + c * 8;
        cp16(sbase + soff,                 Ahi + ga);
        cp16(sbase + MAT_BYTES + soff,     Alo + ga);
        cp16(sbase + 2 * MAT_BYTES + soff, Bhi + gb);
        cp16(sbase + 3 * MAT_BYTES + soff, Blo + gb);
    }
}

template <int FUSED>
__device__ __forceinline__ void gemm_bf16x3_body(
    const __nv_bfloat16* __restrict__ Ahi, const __nv_bfloat16* __restrict__ Alo,
    const __nv_bfloat16* __restrict__ Bhi, const __nv_bfloat16* __restrict__ Blo,
    float* __restrict__ Cc, int K, int ldA, int ldB, int ldC,
    const float* __restrict__ qnw, const float* __restrict__ knw)
{
    const int tid  = threadIdx.x;             // 256 threads
    const int lane = tid & 31;
    const int wid  = tid >> 5;                // 0..7
    const int wm   = wid & 1;
    const int wn   = wid >> 1;
    const int m0   = blockIdx.y * 128;
    const int n0   = blockIdx.x * 128;
    const uint32_t smem_base = smem_u32(dyn_smem);

    float c[4][4][4];
#pragma unroll
    for (int i = 0; i < 4; i++)
#pragma unroll
        for (int j = 0; j < 4; j++)
#pragma unroll
            for (int k = 0; k < 4; k++) c[i][j][k] = 0.f;

    const int a_row  = wm * 64 + (lane & 15);
    const int a_swz  = (a_row >> 1) & 3;
    const uint32_t a_base = (uint32_t)(a_row * PITCH);
    const int a_c0   = lane >> 4;
    const int b_row  = wn * 32 + (lane & 7) + ((lane >> 4) << 3);
    const int b_swz  = (b_row >> 1) & 3;
    const uint32_t b_base = (uint32_t)(b_row * PITCH);
    const int b_c0   = (lane >> 3) & 1;

    const int nk = K / BK;

    prefetch_stage(smem_base, Ahi, Alo, Bhi, Blo, m0, n0, 0, ldA, ldB, tid);
    CP_COMMIT();
    prefetch_stage(smem_base + STAGE_BYTES, Ahi, Alo, Bhi, Blo, m0, n0, BK, ldA, ldB, tid);
    CP_COMMIT();

    int slot = 0;
    for (int it = 0; it < nk; it++) {
        if (it < nk - 1) { CP_WAIT(1); } else { CP_WAIT(0); }
        __syncthreads();

        if (it + 2 < nk) {
            int ps = slot + 2;
            if (ps >= 3) ps -= 3;
            prefetch_stage(smem_base + ps * STAGE_BYTES,
                           Ahi, Alo, Bhi, Blo, m0, n0, (it + 2) * BK, ldA, ldB, tid);
            CP_COMMIT();
        }

        const uint32_t sA = smem_base + slot * STAGE_BYTES;
        const uint32_t sB = sA + 2 * MAT_BYTES;

#pragma unroll
        for (int kf = 0; kf < 2; kf++) {
            uint32_t b[2][2][4];
            const uint32_t a_coff = (uint32_t)(((a_c0 + kf * 2) ^ a_swz) << 4);
            const uint32_t b_coff = (uint32_t)(((b_c0 + kf * 2) ^ b_swz) << 4);
#pragma unroll
            for (int nf2 = 0; nf2 < 2; nf2++) {
                const uint32_t bd = sB + b_base + nf2 * (16 * PITCH) + b_coff;
                ldsm4(b[0][nf2], bd);
                ldsm4(b[1][nf2], bd + MAT_BYTES);
            }
#pragma unroll
            for (int mf = 0; mf < 4; mf++) {
                uint32_t ah[4], al[4];
                const uint32_t ad = sA + a_base + mf * (16 * PITCH) + a_coff;
                ldsm4(ah, ad);
                ldsm4(al, ad + MAT_BYTES);
#pragma unroll
                for (int nf = 0; nf < 4; nf++)
                    mma_bf16(c[mf][nf], ah, &b[0][nf >> 1][(nf & 1) * 2]);
#pragma unroll
                for (int nf = 0; nf < 4; nf++)
                    mma_bf16(c[mf][nf], ah, &b[1][nf >> 1][(nf & 1) * 2]);
#pragma unroll
                for (int nf = 0; nf < 4; nf++)
                    mma_bf16(c[mf][nf], al, &b[0][nf >> 1][(nf & 1) * 2]);
            }
        }

        if (++slot == 3) slot = 0;
    }

    const int gr = lane >> 2;
    const int gc = (lane & 3) * 2;

    if (FUSED == 0) {
        const int row0 = m0 + wm * 64;
        const int col0 = n0 + wn * 32;
#pragma unroll
        for (int mf = 0; mf < 4; mf++)
#pragma unroll
            for (int nf = 0; nf < 4; nf++) {
                float* cc = c[mf][nf];
                const int r = row0 + mf * 16 + gr;
                const int cl = col0 + nf * 8 + gc;
                *(float2*)&Cc[(size_t)r * ldC + cl]       = make_float2(cc[0], cc[1]);
                *(float2*)&Cc[(size_t)(r + 8) * ldC + cl] = make_float2(cc[2], cc[3]);
            }
        return;
    }

    // --- FUSED epilogue: SMEM bounce + RMSNorm + RoPE + hi/lo split ---
    float* Sb = (float*)dyn_smem;
    __syncthreads();
    {
        const int row0 = wm * 64;
        const int col0 = wn * 32;
#pragma unroll
        for (int mf = 0; mf < 4; mf++)
#pragma unroll
            for (int nf = 0; nf < 4; nf++) {
                float* cc = c[mf][nf];
                const int r = row0 + mf * 16 + gr;
                const int cl = col0 + nf * 8 + gc;
                *(float2*)&Sb[r * EPI_PITCH + cl]       = make_float2(cc[0], cc[1]);
                *(float2*)&Sb[(r + 8) * EPI_PITCH + cl] = make_float2(cc[2], cc[3]);
            }
    }
    __syncthreads();

    const bool isq = (n0 < 2048);
    const bool isv = (n0 >= 3072);
    __nv_bfloat16 *dhi, *dlo;
    int colbase, ldd;
    if (isq)              { dhi = g_qhi; dlo = g_qlo; colbase = n0;        ldd = 2048; }
    else if (n0 < 3072)   { dhi = g_khi; dlo = g_klo; colbase = n0 - 2048; ldd = 1024; }
    else                  { dhi = g_vhi; dlo = g_vlo; colbase = n0 - 3072; ldd = 1024; }

    const float QS = isq ? 0.08838834764831845f * 1.4426950408889634f : 1.0f;
    const bool firsthalf = lane < 16;
    const int pbase = (lane & 15) * 4;

    float4 w4 = make_float4(1.f, 1.f, 1.f, 1.f);
    if (!isv) {
        const float* nw = isq ? qnw : knw;
        w4 = *(const float4*)&nw[lane * 4];
    }

#pragma unroll 1
    for (int i = 0; i < 16; i++) {
        const int row = wid * 16 + i;
        const int token = m0 + row;
        float4 xv = *(float4*)&Sb[row * EPI_PITCH + lane * 4];
        float r0, r1, r2, r3;
        if (!isv) {
            float ss = xv.x * xv.x + xv.y * xv.y + xv.z * xv.z + xv.w * xv.w;
#pragma unroll
            for (int m = 16; m; m >>= 1) ss += __shfl_xor_sync(0xffffffffu, ss, m);
            const float rinv = rsqrtf(ss * (1.0f / HDIM) + EPSV);
            const float nn0 = xv.x * w4.x * rinv;
            const float nn1 = xv.y * w4.y * rinv;
            const float nn2 = xv.z * w4.z * rinv;
            const float nn3 = xv.w * w4.w * rinv;
            const float pp0 = __shfl_xor_sync(0xffffffffu, nn0, 16);
            const float pp1 = __shfl_xor_sync(0xffffffffu, nn1, 16);
            const float pp2 = __shfl_xor_sync(0xffffffffu, nn2, 16);
            const float pp3 = __shfl_xor_sync(0xffffffffu, nn3, 16);
            const float4 sn = *(const float4*)&g_rsin[(size_t)token * 64 + pbase];
            const float4 cs = *(const float4*)&g_rcos[(size_t)token * 64 + pbase];
            if (firsthalf) {
                r0 = (nn0 * cs.x - pp0 * sn.x) * QS;
                r1 = (nn1 * cs.y - pp1 * sn.y) * QS;
                r2 = (nn2 * cs.z - pp2 * sn.z) * QS;
                r3 = (nn3 * cs.w - pp3 * sn.w) * QS;
            } else {
                r0 = (nn0 * cs.x + pp0 * sn.x) * QS;
                r1 = (nn1 * cs.y + pp1 * sn.y) * QS;
                r2 = (nn2 * cs.z + pp2 * sn.z) * QS;
                r3 = (nn3 * cs.w + pp3 * sn.w) * QS;
            }
        } else {
            r0 = xv.x; r1 = xv.y; r2 = xv.z; r3 = xv.w;
        }
        const __nv_bfloat16 h0 = __float2bfloat16(r0);
        const __nv_bfloat16 h1 = __float2bfloat16(r1);
        const __nv_bfloat16 h2 = __float2bfloat16(r2);
        const __nv_bfloat16 h3 = __float2bfloat16(r3);
        uint2 hp, lp;
        hp.x = pack_bf2(r0, r1);
        hp.y = pack_bf2(r2, r3);
        lp.x = pack_bf2(r0 - __bfloat162float(h0), r1 - __bfloat162float(h1));
        lp.y = pack_bf2(r2 - __bfloat162float(h2), r3 - __bfloat162float(h3));
        const size_t off = (size_t)token * ldd + colbase + lane * 4;
        *(uint2*)&dhi[off] = hp;
        *(uint2*)&dlo[off] = lp;
    }
}

__global__ void __launch_bounds__(256, 2) gemm_qkv_kernel(
    const float* __restrict__ qnw, const float* __restrict__ knw) {
    gemm_bf16x3_body<1>(g_xhi, g_xlo, g_wthi, g_wtlo, nullptr, DD, DD, DD, 0, qnw, knw);
}
__global__ void __launch_bounds__(256, 2) gemm_out_kernel(float* __restrict__ out) {
    gemm_bf16x3_body<0>(g_ohi, g_olo, g_wothi, g_wotlo, out, DD, DD, DD, DD,
                        nullptr, nullptr);
}

// ---------------------------------------------------------------------------
// Flash attention (R12 exact): software-pipelined — QK(it+1) between
// softmax(it) and PV(it), double score buffer, KV in one commit group per
// stage, 3-stage ring, Q in registers.
// ---------------------------------------------------------------------------
#define FLP 272
#define FL_KVSZ (64 * FLP)          // 17408
#define FL_STAGE (4 * FL_KVSZ)      // 69632
#define FL_SMEM (3 * FL_STAGE)      // 208896

__device__ __forceinline__ void fl_prefetch_kv(
    uint32_t sbase, int b, int kvh, int kv0, int tid)
{
#pragma unroll
    for (int u = 0; u < 16; u++) {
        const int mtx = u >> 2;                      // 0:Khi 1:Klo 2:Vhi 3:Vlo
        const int row = ((u & 3) << 4) + (tid >> 4); // 0..63
        const int ch = tid & 15;
        const __nv_bfloat16* g;
        if (mtx == 0)      g = g_khi;
        else if (mtx == 1) g = g_klo;
        else if (mtx == 2) g = g_vhi;
        else               g = g_vlo;
        g += (size_t)(b * LL + kv0 + row) * 1024 + kvh * HDIM + ch * 8;
        cp16(sbase + mtx * FL_KVSZ + row * FLP + ch * 16, g);
    }
}

__device__ __forceinline__ void fl_qk(
    float (&s)[8][4],
    const uint32_t (&qh)[8][4], const uint32_t (&ql)[8][4],
    uint32_t sK, uint32_t bk_off)
{
#pragma unroll
    for (int i = 0; i < 8; i++)
#pragma unroll
        for (int j = 0; j < 4; j++) s[i][j] = 0.f;
#pragma unroll
    for (int kf = 0; kf < 8; kf++) {
        uint32_t bh[4][4], bl[4][4];
#pragma unroll
        for (int p2 = 0; p2 < 4; p2++) {
            ldsm4(bh[p2], sK + bk_off + p2 * 16 * FLP + kf * 32);
            ldsm4(bl[p2], sK + FL_KVSZ + bk_off + p2 * 16 * FLP + kf * 32);
        }
#pragma unroll
        for (int p2 = 0; p2 < 4; p2++) {
            mma_bf16(s[2 * p2],     qh[kf], bh[p2]);
            mma_bf16(s[2 * p2 + 1], qh[kf], bh[p2] + 2);
        }
#pragma unroll
        for (int p2 = 0; p2 < 4; p2++) {
            mma_bf16(s[2 * p2],     qh[kf], bl[p2]);
            mma_bf16(s[2 * p2 + 1], qh[kf], bl[p2] + 2);
        }
#pragma unroll
        for (int p2 = 0; p2 < 4; p2++) {
            mma_bf16(s[2 * p2],     ql[kf], bh[p2]);
            mma_bf16(s[2 * p2 + 1], ql[kf], bh[p2] + 2);
        }
    }
}

__device__ __forceinline__ void fl_pv(
    float (&acc)[16][4], const float (&p)[8][4], uint32_t sVhi, uint32_t v_off)
{
    const uint32_t sVlo = sVhi + FL_KVSZ;
#pragma unroll
    for (int j = 0; j < 4; j++) {
        uint32_t ph[4], pl[4];
#pragma unroll
        for (int q = 0; q < 4; q++) {
            const int nf = 2 * j + (q >> 1);
            const int rb = (q & 1) * 2;
            const float v0 = p[nf][rb], v1 = p[nf][rb + 1];
            const __nv_bfloat16 h0 = __float2bfloat16(v0);
            const __nv_bfloat16 h1 = __float2bfloat16(v1);
            ph[q] = pack_bf2(v0, v1);
            pl[q] = pack_bf2(v0 - __bfloat162float(h0), v1 - __bfloat162float(h1));
        }
#pragma unroll
        for (int t2 = 0; t2 < 4; t2++) {
            uint32_t vh0[4], vl0[4], vh1[4], vl1[4];
            const uint32_t vb = sVhi + v_off + j * 16 * FLP;
            const uint32_t lb = sVlo + v_off + j * 16 * FLP;
            ldsm4t(vh0, vb + (2 * t2) * 32);
            ldsm4t(vl0, lb + (2 * t2) * 32);
            ldsm4t(vh1, vb + (2 * t2 + 1) * 32);
            ldsm4t(vl1, lb + (2 * t2 + 1) * 32);
            float* a0 = acc[4 * t2];
            float* a1 = acc[4 * t2 + 1];
            float* a2 = acc[4 * t2 + 2];
            float* a3 = acc[4 * t2 + 3];
            mma_bf16(a0, ph, vh0); mma_bf16(a1, ph, vh0 + 2);
            mma_bf16(a2, ph, vh1); mma_bf16(a3, ph, vh1 + 2);
            mma_bf16(a0, ph, vl0); mma_bf16(a1, ph, vl0 + 2);
            mma_bf16(a2, ph, vl1); mma_bf16(a3, ph, vl1 + 2);
            mma_bf16(a0, pl, vh0); mma_bf16(a1, pl, vh0 + 2);
            mma_bf16(a2, pl, vh1); mma_bf16(a3, pl, vh1 + 2);
        }
    }
}

__device__ __forceinline__ void fl_softmax(
    float (&sfr)[8][4], float (&acc)[16][4], float (&m2)[2], float (&lsum)[2],
    int it, int m0, int wid, int lane)
{
    const int rbase = m0 + wid * 16 + (lane >> 2);
    if (it * 64 + 63 > m0 + wid * 16) {
#pragma unroll
        for (int nf = 0; nf < 8; nf++) {
            const int cg = it * 64 + nf * 8 + 2 * (lane & 3);
#pragma unroll
            for (int rg = 0; rg < 4; rg++) {
                const int row = rbase + (rg >> 1) * 8;
                const int col = cg + (rg & 1);
                if (col > row) sfr[nf][rg] = -1e30f;
            }
        }
    }
#pragma unroll
    for (int h = 0; h < 2; h++) {
        float tm = -1e30f;
#pragma unroll
        for (int nf = 0; nf < 8; nf++)
            tm = fmaxf(tm, fmaxf(sfr[nf][2 * h], sfr[nf][2 * h + 1]));
        tm = fmaxf(tm, __shfl_xor_sync(0xffffffffu, tm, 1));
        tm = fmaxf(tm, __shfl_xor_sync(0xffffffffu, tm, 2));
        const float mn = fmaxf(m2[h], tm);
        const float corr = exp2f(m2[h] - mn);
        m2[h] = mn;
        float rs = 0.f;
#pragma unroll
        for (int nf = 0; nf < 8; nf++) {
            const float e0 = exp2f(sfr[nf][2 * h] - mn);
            const float e1 = exp2f(sfr[nf][2 * h + 1] - mn);
            sfr[nf][2 * h] = e0;
            sfr[nf][2 * h + 1] = e1;
            rs += e0 + e1;
        }
        rs += __shfl_xor_sync(0xffffffffu, rs, 1);
        rs += __shfl_xor_sync(0xffffffffu, rs, 2);
        lsum[h] = lsum[h] * corr + rs;
#pragma unroll
        for (int nf = 0; nf < 16; nf++) {
            acc[nf][2 * h] *= corr;
            acc[nf][2 * h + 1] *= corr;
        }
    }
}

__global__ void __launch_bounds__(256, 1) flash_kernel()
{
    const int tid = threadIdx.x;
    const int lane = tid & 31;
    const int wid = tid >> 5;
    const int b = blockIdx.z;
    const int n = blockIdx.y;
    const int mt = (int)gridDim.x - 1 - (int)blockIdx.x;  // big tiles launch first
    const int kvh = n >> 1;
    const int m0 = mt * 128;

    const uint32_t sb = smem_u32(dyn_smem);

    // group 0: Q (hi at stage0+0, lo at stage0+34816)
#pragma unroll
    for (int u = 0; u < 16; u++) {
        const int mtx = u >> 3;
        const int row = ((u & 7) << 4) + (tid >> 4);
        const int ch = tid & 15;
        const __nv_bfloat16* g = (mtx ? g_qlo : g_qhi) +
            (size_t)(b * LL + m0 + row) * 2048 + n * HDIM + ch * 8;
        cp16(sb + mtx * 34816 + row * FLP + ch * 16, g);
    }
    CP_COMMIT();
    fl_prefetch_kv(sb + 1 * FL_STAGE, b, kvh, 0, tid);   // group 1: KV0
    CP_COMMIT();
    fl_prefetch_kv(sb + 2 * FL_STAGE, b, kvh, 64, tid);  // group 2: KV1
    CP_COMMIT();

    const uint32_t a_off = (uint32_t)((wid * 16 + (lane & 15)) * FLP + (lane >> 4) * 16);
    const uint32_t bk_off = (uint32_t)(((lane & 7) + ((lane >> 4) << 3)) * FLP +
                                       ((lane >> 3) & 1) * 16);
    const uint32_t v_off = (uint32_t)(((lane & 7) + ((lane >> 3) & 1) * 8) * FLP +
                                      (lane >> 4) * 16);

    CP_WAIT(1);          // Q + KV0 landed
    __syncthreads();
    uint32_t qh[8][4], ql[8][4];
#pragma unroll
    for (int kf = 0; kf < 8; kf++) {
        ldsm4(qh[kf], sb + a_off + kf * 32);
        ldsm4(ql[kf], sb + 34816 + a_off + kf * 32);
    }

    float acc[16][4];
#pragma unroll
    for (int i = 0; i < 16; i++)
#pragma unroll
        for (int j = 0; j < 4; j++) acc[i][j] = 0.f;
    float m2[2] = {-1e30f, -1e30f};
    float lsum[2] = {0.f, 0.f};

    float sA[8][4], sB[8][4];
    const int nkv = 2 * (mt + 1);    // always even

    // prologue: QK(0) from stage 1
    fl_qk(sA, qh, ql, sb + 1 * FL_STAGE, bk_off);

#define FL_ITER(IT, CUR, NXT)                                                  \
    {                                                                          \
        CP_WAIT(0);          /* KV(IT+1) landed */                             \
        __syncthreads();     /* visibility + stage (IT)%3 free for refill */   \
        if ((IT) + 2 < nkv) {                                                  \
            fl_prefetch_kv(sb + ((IT) % 3) * FL_STAGE, b, kvh,                 \
                           ((IT) + 2) * 64, tid);                              \
            CP_COMMIT();                                                       \
        }                                                                      \
        fl_softmax(CUR, acc, m2, lsum, (IT), m0, wid, lane);                   \
        if ((IT) + 1 < nkv)                                                    \
            fl_qk(NXT, qh, ql, sb + (((IT) + 2) % 3) * FL_STAGE, bk_off);      \
        fl_pv(acc, CUR, sb + (((IT) + 1) % 3) * FL_STAGE + 2 * FL_KVSZ,        \
              v_off);                                                          \
    }

    for (int it = 0; it < nkv; it += 2) {
        FL_ITER(it, sA, sB);
        FL_ITER(it + 1, sB, sA);
    }
#undef FL_ITER

    // --- finalize: /l, split to bf16 hi/lo, store ---
#pragma unroll
    for (int h = 0; h < 2; h++) {
        const float inv = 1.0f / lsum[h];
        const int row = m0 + wid * 16 + (lane >> 2) + h * 8;
        const size_t base = (size_t)(b * LL + row) * 2048 + n * HDIM + 2 * (lane & 3);
#pragma unroll
        for (int nf = 0; nf < 16; nf++) {
            const float v0 = acc[nf][2 * h] * inv;
            const float v1 = acc[nf][2 * h + 1] * inv;
            const __nv_bfloat16 h0 = __float2bfloat16(v0);
            const __nv_bfloat16 h1 = __float2bfloat16(v1);
            *(uint32_t*)&g_ohi[base + nf * 8] = pack_bf2(v0, v1);
            *(uint32_t*)&g_olo[base + nf * 8] =
                pack_bf2(v0 - __bfloat162float(h0), v1 - __bfloat162float(h1));
        }
    }
}

// ---------------------------------------------------------------------------
// Launch
// ---------------------------------------------------------------------------
extern "C" void kernel_launch(void* const* d_in, const int* in_sizes, int n_in,
                              void* d_out, int out_size)
{
    const float* x   = (const float*)d_in[0];
    const int*   pos = (const int*)d_in[1];
    // d_in[2] = attn_mask (causal tril) — implied analytically, unused
    const float* wq  = (const float*)d_in[3];
    const float* wk  = (const float*)d_in[4];
    const float* wv  = (const float*)d_in[5];
    const float* wo  = (const float*)d_in[6];
    const float* qnw = (const float*)d_in[7];
    const float* knw = (const float*)d_in[8];
    float* out = (float*)d_out;

    cudaFuncSetAttribute(gemm_qkv_kernel,
                         cudaFuncAttributeMaxDynamicSharedMemorySize, GEMM_SMEM_BYTES);
    cudaFuncSetAttribute(gemm_out_kernel,
                         cudaFuncAttributeMaxDynamicSharedMemorySize, GEMM_SMEM_BYTES);
    cudaFuncSetAttribute(flash_kernel,
                         cudaFuncAttributeMaxDynamicSharedMemorySize, FL_SMEM);

    // 1. weights -> transposed bf16 hi/lo + rope tables + split X
    transpose_convert_all_kernel<<<dim3(64, 64, 4), dim3(32, 8)>>>(wq, wk, wv, wo);
    rope_table_kernel<<<(TOK * 64 + 255) / 256, 256>>>(pos);
    convert_split_x_kernel<<<(TOK * DD / 4 + 255) / 256, 256>>>(x);

    // 2. QKV projection (R9 wave-launched 128x128) with fused epilogue
    gemm_qkv_kernel<<<dim3(QKVW / 128, TOK / 128), 256, GEMM_SMEM_BYTES>>>(qnw, knw);

    // 3. Flash attention (R12 software-pipelined)
    flash_kernel<<<dim3(LL / 128, NHEADS, BB), 256, FL_SMEM>>>();

    // 4. output projection (R9 wave-launched 128x128)
    gemm_out_kernel<<<dim3(DD / 128, TOK / 128), 256, GEMM_SMEM_BYTES>>>(out);
}

// round 14
// speedup vs baseline: 1.0132x; 1.0024x over previous
#include <cuda_runtime.h>
#include <cuda_bf16.h>
#include <math.h>
#include <stdint.h>

// Problem constants
#define BB 2
#define LL 2048
#define DD 2048
#define NHEADS 16
#define KHEADS 8
#define HDIM 128
#define TOK (BB * LL)        // 4096
#define EPSV 1e-6f
#define QKVW 4096            // concatenated qkv col space (q:0..2047, k:..3071, v:..4095)

// ---------------------------------------------------------------------------
// Scratch (device globals — no runtime allocation allowed)
// ---------------------------------------------------------------------------
__device__ __align__(16) __nv_bfloat16 g_xhi[(size_t)TOK * DD];
__device__ __align__(16) __nv_bfloat16 g_xlo[(size_t)TOK * DD];
__device__ __align__(16) __nv_bfloat16 g_qhi[(size_t)TOK * DD];     // normed/rope'd/pre-scaled q
__device__ __align__(16) __nv_bfloat16 g_qlo[(size_t)TOK * DD];
__device__ __align__(16) __nv_bfloat16 g_khi[(size_t)TOK * KHEADS * HDIM];
__device__ __align__(16) __nv_bfloat16 g_klo[(size_t)TOK * KHEADS * HDIM];
__device__ __align__(16) __nv_bfloat16 g_vhi[(size_t)TOK * KHEADS * HDIM];
__device__ __align__(16) __nv_bfloat16 g_vlo[(size_t)TOK * KHEADS * HDIM];
__device__ __align__(16) __nv_bfloat16 g_ohi[(size_t)TOK * DD];     // attention out
__device__ __align__(16) __nv_bfloat16 g_olo[(size_t)TOK * DD];
__device__ __align__(16) __nv_bfloat16 g_wthi[(size_t)QKVW * DD];   // [n][k] qkv weights
__device__ __align__(16) __nv_bfloat16 g_wtlo[(size_t)QKVW * DD];
__device__ __align__(16) __nv_bfloat16 g_wothi[(size_t)DD * DD];    // [n][k] wo
__device__ __align__(16) __nv_bfloat16 g_wotlo[(size_t)DD * DD];
__device__ __align__(16) float g_rsin[(size_t)TOK * 64];            // rope tables
__device__ __align__(16) float g_rcos[(size_t)TOK * 64];

extern __shared__ char dyn_smem[];

// ---------------------------------------------------------------------------
// PTX helpers (family-portable: cp.async / ldmatrix / mma.sync)
// ---------------------------------------------------------------------------
__device__ __forceinline__ uint32_t smem_u32(const void* p) {
    uint32_t a;
    asm("{ .reg .u64 t; cvta.to.shared.u64 t, %1; cvt.u32.u64 %0, t; }"
        : "=r"(a) : "l"(p));
    return a;
}

__device__ __forceinline__ void cp16(uint32_t dst, const void* src) {
    asm volatile("cp.async.cg.shared.global [%0], [%1], 16;" :: "r"(dst), "l"(src));
}
#define CP_COMMIT() asm volatile("cp.async.commit_group;" ::: "memory")
#define CP_WAIT(N)  asm volatile("cp.async.wait_group %0;" :: "n"(N) : "memory")

__device__ __forceinline__ void ldsm4(uint32_t* r, uint32_t a) {
    asm volatile("ldmatrix.sync.aligned.m8n8.x4.shared.b16 {%0,%1,%2,%3}, [%4];"
        : "=r"(r[0]), "=r"(r[1]), "=r"(r[2]), "=r"(r[3]) : "r"(a));
}
__device__ __forceinline__ void ldsm4t(uint32_t* r, uint32_t a) {
    asm volatile("ldmatrix.sync.aligned.m8n8.x4.trans.shared.b16 {%0,%1,%2,%3}, [%4];"
        : "=r"(r[0]), "=r"(r[1]), "=r"(r[2]), "=r"(r[3]) : "r"(a));
}

__device__ __forceinline__ void mma_bf16(float* c, const uint32_t* a, const uint32_t* b) {
    asm volatile(
        "mma.sync.aligned.m16n8k16.row.col.f32.bf16.bf16.f32 "
        "{%0,%1,%2,%3}, {%4,%5,%6,%7}, {%8,%9}, {%0,%1,%2,%3};"
        : "+f"(c[0]), "+f"(c[1]), "+f"(c[2]), "+f"(c[3])
        : "r"(a[0]), "r"(a[1]), "r"(a[2]), "r"(a[3]), "r"(b[0]), "r"(b[1]));
}

__device__ __forceinline__ uint32_t pack_bf2(float x, float y) {
    __nv_bfloat162 t;
    t.x = __float2bfloat16(x);
    t.y = __float2bfloat16(y);
    return *(uint32_t*)&t;
}

// ---------------------------------------------------------------------------
// Conversion / table kernels
// ---------------------------------------------------------------------------
__global__ void __launch_bounds__(256) transpose_convert_all_kernel(
    const float* __restrict__ wq, const float* __restrict__ wk,
    const float* __restrict__ wv, const float* __restrict__ wo)
{
    const int z = blockIdx.z;
    const float* src;
    int C, row_off;
    __nv_bfloat16 *dhi, *dlo;
    if (z == 0)      { src = wq; C = 2048; row_off = 0;    dhi = g_wthi;  dlo = g_wtlo;  }
    else if (z == 1) { if (blockIdx.x >= 32) return;
                       src = wk; C = 1024; row_off = 2048; dhi = g_wthi;  dlo = g_wtlo;  }
    else if (z == 2) { if (blockIdx.x >= 32) return;
                       src = wv; C = 1024; row_off = 3072; dhi = g_wthi;  dlo = g_wtlo;  }
    else             { src = wo; C = 2048; row_off = 0;    dhi = g_wothi; dlo = g_wotlo; }

    __shared__ float t[32][33];
    const int c0 = blockIdx.x * 32;
    const int r0 = blockIdx.y * 32;
    const int tx = threadIdx.x;
    const int ty = threadIdx.y;

#pragma unroll
    for (int j = 0; j < 4; j++)
        t[ty + j * 8][tx] = src[(size_t)(r0 + ty + j * 8) * C + c0 + tx];
    __syncthreads();

#pragma unroll
    for (int j = 0; j < 4; j++) {
        const int i = ty + j * 8;
        const float v = t[tx][i];
        const __nv_bfloat16 h = __float2bfloat16(v);
        const __nv_bfloat16 l = __float2bfloat16(v - __bfloat162float(h));
        const size_t off = (size_t)(row_off + c0 + i) * DD + r0 + tx;
        dhi[off] = h;
        dlo[off] = l;
    }
}

__global__ void __launch_bounds__(256) convert_split_x_kernel(const float* __restrict__ src)
{
    const size_t i = (size_t)blockIdx.x * blockDim.x + threadIdx.x;
    const size_t n4 = (size_t)TOK * DD / 4;
    if (i >= n4) return;
    const float4 v = ((const float4*)src)[i];
    __nv_bfloat16 h0 = __float2bfloat16(v.x);
    __nv_bfloat16 h1 = __float2bfloat16(v.y);
    __nv_bfloat16 h2 = __float2bfloat16(v.z);
    __nv_bfloat16 h3 = __float2bfloat16(v.w);
    uint2 hp, lp;
    hp.x = pack_bf2(v.x, v.y);
    hp.y = pack_bf2(v.z, v.w);
    lp.x = pack_bf2(v.x - __bfloat162float(h0), v.y - __bfloat162float(h1));
    lp.y = pack_bf2(v.z - __bfloat162float(h2), v.w - __bfloat162float(h3));
    ((uint2*)g_xhi)[i] = hp;
    ((uint2*)g_xlo)[i] = lp;
}

// RoPE tables: sin/cos per (token, freq-pair). One-time, full-precision.
__global__ void __launch_bounds__(256) rope_table_kernel(const int* __restrict__ pos_ids)
{
    const int idx = blockIdx.x * 256 + threadIdx.x;
    if (idx >= TOK * 64) return;
    const int token = idx >> 6;
    const int p = idx & 63;
    const double L2T = 19.931568569324174;   // log2(1e6)
    const float inv_ts = exp2f((float)(-(double)p * L2T / 64.0));
    const float ang = (float)pos_ids[token] * inv_ts;
    float sv, cv;
    sincosf(ang, &sv, &cv);
    g_rsin[idx] = sv;
    g_rcos[idx] = cv;
}

// ---------------------------------------------------------------------------
// split-bf16 warp-MMA GEMM tile body: C = A * B^T, CTA tile 128x128, BK=32,
// 256 threads, 8 warps (2m x 4n), warp tile 64x32, XOR-swizzled 64B pitch,
// 3-stage cp.async ring, product-major MMAs.
//   qkv kernel: wave-launched (measured best), fused norm/rope/split epilogue.
//   out kernel: PERSISTENT CTAs (measured best: kills the 1.73-wave tail).
// ---------------------------------------------------------------------------
#define BK 32
#define PITCH 64
#define MAT_BYTES (128 * PITCH)           // 8192 per split
#define STAGE_BYTES (4 * MAT_BYTES)       // 32768
#define GEMM_SMEM_BYTES (3 * STAGE_BYTES) // 98304 (x2 CTAs = 196KB)
#define EPI_PITCH 132                     // fp32 words per row in epilogue buffer

__device__ __forceinline__ uint32_t gswz(int r, int c) {
    return (uint32_t)(r * PITCH + ((c ^ ((r >> 1) & 3)) << 4));
}

__device__ __forceinline__ void prefetch_stage(
    uint32_t sbase,
    const __nv_bfloat16* __restrict__ Ahi, const __nv_bfloat16* __restrict__ Alo,
    const __nv_bfloat16* __restrict__ Bhi, const __nv_bfloat16* __restrict__ Blo,
    int m0, int n0, int k0, int ldA, int ldB, int tid)
{
#pragma unroll
    for (int j = 0; j < 2; j++) {
        const int id = tid * 2 + j;
        const int r = id >> 2;
        const int c = id & 3;
        const uint32_t soff = gswz(r, c);
        const size_t ga = (size_t)(m0 + r) * ldA + k0 + c * 8;
        const size_t gb = (size_t)(n0 + r) * ldB + k0 + c * 8;
        cp16(sbase + soff,                 Ahi + ga);
        cp16(sbase + MAT_BYTES + soff,     Alo + ga);
        cp16(sbase + 2 * MAT_BYTES + soff, Bhi + gb);
        cp16(sbase + 3 * MAT_BYTES + soff, Blo + gb);
    }
}

template <int FUSED>
__device__ __forceinline__ void gemm_tile(
    const __nv_bfloat16* __restrict__ Ahi, const __nv_bfloat16* __restrict__ Alo,
    const __nv_bfloat16* __restrict__ Bhi, const __nv_bfloat16* __restrict__ Blo,
    float* __restrict__ Cc, int ldC, int m0, int n0,
    const float* __restrict__ qnw, const float* __restrict__ knw)
{
    const int tid  = threadIdx.x;             // 256 threads
    const int lane = tid & 31;
    const int wid  = tid >> 5;                // 0..7
    const int wm   = wid & 1;
    const int wn   = wid >> 1;
    const uint32_t smem_base = smem_u32(dyn_smem);

    float c[4][4][4];
#pragma unroll
    for (int i = 0; i < 4; i++)
#pragma unroll
        for (int j = 0; j < 4; j++)
#pragma unroll
            for (int k = 0; k < 4; k++) c[i][j][k] = 0.f;

    const int a_row  = wm * 64 + (lane & 15);
    const int a_swz  = (a_row >> 1) & 3;
    const uint32_t a_base = (uint32_t)(a_row * PITCH);
    const int a_c0   = lane >> 4;
    const int b_row  = wn * 32 + (lane & 7) + ((lane >> 4) << 3);
    const int b_swz  = (b_row >> 1) & 3;
    const uint32_t b_base = (uint32_t)(b_row * PITCH);
    const int b_c0   = (lane >> 3) & 1;

    const int nk = DD / BK;

    prefetch_stage(smem_base, Ahi, Alo, Bhi, Blo, m0, n0, 0, DD, DD, tid);
    CP_COMMIT();
    prefetch_stage(smem_base + STAGE_BYTES, Ahi, Alo, Bhi, Blo, m0, n0, BK, DD, DD, tid);
    CP_COMMIT();

    int slot = 0;
    for (int it = 0; it < nk; it++) {
        if (it < nk - 1) { CP_WAIT(1); } else { CP_WAIT(0); }
        __syncthreads();

        if (it + 2 < nk) {
            int ps = slot + 2;
            if (ps >= 3) ps -= 3;
            prefetch_stage(smem_base + ps * STAGE_BYTES,
                           Ahi, Alo, Bhi, Blo, m0, n0, (it + 2) * BK, DD, DD, tid);
            CP_COMMIT();
        }

        const uint32_t sA = smem_base + slot * STAGE_BYTES;
        const uint32_t sB = sA + 2 * MAT_BYTES;

#pragma unroll
        for (int kf = 0; kf < 2; kf++) {
            uint32_t b[2][2][4];
            const uint32_t a_coff = (uint32_t)(((a_c0 + kf * 2) ^ a_swz) << 4);
            const uint32_t b_coff = (uint32_t)(((b_c0 + kf * 2) ^ b_swz) << 4);
#pragma unroll
            for (int nf2 = 0; nf2 < 2; nf2++) {
                const uint32_t bd = sB + b_base + nf2 * (16 * PITCH) + b_coff;
                ldsm4(b[0][nf2], bd);
                ldsm4(b[1][nf2], bd + MAT_BYTES);
            }
#pragma unroll
            for (int mf = 0; mf < 4; mf++) {
                uint32_t ah[4], al[4];
                const uint32_t ad = sA + a_base + mf * (16 * PITCH) + a_coff;
                ldsm4(ah, ad);
                ldsm4(al, ad + MAT_BYTES);
#pragma unroll
                for (int nf = 0; nf < 4; nf++)
                    mma_bf16(c[mf][nf], ah, &b[0][nf >> 1][(nf & 1) * 2]);
#pragma unroll
                for (int nf = 0; nf < 4; nf++)
                    mma_bf16(c[mf][nf], ah, &b[1][nf >> 1][(nf & 1) * 2]);
#pragma unroll
                for (int nf = 0; nf < 4; nf++)
                    mma_bf16(c[mf][nf], al, &b[0][nf >> 1][(nf & 1) * 2]);
            }
        }

        if (++slot == 3) slot = 0;
    }

    const int gr = lane >> 2;
    const int gc = (lane & 3) * 2;

    if (FUSED == 0) {
        const int row0 = m0 + wm * 64;
        const int col0 = n0 + wn * 32;
#pragma unroll
        for (int mf = 0; mf < 4; mf++)
#pragma unroll
            for (int nf = 0; nf < 4; nf++) {
                float* cc = c[mf][nf];
                const int r = row0 + mf * 16 + gr;
                const int cl = col0 + nf * 8 + gc;
                *(float2*)&Cc[(size_t)r * ldC + cl]       = make_float2(cc[0], cc[1]);
                *(float2*)&Cc[(size_t)(r + 8) * ldC + cl] = make_float2(cc[2], cc[3]);
            }
        return;
    }

    // --- FUSED epilogue: SMEM bounce + RMSNorm + RoPE + hi/lo split ---
    float* Sb = (float*)dyn_smem;
    __syncthreads();
    {
        const int row0 = wm * 64;
        const int col0 = wn * 32;
#pragma unroll
        for (int mf = 0; mf < 4; mf++)
#pragma unroll
            for (int nf = 0; nf < 4; nf++) {
                float* cc = c[mf][nf];
                const int r = row0 + mf * 16 + gr;
                const int cl = col0 + nf * 8 + gc;
                *(float2*)&Sb[r * EPI_PITCH + cl]       = make_float2(cc[0], cc[1]);
                *(float2*)&Sb[(r + 8) * EPI_PITCH + cl] = make_float2(cc[2], cc[3]);
            }
    }
    __syncthreads();

    const bool isq = (n0 < 2048);
    const bool isv = (n0 >= 3072);
    __nv_bfloat16 *dhi, *dlo;
    int colbase, ldd;
    if (isq)              { dhi = g_qhi; dlo = g_qlo; colbase = n0;        ldd = 2048; }
    else if (n0 < 3072)   { dhi = g_khi; dlo = g_klo; colbase = n0 - 2048; ldd = 1024; }
    else                  { dhi = g_vhi; dlo = g_vlo; colbase = n0 - 3072; ldd = 1024; }

    const float QS = isq ? 0.08838834764831845f * 1.4426950408889634f : 1.0f;
    const bool firsthalf = lane < 16;
    const int pbase = (lane & 15) * 4;

    float4 w4 = make_float4(1.f, 1.f, 1.f, 1.f);
    if (!isv) {
        const float* nw = isq ? qnw : knw;
        w4 = *(const float4*)&nw[lane * 4];
    }

#pragma unroll 1
    for (int i = 0; i < 16; i++) {
        const int row = wid * 16 + i;
        const int token = m0 + row;
        float4 xv = *(float4*)&Sb[row * EPI_PITCH + lane * 4];
        float r0, r1, r2, r3;
        if (!isv) {
            float ss = xv.x * xv.x + xv.y * xv.y + xv.z * xv.z + xv.w * xv.w;
#pragma unroll
            for (int m = 16; m; m >>= 1) ss += __shfl_xor_sync(0xffffffffu, ss, m);
            const float rinv = rsqrtf(ss * (1.0f / HDIM) + EPSV);
            const float nn0 = xv.x * w4.x * rinv;
            const float nn1 = xv.y * w4.y * rinv;
            const float nn2 = xv.z * w4.z * rinv;
            const float nn3 = xv.w * w4.w * rinv;
            const float pp0 = __shfl_xor_sync(0xffffffffu, nn0, 16);
            const float pp1 = __shfl_xor_sync(0xffffffffu, nn1, 16);
            const float pp2 = __shfl_xor_sync(0xffffffffu, nn2, 16);
            const float pp3 = __shfl_xor_sync(0xffffffffu, nn3, 16);
            const float4 sn = *(const float4*)&g_rsin[(size_t)token * 64 + pbase];
            const float4 cs = *(const float4*)&g_rcos[(size_t)token * 64 + pbase];
            if (firsthalf) {
                r0 = (nn0 * cs.x - pp0 * sn.x) * QS;
                r1 = (nn1 * cs.y - pp1 * sn.y) * QS;
                r2 = (nn2 * cs.z - pp2 * sn.z) * QS;
                r3 = (nn3 * cs.w - pp3 * sn.w) * QS;
            } else {
                r0 = (nn0 * cs.x + pp0 * sn.x) * QS;
                r1 = (nn1 * cs.y + pp1 * sn.y) * QS;
                r2 = (nn2 * cs.z + pp2 * sn.z) * QS;
                r3 = (nn3 * cs.w + pp3 * sn.w) * QS;
            }
        } else {
            r0 = xv.x; r1 = xv.y; r2 = xv.z; r3 = xv.w;
        }
        const __nv_bfloat16 h0 = __float2bfloat16(r0);
        const __nv_bfloat16 h1 = __float2bfloat16(r1);
        const __nv_bfloat16 h2 = __float2bfloat16(r2);
        const __nv_bfloat16 h3 = __float2bfloat16(r3);
        uint2 hp, lp;
        hp.x = pack_bf2(r0, r1);
        hp.y = pack_bf2(r2, r3);
        lp.x = pack_bf2(r0 - __bfloat162float(h0), r1 - __bfloat162float(h1));
        lp.y = pack_bf2(r2 - __bfloat162float(h2), r3 - __bfloat162float(h3));
        const size_t off = (size_t)token * ldd + colbase + lane * 4;
        *(uint2*)&dhi[off] = hp;
        *(uint2*)&dlo[off] = lp;
    }
}

// qkv: wave-launched (measured best for 3.46-wave grids)
__global__ void __launch_bounds__(256, 2) gemm_qkv_kernel(
    const float* __restrict__ qnw, const float* __restrict__ knw) {
    gemm_tile<1>(g_xhi, g_xlo, g_wthi, g_wtlo, nullptr, 0,
                 blockIdx.y * 128, blockIdx.x * 128, qnw, knw);
}

// out: persistent (measured best for 1.73-wave grids — tail elimination wins)
__global__ void __launch_bounds__(256, 2) gemm_out_kernel(float* __restrict__ out) {
    for (int t = blockIdx.x; t < 512; t += gridDim.x) {
        const int m0 = (t / 16) * 128;
        const int n0 = (t % 16) * 128;
        __syncthreads();   // previous tile's smem reads complete
        gemm_tile<0>(g_ohi, g_olo, g_wothi, g_wotlo, out, DD, m0, n0,
                     nullptr, nullptr);
    }
}

// ---------------------------------------------------------------------------
// Flash attention (R12/R13 exact): software-pipelined — QK(it+1) between
// softmax(it) and PV(it), double score buffer, KV in one commit group per
// stage, 3-stage ring, Q in registers.
// ---------------------------------------------------------------------------
#define FLP 272
#define FL_KVSZ (64 * FLP)          // 17408
#define FL_STAGE (4 * FL_KVSZ)      // 69632
#define FL_SMEM (3 * FL_STAGE)      // 208896

__device__ __forceinline__ void fl_prefetch_kv(
    uint32_t sbase, int b, int kvh, int kv0, int tid)
{
#pragma unroll
    for (int u = 0; u < 16; u++) {
        const int mtx = u >> 2;                      // 0:Khi 1:Klo 2:Vhi 3:Vlo
        const int row = ((u & 3) << 4) + (tid >> 4); // 0..63
        const int ch = tid & 15;
        const __nv_bfloat16* g;
        if (mtx == 0)      g = g_khi;
        else if (mtx == 1) g = g_klo;
        else if (mtx == 2) g = g_vhi;
        else               g = g_vlo;
        g += (size_t)(b * LL + kv0 + row) * 1024 + kvh * HDIM + ch * 8;
        cp16(sbase + mtx * FL_KVSZ + row * FLP + ch * 16, g);
    }
}

__device__ __forceinline__ void fl_qk(
    float (&s)[8][4],
    const uint32_t (&qh)[8][4], const uint32_t (&ql)[8][4],
    uint32_t sK, uint32_t bk_off)
{
#pragma unroll
    for (int i = 0; i < 8; i++)
#pragma unroll
        for (int j = 0; j < 4; j++) s[i][j] = 0.f;
#pragma unroll
    for (int kf = 0; kf < 8; kf++) {
        uint32_t bh[4][4], bl[4][4];
#pragma unroll
        for (int p2 = 0; p2 < 4; p2++) {
            ldsm4(bh[p2], sK + bk_off + p2 * 16 * FLP + kf * 32);
            ldsm4(bl[p2], sK + FL_KVSZ + bk_off + p2 * 16 * FLP + kf * 32);
        }
#pragma unroll
        for (int p2 = 0; p2 < 4; p2++) {
            mma_bf16(s[2 * p2],     qh[kf], bh[p2]);
            mma_bf16(s[2 * p2 + 1], qh[kf], bh[p2] + 2);
        }
#pragma unroll
        for (int p2 = 0; p2 < 4; p2++) {
            mma_bf16(s[2 * p2],     qh[kf], bl[p2]);
            mma_bf16(s[2 * p2 + 1], qh[kf], bl[p2] + 2);
        }
#pragma unroll
        for (int p2 = 0; p2 < 4; p2++) {
            mma_bf16(s[2 * p2],     ql[kf], bh[p2]);
            mma_bf16(s[2 * p2 + 1], ql[kf], bh[p2] + 2);
        }
    }
}

__device__ __forceinline__ void fl_pv(
    float (&acc)[16][4], const float (&p)[8][4], uint32_t sVhi, uint32_t v_off)
{
    const uint32_t sVlo = sVhi + FL_KVSZ;
#pragma unroll
    for (int j = 0; j < 4; j++) {
        uint32_t ph[4], pl[4];
#pragma unroll
        for (int q = 0; q < 4; q++) {
            const int nf = 2 * j + (q >> 1);
            const int rb = (q & 1) * 2;
            const float v0 = p[nf][rb], v1 = p[nf][rb + 1];
            const __nv_bfloat16 h0 = __float2bfloat16(v0);
            const __nv_bfloat16 h1 = __float2bfloat16(v1);
            ph[q] = pack_bf2(v0, v1);
            pl[q] = pack_bf2(v0 - __bfloat162float(h0), v1 - __bfloat162float(h1));
        }
#pragma unroll
        for (int t2 = 0; t2 < 4; t2++) {
            uint32_t vh0[4], vl0[4], vh1[4], vl1[4];
            const uint32_t vb = sVhi + v_off + j * 16 * FLP;
            const uint32_t lb = sVlo + v_off + j * 16 * FLP;
            ldsm4t(vh0, vb + (2 * t2) * 32);
            ldsm4t(vl0, lb + (2 * t2) * 32);
            ldsm4t(vh1, vb + (2 * t2 + 1) * 32);
            ldsm4t(vl1, lb + (2 * t2 + 1) * 32);
            float* a0 = acc[4 * t2];
            float* a1 = acc[4 * t2 + 1];
            float* a2 = acc[4 * t2 + 2];
            float* a3 = acc[4 * t2 + 3];
            mma_bf16(a0, ph, vh0); mma_bf16(a1, ph, vh0 + 2);
            mma_bf16(a2, ph, vh1); mma_bf16(a3, ph, vh1 + 2);
            mma_bf16(a0, ph, vl0); mma_bf16(a1, ph, vl0 + 2);
            mma_bf16(a2, ph, vl1); mma_bf16(a3, ph, vl1 + 2);
            mma_bf16(a0, pl, vh0); mma_bf16(a1, pl, vh0 + 2);
            mma_bf16(a2, pl, vh1); mma_bf16(a3, pl, vh1 + 2);
        }
    }
}

__device__ __forceinline__ void fl_softmax(
    float (&sfr)[8][4], float (&acc)[16][4], float (&m2)[2], float (&lsum)[2],
    int it, int m0, int wid, int lane)
{
    const int rbase = m0 + wid * 16 + (lane >> 2);
    if (it * 64 + 63 > m0 + wid * 16) {
#pragma unroll
        for (int nf = 0; nf < 8; nf++) {
            const int cg = it * 64 + nf * 8 + 2 * (lane & 3);
#pragma unroll
            for (int rg = 0; rg < 4; rg++) {
                const int row = rbase + (rg >> 1) * 8;
                const int col = cg + (rg & 1);
                if (col > row) sfr[nf][rg] = -1e30f;
            }
        }
    }
#pragma unroll
    for (int h = 0; h < 2; h++) {
        float tm = -1e30f;
#pragma unroll
        for (int nf = 0; nf < 8; nf++)
            tm = fmaxf(tm, fmaxf(sfr[nf][2 * h], sfr[nf][2 * h + 1]));
        tm = fmaxf(tm, __shfl_xor_sync(0xffffffffu, tm, 1));
        tm = fmaxf(tm, __shfl_xor_sync(0xffffffffu, tm, 2));
        const float mn = fmaxf(m2[h], tm);
        const float corr = exp2f(m2[h] - mn);
        m2[h] = mn;
        float rs = 0.f;
#pragma unroll
        for (int nf = 0; nf < 8; nf++) {
            const float e0 = exp2f(sfr[nf][2 * h] - mn);
            const float e1 = exp2f(sfr[nf][2 * h + 1] - mn);
            sfr[nf][2 * h] = e0;
            sfr[nf][2 * h + 1] = e1;
            rs += e0 + e1;
        }
        rs += __shfl_xor_sync(0xffffffffu, rs, 1);
        rs += __shfl_xor_sync(0xffffffffu, rs, 2);
        lsum[h] = lsum[h] * corr + rs;
#pragma unroll
        for (int nf = 0; nf < 16; nf++) {
            acc[nf][2 * h] *= corr;
            acc[nf][2 * h + 1] *= corr;
        }
    }
}

__global__ void __launch_bounds__(256, 1) flash_kernel()
{
    const int tid = threadIdx.x;
    const int lane = tid & 31;
    const int wid = tid >> 5;
    const int b = blockIdx.z;
    const int n = blockIdx.y;
    const int mt = (int)gridDim.x - 1 - (int)blockIdx.x;  // big tiles launch first
    const int kvh = n >> 1;
    const int m0 = mt * 128;

    const uint32_t sb = smem_u32(dyn_smem);

    // group 0: Q (hi at stage0+0, lo at stage0+34816)
#pragma unroll
    for (int u = 0; u < 16; u++) {
        const int mtx = u >> 3;
        const int row = ((u & 7) << 4) + (tid >> 4);
        const int ch = tid & 15;
        const __nv_bfloat16* g = (mtx ? g_qlo : g_qhi) +
            (size_t)(b * LL + m0 + row) * 2048 + n * HDIM + ch * 8;
        cp16(sb + mtx * 34816 + row * FLP + ch * 16, g);
    }
    CP_COMMIT();
    fl_prefetch_kv(sb + 1 * FL_STAGE, b, kvh, 0, tid);   // group 1: KV0
    CP_COMMIT();
    fl_prefetch_kv(sb + 2 * FL_STAGE, b, kvh, 64, tid);  // group 2: KV1
    CP_COMMIT();

    const uint32_t a_off = (uint32_t)((wid * 16 + (lane & 15)) * FLP + (lane >> 4) * 16);
    const uint32_t bk_off = (uint32_t)(((lane & 7) + ((lane >> 4) << 3)) * FLP +
                                       ((lane >> 3) & 1) * 16);
    const uint32_t v_off = (uint32_t)(((lane & 7) + ((lane >> 3) & 1) * 8) * FLP +
                                      (lane >> 4) * 16);

    CP_WAIT(1);          // Q + KV0 landed
    __syncthreads();
    uint32_t qh[8][4], ql[8][4];
#pragma unroll
    for (int kf = 0; kf < 8; kf++) {
        ldsm4(qh[kf], sb + a_off + kf * 32);
        ldsm4(ql[kf], sb + 34816 + a_off + kf * 32);
    }

    float acc[16][4];
#pragma unroll
    for (int i = 0; i < 16; i++)
#pragma unroll
        for (int j = 0; j < 4; j++) acc[i][j] = 0.f;
    float m2[2] = {-1e30f, -1e30f};
    float lsum[2] = {0.f, 0.f};

    float sA[8][4], sB[8][4];
    const int nkv = 2 * (mt + 1);    // always even

    // prologue: QK(0) from stage 1
    fl_qk(sA, qh, ql, sb + 1 * FL_STAGE, bk_off);

#define FL_ITER(IT, CUR, NXT)                                                  \
    {                                                                          \
        CP_WAIT(0);          /* KV(IT+1) landed */                             \
        __syncthreads();     /* visibility + stage (IT)%3 free for refill */   \
        if ((IT) + 2 < nkv) {                                                  \
            fl_prefetch_kv(sb + ((IT) % 3) * FL_STAGE, b, kvh,                 \
                           ((IT) + 2) * 64, tid);                              \
            CP_COMMIT();                                                       \
        }                                                                      \
        fl_softmax(CUR, acc, m2, lsum, (IT), m0, wid, lane);                   \
        if ((IT) + 1 < nkv)                                                    \
            fl_qk(NXT, qh, ql, sb + (((IT) + 2) % 3) * FL_STAGE, bk_off);      \
        fl_pv(acc, CUR, sb + (((IT) + 1) % 3) * FL_STAGE + 2 * FL_KVSZ,        \
              v_off);                                                          \
    }

    for (int it = 0; it < nkv; it += 2) {
        FL_ITER(it, sA, sB);
        FL_ITER(it + 1, sB, sA);
    }
#undef FL_ITER

    // --- finalize: /l, split to bf16 hi/lo, store ---
#pragma unroll
    for (int h = 0; h < 2; h++) {
        const float inv = 1.0f / lsum[h];
        const int row = m0 + wid * 16 + (lane >> 2) + h * 8;
        const size_t base = (size_t)(b * LL + row) * 2048 + n * HDIM + 2 * (lane & 3);
#pragma unroll
        for (int nf = 0; nf < 16; nf++) {
            const float v0 = acc[nf][2 * h] * inv;
            const float v1 = acc[nf][2 * h + 1] * inv;
            const __nv_bfloat16 h0 = __float2bfloat16(v0);
            const __nv_bfloat16 h1 = __float2bfloat16(v1);
            *(uint32_t*)&g_ohi[base + nf * 8] = pack_bf2(v0, v1);
            *(uint32_t*)&g_olo[base + nf * 8] =
                pack_bf2(v0 - __bfloat162float(h0), v1 - __bfloat162float(h1));
        }
    }
}

// ---------------------------------------------------------------------------
// Launch
// ---------------------------------------------------------------------------
extern "C" void kernel_launch(void* const* d_in, const int* in_sizes, int n_in,
                              void* d_out, int out_size)
{
    const float* x   = (const float*)d_in[0];
    const int*   pos = (const int*)d_in[1];
    // d_in[2] = attn_mask (causal tril) — implied analytically, unused
    const float* wq  = (const float*)d_in[3];
    const float* wk  = (const float*)d_in[4];
    const float* wv  = (const float*)d_in[5];
    const float* wo  = (const float*)d_in[6];
    const float* qnw = (const float*)d_in[7];
    const float* knw = (const float*)d_in[8];
    float* out = (float*)d_out;

    cudaFuncSetAttribute(gemm_qkv_kernel,
                         cudaFuncAttributeMaxDynamicSharedMemorySize, GEMM_SMEM_BYTES);
    cudaFuncSetAttribute(gemm_out_kernel,
                         cudaFuncAttributeMaxDynamicSharedMemorySize, GEMM_SMEM_BYTES);
    cudaFuncSetAttribute(flash_kernel,
                         cudaFuncAttributeMaxDynamicSharedMemorySize, FL_SMEM);

    int dev = 0, sms = 148;
    cudaGetDevice(&dev);
    cudaDeviceGetAttribute(&sms, cudaDevAttrMultiProcessorCount, dev);

    // 1. weights -> transposed bf16 hi/lo + rope tables + split X
    transpose_convert_all_kernel<<<dim3(64, 64, 4), dim3(32, 8)>>>(wq, wk, wv, wo);
    rope_table_kernel<<<(TOK * 64 + 255) / 256, 256>>>(pos);
    convert_split_x_kernel<<<(TOK * DD / 4 + 255) / 256, 256>>>(x);

    // 2. QKV projection (wave-launched, fused epilogue)
    gemm_qkv_kernel<<<dim3(QKVW / 128, TOK / 128), 256, GEMM_SMEM_BYTES>>>(qnw, knw);

    // 3. Flash attention (software-pipelined)
    flash_kernel<<<dim3(LL / 128, NHEADS, BB), 256, FL_SMEM>>>();

    // 4. output projection (persistent — measured winner for this grid)
    gemm_out_kernel<<<sms * 2, 256, GEMM_SMEM_BYTES>>>(out);
}

// round 15
// speedup vs baseline: 1.1678x; 1.1525x over previous
#include <cuda_runtime.h>
#include <cuda_bf16.h>
#include <math.h>
#include <stdint.h>

// Problem constants
#define BB 2
#define LL 2048
#define DD 2048
#define NHEADS 16
#define KHEADS 8
#define HDIM 128
#define TOK (BB * LL)        // 4096
#define EPSV 1e-6f
#define QKVW 4096            // concatenated qkv col space (q:0..2047, k:..3071, v:..4095)

// ---------------------------------------------------------------------------
// Scratch (device globals — no runtime allocation allowed)
// ---------------------------------------------------------------------------
__device__ __align__(16) __nv_bfloat16 g_xhi[(size_t)TOK * DD];
__device__ __align__(16) __nv_bfloat16 g_xlo[(size_t)TOK * DD];
__device__ __align__(16) __nv_bfloat16 g_qhi[(size_t)TOK * DD];     // normed/rope'd/pre-scaled q
__device__ __align__(16) __nv_bfloat16 g_qlo[(size_t)TOK * DD];
__device__ __align__(16) __nv_bfloat16 g_khi[(size_t)TOK * KHEADS * HDIM];
__device__ __align__(16) __nv_bfloat16 g_klo[(size_t)TOK * KHEADS * HDIM];
__device__ __align__(16) __nv_bfloat16 g_vhi[(size_t)TOK * KHEADS * HDIM];
__device__ __align__(16) __nv_bfloat16 g_vlo[(size_t)TOK * KHEADS * HDIM];
__device__ __align__(16) __nv_bfloat16 g_ohi[(size_t)TOK * DD];     // attention out
__device__ __align__(16) __nv_bfloat16 g_olo[(size_t)TOK * DD];
__device__ __align__(16) __nv_bfloat16 g_wthi[(size_t)QKVW * DD];   // [n][k] qkv weights
__device__ __align__(16) __nv_bfloat16 g_wtlo[(size_t)QKVW * DD];
__device__ __align__(16) __nv_bfloat16 g_wothi[(size_t)DD * DD];    // [n][k] wo
__device__ __align__(16) __nv_bfloat16 g_wotlo[(size_t)DD * DD];
__device__ __align__(16) float g_rsin[(size_t)TOK * 64];            // rope tables
__device__ __align__(16) float g_rcos[(size_t)TOK * 64];

extern __shared__ char dyn_smem[];

// ---------------------------------------------------------------------------
// PTX helpers (family-portable: cp.async / ldmatrix / mma.sync)
// ---------------------------------------------------------------------------
__device__ __forceinline__ uint32_t smem_u32(const void* p) {
    uint32_t a;
    asm("{ .reg .u64 t; cvta.to.shared.u64 t, %1; cvt.u32.u64 %0, t; }"
        : "=r"(a) : "l"(p));
    return a;
}

__device__ __forceinline__ void cp16(uint32_t dst, const void* src) {
    asm volatile("cp.async.cg.shared.global [%0], [%1], 16;" :: "r"(dst), "l"(src));
}
#define CP_COMMIT() asm volatile("cp.async.commit_group;" ::: "memory")
#define CP_WAIT(N)  asm volatile("cp.async.wait_group %0;" :: "n"(N) : "memory")

__device__ __forceinline__ void ldsm4(uint32_t* r, uint32_t a) {
    asm volatile("ldmatrix.sync.aligned.m8n8.x4.shared.b16 {%0,%1,%2,%3}, [%4];"
        : "=r"(r[0]), "=r"(r[1]), "=r"(r[2]), "=r"(r[3]) : "r"(a));
}
__device__ __forceinline__ void ldsm4t(uint32_t* r, uint32_t a) {
    asm volatile("ldmatrix.sync.aligned.m8n8.x4.trans.shared.b16 {%0,%1,%2,%3}, [%4];"
        : "=r"(r[0]), "=r"(r[1]), "=r"(r[2]), "=r"(r[3]) : "r"(a));
}

__device__ __forceinline__ void mma_bf16(float* c, const uint32_t* a, const uint32_t* b) {
    asm volatile(
        "mma.sync.aligned.m16n8k16.row.col.f32.bf16.bf16.f32 "
        "{%0,%1,%2,%3}, {%4,%5,%6,%7}, {%8,%9}, {%0,%1,%2,%3};"
        : "+f"(c[0]), "+f"(c[1]), "+f"(c[2]), "+f"(c[3])
        : "r"(a[0]), "r"(a[1]), "r"(a[2]), "r"(a[3]), "r"(b[0]), "r"(b[1]));
}

__device__ __forceinline__ uint32_t pack_bf2(float x, float y) {
    __nv_bfloat162 t;
    t.x = __float2bfloat16(x);
    t.y = __float2bfloat16(y);
    return *(uint32_t*)&t;
}

// ---------------------------------------------------------------------------
// Conversion / table kernels
// ---------------------------------------------------------------------------
__global__ void __launch_bounds__(256) transpose_convert_all_kernel(
    const float* __restrict__ wq, const float* __restrict__ wk,
    const float* __restrict__ wv, const float* __restrict__ wo)
{
    const int z = blockIdx.z;
    const float* src;
    int C, row_off;
    __nv_bfloat16 *dhi, *dlo;
    if (z == 0)      { src = wq; C = 2048; row_off = 0;    dhi = g_wthi;  dlo = g_wtlo;  }
    else if (z == 1) { if (blockIdx.x >= 32) return;
                       src = wk; C = 1024; row_off = 2048; dhi = g_wthi;  dlo = g_wtlo;  }
    else if (z == 2) { if (blockIdx.x >= 32) return;
                       src = wv; C = 1024; row_off = 3072; dhi = g_wthi;  dlo = g_wtlo;  }
    else             { src = wo; C = 2048; row_off = 0;    dhi = g_wothi; dlo = g_wotlo; }

    __shared__ float t[32][33];
    const int c0 = blockIdx.x * 32;
    const int r0 = blockIdx.y * 32;
    const int tx = threadIdx.x;
    const int ty = threadIdx.y;

#pragma unroll
    for (int j = 0; j < 4; j++)
        t[ty + j * 8][tx] = src[(size_t)(r0 + ty + j * 8) * C + c0 + tx];
    __syncthreads();

#pragma unroll
    for (int j = 0; j < 4; j++) {
        const int i = ty + j * 8;
        const float v = t[tx][i];
        const __nv_bfloat16 h = __float2bfloat16(v);
        const __nv_bfloat16 l = __float2bfloat16(v - __bfloat162float(h));
        const size_t off = (size_t)(row_off + c0 + i) * DD + r0 + tx;
        dhi[off] = h;
        dlo[off] = l;
    }
}

__global__ void __launch_bounds__(256) convert_split_x_kernel(const float* __restrict__ src)
{
    const size_t i = (size_t)blockIdx.x * blockDim.x + threadIdx.x;
    const size_t n4 = (size_t)TOK * DD / 4;
    if (i >= n4) return;
    const float4 v = ((const float4*)src)[i];
    __nv_bfloat16 h0 = __float2bfloat16(v.x);
    __nv_bfloat16 h1 = __float2bfloat16(v.y);
    __nv_bfloat16 h2 = __float2bfloat16(v.z);
    __nv_bfloat16 h3 = __float2bfloat16(v.w);
    uint2 hp, lp;
    hp.x = pack_bf2(v.x, v.y);
    hp.y = pack_bf2(v.z, v.w);
    lp.x = pack_bf2(v.x - __bfloat162float(h0), v.y - __bfloat162float(h1));
    lp.y = pack_bf2(v.z - __bfloat162float(h2), v.w - __bfloat162float(h3));
    ((uint2*)g_xhi)[i] = hp;
    ((uint2*)g_xlo)[i] = lp;
}

// RoPE tables: sin/cos per (token, freq-pair). One-time, full-precision.
__global__ void __launch_bounds__(256) rope_table_kernel(const int* __restrict__ pos_ids)
{
    const int idx = blockIdx.x * 256 + threadIdx.x;
    if (idx >= TOK * 64) return;
    const int token = idx >> 6;
    const int p = idx & 63;
    const double L2T = 19.931568569324174;   // log2(1e6)
    const float inv_ts = exp2f((float)(-(double)p * L2T / 64.0));
    const float ang = (float)pos_ids[token] * inv_ts;
    float sv, cv;
    sincosf(ang, &sv, &cv);
    g_rsin[idx] = sv;
    g_rcos[idx] = cv;
}

// ---------------------------------------------------------------------------
// split-bf16 warp-MMA GEMM: C = A * B^T, CTA tile 128x128, BK=32, 256 thr,
// 8 warps (2m x 4n), warp tile 64x32, XOR-swizzled 64B pitch, 3-stage ring.
// R15: prefetch cp.asyncs SPREAD across the MMA loops (4 parts) instead of
// one post-barrier burst — LDGSTS issue cost (4 cyc/op) no longer starves
// the HMMA pipe at iteration boundaries.
// ---------------------------------------------------------------------------
#define BK 32
#define PITCH 64
#define MAT_BYTES (128 * PITCH)           // 8192 per split
#define STAGE_BYTES (4 * MAT_BYTES)       // 32768
#define GEMM_SMEM_BYTES (3 * STAGE_BYTES) // 98304 (x2 CTAs = 196KB)
#define EPI_PITCH 132                     // fp32 words per row in epilogue buffer

__device__ __forceinline__ uint32_t gswz(int r, int c) {
    return (uint32_t)(r * PITCH + ((c ^ ((r >> 1) & 3)) << 4));
}

// 2 cp16s: A hi+lo for j-th chunk pair
__device__ __forceinline__ void prefetch_A(
    uint32_t sbase, const __nv_bfloat16* __restrict__ Ahi,
    const __nv_bfloat16* __restrict__ Alo, int m0, int k0, int j, int tid)
{
    const int id = tid * 2 + j;
    const int r = id >> 2;
    const int c = id & 3;
    const uint32_t soff = gswz(r, c);
    const size_t ga = (size_t)(m0 + r) * DD + k0 + c * 8;
    cp16(sbase + soff,             Ahi + ga);
    cp16(sbase + MAT_BYTES + soff, Alo + ga);
}
// 2 cp16s: B hi+lo for j-th chunk pair
__device__ __forceinline__ void prefetch_B(
    uint32_t sbase, const __nv_bfloat16* __restrict__ Bhi,
    const __nv_bfloat16* __restrict__ Blo, int n0, int k0, int j, int tid)
{
    const int id = tid * 2 + j;
    const int r = id >> 2;
    const int c = id & 3;
    const uint32_t soff = gswz(r, c);
    const size_t gb = (size_t)(n0 + r) * DD + k0 + c * 8;
    cp16(sbase + 2 * MAT_BYTES + soff, Bhi + gb);
    cp16(sbase + 3 * MAT_BYTES + soff, Blo + gb);
}

__device__ __forceinline__ void prefetch_stage_full(
    uint32_t sbase,
    const __nv_bfloat16* __restrict__ Ahi, const __nv_bfloat16* __restrict__ Alo,
    const __nv_bfloat16* __restrict__ Bhi, const __nv_bfloat16* __restrict__ Blo,
    int m0, int n0, int k0, int tid)
{
    prefetch_A(sbase, Ahi, Alo, m0, k0, 0, tid);
    prefetch_B(sbase, Bhi, Blo, n0, k0, 0, tid);
    prefetch_A(sbase, Ahi, Alo, m0, k0, 1, tid);
    prefetch_B(sbase, Bhi, Blo, n0, k0, 1, tid);
}

template <int FUSED>
__device__ __forceinline__ void gemm_tile(
    const __nv_bfloat16* __restrict__ Ahi, const __nv_bfloat16* __restrict__ Alo,
    const __nv_bfloat16* __restrict__ Bhi, const __nv_bfloat16* __restrict__ Blo,
    float* __restrict__ Cc, int ldC, int m0, int n0,
    const float* __restrict__ qnw, const float* __restrict__ knw)
{
    const int tid  = threadIdx.x;             // 256 threads
    const int lane = tid & 31;
    const int wid  = tid >> 5;                // 0..7
    const int wm   = wid & 1;
    const int wn   = wid >> 1;
    const uint32_t smem_base = smem_u32(dyn_smem);

    float c[4][4][4];
#pragma unroll
    for (int i = 0; i < 4; i++)
#pragma unroll
        for (int j = 0; j < 4; j++)
#pragma unroll
            for (int k = 0; k < 4; k++) c[i][j][k] = 0.f;

    const int a_row  = wm * 64 + (lane & 15);
    const int a_swz  = (a_row >> 1) & 3;
    const uint32_t a_base = (uint32_t)(a_row * PITCH);
    const int a_c0   = lane >> 4;
    const int b_row  = wn * 32 + (lane & 7) + ((lane >> 4) << 3);
    const int b_swz  = (b_row >> 1) & 3;
    const uint32_t b_base = (uint32_t)(b_row * PITCH);
    const int b_c0   = (lane >> 3) & 1;

    const int nk = DD / BK;

    prefetch_stage_full(smem_base, Ahi, Alo, Bhi, Blo, m0, n0, 0, tid);
    CP_COMMIT();
    prefetch_stage_full(smem_base + STAGE_BYTES, Ahi, Alo, Bhi, Blo, m0, n0, BK, tid);
    CP_COMMIT();

    int slot = 0;
    for (int it = 0; it < nk; it++) {
        if (it < nk - 1) { CP_WAIT(1); } else { CP_WAIT(0); }
        __syncthreads();

        const bool pf = (it + 2 < nk);
        int ps = slot + 2;
        if (ps >= 3) ps -= 3;
        const uint32_t pbase = smem_base + ps * STAGE_BYTES;
        const int pk = (it + 2) * BK;

        const uint32_t sA = smem_base + slot * STAGE_BYTES;
        const uint32_t sB = sA + 2 * MAT_BYTES;

#pragma unroll
        for (int kf = 0; kf < 2; kf++) {
            uint32_t b[2][2][4];
            const uint32_t a_coff = (uint32_t)(((a_c0 + kf * 2) ^ a_swz) << 4);
            const uint32_t b_coff = (uint32_t)(((b_c0 + kf * 2) ^ b_swz) << 4);
#pragma unroll
            for (int nf2 = 0; nf2 < 2; nf2++) {
                const uint32_t bd = sB + b_base + nf2 * (16 * PITCH) + b_coff;
                ldsm4(b[0][nf2], bd);
                ldsm4(b[1][nf2], bd + MAT_BYTES);
            }
            // spread prefetch: A-part after b-frag loads
            if (pf) prefetch_A(pbase, Ahi, Alo, m0, pk, kf, tid);
#pragma unroll
            for (int mf = 0; mf < 4; mf++) {
                uint32_t ah[4], al[4];
                const uint32_t ad = sA + a_base + mf * (16 * PITCH) + a_coff;
                ldsm4(ah, ad);
                ldsm4(al, ad + MAT_BYTES);
                // spread prefetch: B-part mid-way through the mf loop
                if (pf && mf == 2) prefetch_B(pbase, Bhi, Blo, n0, pk, kf, tid);
#pragma unroll
                for (int nf = 0; nf < 4; nf++)
                    mma_bf16(c[mf][nf], ah, &b[0][nf >> 1][(nf & 1) * 2]);
#pragma unroll
                for (int nf = 0; nf < 4; nf++)
                    mma_bf16(c[mf][nf], ah, &b[1][nf >> 1][(nf & 1) * 2]);
#pragma unroll
                for (int nf = 0; nf < 4; nf++)
                    mma_bf16(c[mf][nf], al, &b[0][nf >> 1][(nf & 1) * 2]);
            }
        }
        if (pf) CP_COMMIT();

        if (++slot == 3) slot = 0;
    }

    const int gr = lane >> 2;
    const int gc = (lane & 3) * 2;

    if (FUSED == 0) {
        const int row0 = m0 + wm * 64;
        const int col0 = n0 + wn * 32;
#pragma unroll
        for (int mf = 0; mf < 4; mf++)
#pragma unroll
            for (int nf = 0; nf < 4; nf++) {
                float* cc = c[mf][nf];
                const int r = row0 + mf * 16 + gr;
                const int cl = col0 + nf * 8 + gc;
                *(float2*)&Cc[(size_t)r * ldC + cl]       = make_float2(cc[0], cc[1]);
                *(float2*)&Cc[(size_t)(r + 8) * ldC + cl] = make_float2(cc[2], cc[3]);
            }
        return;
    }

    // --- FUSED epilogue: SMEM bounce + RMSNorm + RoPE + hi/lo split ---
    float* Sb = (float*)dyn_smem;
    __syncthreads();
    {
        const int row0 = wm * 64;
        const int col0 = wn * 32;
#pragma unroll
        for (int mf = 0; mf < 4; mf++)
#pragma unroll
            for (int nf = 0; nf < 4; nf++) {
                float* cc = c[mf][nf];
                const int r = row0 + mf * 16 + gr;
                const int cl = col0 + nf * 8 + gc;
                *(float2*)&Sb[r * EPI_PITCH + cl]       = make_float2(cc[0], cc[1]);
                *(float2*)&Sb[(r + 8) * EPI_PITCH + cl] = make_float2(cc[2], cc[3]);
            }
    }
    __syncthreads();

    const bool isq = (n0 < 2048);
    const bool isv = (n0 >= 3072);
    __nv_bfloat16 *dhi, *dlo;
    int colbase, ldd;
    if (isq)              { dhi = g_qhi; dlo = g_qlo; colbase = n0;        ldd = 2048; }
    else if (n0 < 3072)   { dhi = g_khi; dlo = g_klo; colbase = n0 - 2048; ldd = 1024; }
    else                  { dhi = g_vhi; dlo = g_vlo; colbase = n0 - 3072; ldd = 1024; }

    const float QS = isq ? 0.08838834764831845f * 1.4426950408889634f : 1.0f;
    const bool firsthalf = lane < 16;
    const int pbase2 = (lane & 15) * 4;

    float4 w4 = make_float4(1.f, 1.f, 1.f, 1.f);
    if (!isv) {
        const float* nw = isq ? qnw : knw;
        w4 = *(const float4*)&nw[lane * 4];
    }

#pragma unroll 1
    for (int i = 0; i < 16; i++) {
        const int row = wid * 16 + i;
        const int token = m0 + row;
        float4 xv = *(float4*)&Sb[row * EPI_PITCH + lane * 4];
        float r0, r1, r2, r3;
        if (!isv) {
            float ss = xv.x * xv.x + xv.y * xv.y + xv.z * xv.z + xv.w * xv.w;
#pragma unroll
            for (int m = 16; m; m >>= 1) ss += __shfl_xor_sync(0xffffffffu, ss, m);
            const float rinv = rsqrtf(ss * (1.0f / HDIM) + EPSV);
            const float nn0 = xv.x * w4.x * rinv;
            const float nn1 = xv.y * w4.y * rinv;
            const float nn2 = xv.z * w4.z * rinv;
            const float nn3 = xv.w * w4.w * rinv;
            const float pp0 = __shfl_xor_sync(0xffffffffu, nn0, 16);
            const float pp1 = __shfl_xor_sync(0xffffffffu, nn1, 16);
            const float pp2 = __shfl_xor_sync(0xffffffffu, nn2, 16);
            const float pp3 = __shfl_xor_sync(0xffffffffu, nn3, 16);
            const float4 sn = *(const float4*)&g_rsin[(size_t)token * 64 + pbase2];
            const float4 cs = *(const float4*)&g_rcos[(size_t)token * 64 + pbase2];
            if (firsthalf) {
                r0 = (nn0 * cs.x - pp0 * sn.x) * QS;
                r1 = (nn1 * cs.y - pp1 * sn.y) * QS;
                r2 = (nn2 * cs.z - pp2 * sn.z) * QS;
                r3 = (nn3 * cs.w - pp3 * sn.w) * QS;
            } else {
                r0 = (nn0 * cs.x + pp0 * sn.x) * QS;
                r1 = (nn1 * cs.y + pp1 * sn.y) * QS;
                r2 = (nn2 * cs.z + pp2 * sn.z) * QS;
                r3 = (nn3 * cs.w + pp3 * sn.w) * QS;
            }
        } else {
            r0 = xv.x; r1 = xv.y; r2 = xv.z; r3 = xv.w;
        }
        const __nv_bfloat16 h0 = __float2bfloat16(r0);
        const __nv_bfloat16 h1 = __float2bfloat16(r1);
        const __nv_bfloat16 h2 = __float2bfloat16(r2);
        const __nv_bfloat16 h3 = __float2bfloat16(r3);
        uint2 hp, lp;
        hp.x = pack_bf2(r0, r1);
        hp.y = pack_bf2(r2, r3);
        lp.x = pack_bf2(r0 - __bfloat162float(h0), r1 - __bfloat162float(h1));
        lp.y = pack_bf2(r2 - __bfloat162float(h2), r3 - __bfloat162float(h3));
        const size_t off = (size_t)token * ldd + colbase + lane * 4;
        *(uint2*)&dhi[off] = hp;
        *(uint2*)&dlo[off] = lp;
    }
}

// qkv: wave-launched
__global__ void __launch_bounds__(256, 2) gemm_qkv_kernel(
    const float* __restrict__ qnw, const float* __restrict__ knw) {
    gemm_tile<1>(g_xhi, g_xlo, g_wthi, g_wtlo, nullptr, 0,
                 blockIdx.y * 128, blockIdx.x * 128, qnw, knw);
}

// out: persistent
__global__ void __launch_bounds__(256, 2) gemm_out_kernel(float* __restrict__ out) {
    for (int t = blockIdx.x; t < 512; t += gridDim.x) {
        const int m0 = (t / 16) * 128;
        const int n0 = (t % 16) * 128;
        __syncthreads();   // previous tile's smem reads complete
        gemm_tile<0>(g_ohi, g_olo, g_wothi, g_wotlo, out, DD, m0, n0,
                     nullptr, nullptr);
    }
}

// ---------------------------------------------------------------------------
// Flash attention: software-pipelined (QK(it+1) between softmax(it)/PV(it)),
// 3-stage ring, Q in registers. R15: prefetch split into 4 quarters spread
// across the iteration body.
// ---------------------------------------------------------------------------
#define FLP 272
#define FL_KVSZ (64 * FLP)          // 17408
#define FL_STAGE (4 * FL_KVSZ)      // 69632
#define FL_SMEM (3 * FL_STAGE)      // 208896

// quarter p of KV prefetch (p=0:Khi 1:Klo 2:Vhi 3:Vlo), 4 cp16/thread
__device__ __forceinline__ void fl_prefetch_part(
    uint32_t sbase, int b, int kvh, int kv0, int tid, int p)
{
    const __nv_bfloat16* gb;
    if (p == 0)      gb = g_khi;
    else if (p == 1) gb = g_klo;
    else if (p == 2) gb = g_vhi;
    else             gb = g_vlo;
#pragma unroll
    for (int u = 0; u < 4; u++) {
        const int row = (u << 4) + (tid >> 4);       // 0..63
        const int ch = tid & 15;
        const __nv_bfloat16* g = gb +
            (size_t)(b * LL + kv0 + row) * 1024 + kvh * HDIM + ch * 8;
        cp16(sbase + p * FL_KVSZ + row * FLP + ch * 16, g);
    }
}
__device__ __forceinline__ void fl_prefetch_kv_full(
    uint32_t sbase, int b, int kvh, int kv0, int tid)
{
    fl_prefetch_part(sbase, b, kvh, kv0, tid, 0);
    fl_prefetch_part(sbase, b, kvh, kv0, tid, 1);
    fl_prefetch_part(sbase, b, kvh, kv0, tid, 2);
    fl_prefetch_part(sbase, b, kvh, kv0, tid, 3);
}

__device__ __forceinline__ void fl_qk(
    float (&s)[8][4],
    const uint32_t (&qh)[8][4], const uint32_t (&ql)[8][4],
    uint32_t sK, uint32_t bk_off)
{
#pragma unroll
    for (int i = 0; i < 8; i++)
#pragma unroll
        for (int j = 0; j < 4; j++) s[i][j] = 0.f;
#pragma unroll
    for (int kf = 0; kf < 8; kf++) {
        uint32_t bh[4][4], bl[4][4];
#pragma unroll
        for (int p2 = 0; p2 < 4; p2++) {
            ldsm4(bh[p2], sK + bk_off + p2 * 16 * FLP + kf * 32);
            ldsm4(bl[p2], sK + FL_KVSZ + bk_off + p2 * 16 * FLP + kf * 32);
        }
#pragma unroll
        for (int p2 = 0; p2 < 4; p2++) {
            mma_bf16(s[2 * p2],     qh[kf], bh[p2]);
            mma_bf16(s[2 * p2 + 1], qh[kf], bh[p2] + 2);
        }
#pragma unroll
        for (int p2 = 0; p2 < 4; p2++) {
            mma_bf16(s[2 * p2],     qh[kf], bl[p2]);
            mma_bf16(s[2 * p2 + 1], qh[kf], bl[p2] + 2);
        }
#pragma unroll
        for (int p2 = 0; p2 < 4; p2++) {
            mma_bf16(s[2 * p2],     ql[kf], bh[p2]);
            mma_bf16(s[2 * p2 + 1], ql[kf], bh[p2] + 2);
        }
    }
}

__device__ __forceinline__ void fl_pv(
    float (&acc)[16][4], const float (&p)[8][4], uint32_t sVhi, uint32_t v_off)
{
    const uint32_t sVlo = sVhi + FL_KVSZ;
#pragma unroll
    for (int j = 0; j < 4; j++) {
        uint32_t ph[4], pl[4];
#pragma unroll
        for (int q = 0; q < 4; q++) {
            const int nf = 2 * j + (q >> 1);
            const int rb = (q & 1) * 2;
            const float v0 = p[nf][rb], v1 = p[nf][rb + 1];
            const __nv_bfloat16 h0 = __float2bfloat16(v0);
            const __nv_bfloat16 h1 = __float2bfloat16(v1);
            ph[q] = pack_bf2(v0, v1);
            pl[q] = pack_bf2(v0 - __bfloat162float(h0), v1 - __bfloat162float(h1));
        }
#pragma unroll
        for (int t2 = 0; t2 < 4; t2++) {
            uint32_t vh0[4], vl0[4], vh1[4], vl1[4];
            const uint32_t vb = sVhi + v_off + j * 16 * FLP;
            const uint32_t lb = sVlo + v_off + j * 16 * FLP;
            ldsm4t(vh0, vb + (2 * t2) * 32);
            ldsm4t(vl0, lb + (2 * t2) * 32);
            ldsm4t(vh1, vb + (2 * t2 + 1) * 32);
            ldsm4t(vl1, lb + (2 * t2 + 1) * 32);
            float* a0 = acc[4 * t2];
            float* a1 = acc[4 * t2 + 1];
            float* a2 = acc[4 * t2 + 2];
            float* a3 = acc[4 * t2 + 3];
            mma_bf16(a0, ph, vh0); mma_bf16(a1, ph, vh0 + 2);
            mma_bf16(a2, ph, vh1); mma_bf16(a3, ph, vh1 + 2);
            mma_bf16(a0, ph, vl0); mma_bf16(a1, ph, vl0 + 2);
            mma_bf16(a2, ph, vl1); mma_bf16(a3, ph, vl1 + 2);
            mma_bf16(a0, pl, vh0); mma_bf16(a1, pl, vh0 + 2);
            mma_bf16(a2, pl, vh1); mma_bf16(a3, pl, vh1 + 2);
        }
    }
}

__device__ __forceinline__ void fl_softmax(
    float (&sfr)[8][4], float (&acc)[16][4], float (&m2)[2], float (&lsum)[2],
    int it, int m0, int wid, int lane)
{
    const int rbase = m0 + wid * 16 + (lane >> 2);
    if (it * 64 + 63 > m0 + wid * 16) {
#pragma unroll
        for (int nf = 0; nf < 8; nf++) {
            const int cg = it * 64 + nf * 8 + 2 * (lane & 3);
#pragma unroll
            for (int rg = 0; rg < 4; rg++) {
                const int row = rbase + (rg >> 1) * 8;
                const int col = cg + (rg & 1);
                if (col > row) sfr[nf][rg] = -1e30f;
            }
        }
    }
#pragma unroll
    for (int h = 0; h < 2; h++) {
        float tm = -1e30f;
#pragma unroll
        for (int nf = 0; nf < 8; nf++)
            tm = fmaxf(tm, fmaxf(sfr[nf][2 * h], sfr[nf][2 * h + 1]));
        tm = fmaxf(tm, __shfl_xor_sync(0xffffffffu, tm, 1));
        tm = fmaxf(tm, __shfl_xor_sync(0xffffffffu, tm, 2));
        const float mn = fmaxf(m2[h], tm);
        const float corr = exp2f(m2[h] - mn);
        m2[h] = mn;
        float rs = 0.f;
#pragma unroll
        for (int nf = 0; nf < 8; nf++) {
            const float e0 = exp2f(sfr[nf][2 * h] - mn);
            const float e1 = exp2f(sfr[nf][2 * h + 1] - mn);
            sfr[nf][2 * h] = e0;
            sfr[nf][2 * h + 1] = e1;
            rs += e0 + e1;
        }
        rs += __shfl_xor_sync(0xffffffffu, rs, 1);
        rs += __shfl_xor_sync(0xffffffffu, rs, 2);
        lsum[h] = lsum[h] * corr + rs;
#pragma unroll
        for (int nf = 0; nf < 16; nf++) {
            acc[nf][2 * h] *= corr;
            acc[nf][2 * h + 1] *= corr;
        }
    }
}

__global__ void __launch_bounds__(256, 1) flash_kernel()
{
    const int tid = threadIdx.x;
    const int lane = tid & 31;
    const int wid = tid >> 5;
    const int b = blockIdx.z;
    const int n = blockIdx.y;
    const int mt = (int)gridDim.x - 1 - (int)blockIdx.x;  // big tiles launch first
    const int kvh = n >> 1;
    const int m0 = mt * 128;

    const uint32_t sb = smem_u32(dyn_smem);

    // group 0: Q (hi at stage0+0, lo at stage0+34816)
#pragma unroll
    for (int u = 0; u < 16; u++) {
        const int mtx = u >> 3;
        const int row = ((u & 7) << 4) + (tid >> 4);
        const int ch = tid & 15;
        const __nv_bfloat16* g = (mtx ? g_qlo : g_qhi) +
            (size_t)(b * LL + m0 + row) * 2048 + n * HDIM + ch * 8;
        cp16(sb + mtx * 34816 + row * FLP + ch * 16, g);
    }
    CP_COMMIT();
    fl_prefetch_kv_full(sb + 1 * FL_STAGE, b, kvh, 0, tid);   // group 1: KV0
    CP_COMMIT();
    fl_prefetch_kv_full(sb + 2 * FL_STAGE, b, kvh, 64, tid);  // group 2: KV1
    CP_COMMIT();

    const uint32_t a_off = (uint32_t)((wid * 16 + (lane & 15)) * FLP + (lane >> 4) * 16);
    const uint32_t bk_off = (uint32_t)(((lane & 7) + ((lane >> 4) << 3)) * FLP +
                                       ((lane >> 3) & 1) * 16);
    const uint32_t v_off = (uint32_t)(((lane & 7) + ((lane >> 3) & 1) * 8) * FLP +
                                      (lane >> 4) * 16);

    CP_WAIT(1);          // Q + KV0 landed
    __syncthreads();
    uint32_t qh[8][4], ql[8][4];
#pragma unroll
    for (int kf = 0; kf < 8; kf++) {
        ldsm4(qh[kf], sb + a_off + kf * 32);
        ldsm4(ql[kf], sb + 34816 + a_off + kf * 32);
    }

    float acc[16][4];
#pragma unroll
    for (int i = 0; i < 16; i++)
#pragma unroll
        for (int j = 0; j < 4; j++) acc[i][j] = 0.f;
    float m2[2] = {-1e30f, -1e30f};
    float lsum[2] = {0.f, 0.f};

    float sA[8][4], sB[8][4];
    const int nkv = 2 * (mt + 1);    // always even

    // prologue: QK(0) from stage 1
    fl_qk(sA, qh, ql, sb + 1 * FL_STAGE, bk_off);

#define FL_ITER(IT, CUR, NXT)                                                  \
    {                                                                          \
        CP_WAIT(0);          /* KV(IT+1) landed */                             \
        __syncthreads();     /* visibility + stage (IT)%3 free for refill */   \
        const bool pf = ((IT) + 2 < nkv);                                      \
        const uint32_t ns = sb + ((IT) % 3) * FL_STAGE;                        \
        const int nkv0 = ((IT) + 2) * 64;                                      \
        if (pf) {                                                              \
            fl_prefetch_part(ns, b, kvh, nkv0, tid, 0);                        \
            fl_prefetch_part(ns, b, kvh, nkv0, tid, 1);                        \
        }                                                                      \
        fl_softmax(CUR, acc, m2, lsum, (IT), m0, wid, lane);                   \
        if (pf) fl_prefetch_part(ns, b, kvh, nkv0, tid, 2);                    \
        if ((IT) + 1 < nkv)                                                    \
            fl_qk(NXT, qh, ql, sb + (((IT) + 2) % 3) * FL_STAGE, bk_off);      \
        if (pf) {                                                              \
            fl_prefetch_part(ns, b, kvh, nkv0, tid, 3);                        \
            CP_COMMIT();                                                       \
        }                                                                      \
        fl_pv(acc, CUR, sb + (((IT) + 1) % 3) * FL_STAGE + 2 * FL_KVSZ,        \
              v_off);                                                          \
    }

    for (int it = 0; it < nkv; it += 2) {
        FL_ITER(it, sA, sB);
        FL_ITER(it + 1, sB, sA);
    }
#undef FL_ITER

    // --- finalize: /l, split to bf16 hi/lo, store ---
#pragma unroll
    for (int h = 0; h < 2; h++) {
        const float inv = 1.0f / lsum[h];
        const int row = m0 + wid * 16 + (lane >> 2) + h * 8;
        const size_t base = (size_t)(b * LL + row) * 2048 + n * HDIM + 2 * (lane & 3);
#pragma unroll
        for (int nf = 0; nf < 16; nf++) {
            const float v0 = acc[nf][2 * h] * inv;
            const float v1 = acc[nf][2 * h + 1] * inv;
            const __nv_bfloat16 h0 = __float2bfloat16(v0);
            const __nv_bfloat16 h1 = __float2bfloat16(v1);
            *(uint32_t*)&g_ohi[base + nf * 8] = pack_bf2(v0, v1);
            *(uint32_t*)&g_olo[base + nf * 8] =
                pack_bf2(v0 - __bfloat162float(h0), v1 - __bfloat162float(h1));
        }
    }
}

// ---------------------------------------------------------------------------
// Launch
// ---------------------------------------------------------------------------
extern "C" void kernel_launch(void* const* d_in, const int* in_sizes, int n_in,
                              void* d_out, int out_size)
{
    const float* x   = (const float*)d_in[0];
    const int*   pos = (const int*)d_in[1];
    // d_in[2] = attn_mask (causal tril) — implied analytically, unused
    const float* wq  = (const float*)d_in[3];
    const float* wk  = (const float*)d_in[4];
    const float* wv  = (const float*)d_in[5];
    const float* wo  = (const float*)d_in[6];
    const float* qnw = (const float*)d_in[7];
    const float* knw = (const float*)d_in[8];
    float* out = (float*)d_out;

    cudaFuncSetAttribute(gemm_qkv_kernel,
                         cudaFuncAttributeMaxDynamicSharedMemorySize, GEMM_SMEM_BYTES);
    cudaFuncSetAttribute(gemm_out_kernel,
                         cudaFuncAttributeMaxDynamicSharedMemorySize, GEMM_SMEM_BYTES);
    cudaFuncSetAttribute(flash_kernel,
                         cudaFuncAttributeMaxDynamicSharedMemorySize, FL_SMEM);

    int dev = 0, sms = 148;
    cudaGetDevice(&dev);
    cudaDeviceGetAttribute(&sms, cudaDevAttrMultiProcessorCount, dev);

    // 1. weights -> transposed bf16 hi/lo + rope tables + split X
    transpose_convert_all_kernel<<<dim3(64, 64, 4), dim3(32, 8)>>>(wq, wk, wv, wo);
    rope_table_kernel<<<(TOK * 64 + 255) / 256, 256>>>(pos);
    convert_split_x_kernel<<<(TOK * DD / 4 + 255) / 256, 256>>>(x);

    // 2. QKV projection (wave-launched, fused epilogue, spread prefetch)
    gemm_qkv_kernel<<<dim3(QKVW / 128, TOK / 128), 256, GEMM_SMEM_BYTES>>>(qnw, knw);

    // 3. Flash attention (software-pipelined, spread prefetch)
    flash_kernel<<<dim3(LL / 128, NHEADS, BB), 256, FL_SMEM>>>();

    // 4. output projection (persistent, spread prefetch)
    gemm_out_kernel<<<sms * 2, 256, GEMM_SMEM_BYTES>>>(out);
}

// round 16
// speedup vs baseline: 1.1729x; 1.0044x over previous
#include <cuda_runtime.h>
#include <cuda_bf16.h>
#include <math.h>
#include <stdint.h>

// Problem constants
#define BB 2
#define LL 2048
#define DD 2048
#define NHEADS 16
#define KHEADS 8
#define HDIM 128
#define TOK (BB * LL)        // 4096
#define EPSV 1e-6f
#define QKVW 4096            // concatenated qkv col space (q:0..2047, k:..3071, v:..4095)

// ---------------------------------------------------------------------------
// Scratch (device globals — no runtime allocation allowed)
// ---------------------------------------------------------------------------
__device__ __align__(16) __nv_bfloat16 g_xhi[(size_t)TOK * DD];
__device__ __align__(16) __nv_bfloat16 g_xlo[(size_t)TOK * DD];
__device__ __align__(16) __nv_bfloat16 g_qhi[(size_t)TOK * DD];     // normed/rope'd/pre-scaled q
__device__ __align__(16) __nv_bfloat16 g_qlo[(size_t)TOK * DD];
__device__ __align__(16) __nv_bfloat16 g_khi[(size_t)TOK * KHEADS * HDIM];
__device__ __align__(16) __nv_bfloat16 g_klo[(size_t)TOK * KHEADS * HDIM];
__device__ __align__(16) __nv_bfloat16 g_vhi[(size_t)TOK * KHEADS * HDIM];
__device__ __align__(16) __nv_bfloat16 g_vlo[(size_t)TOK * KHEADS * HDIM];
__device__ __align__(16) __nv_bfloat16 g_ohi[(size_t)TOK * DD];     // attention out
__device__ __align__(16) __nv_bfloat16 g_olo[(size_t)TOK * DD];
__device__ __align__(16) __nv_bfloat16 g_wthi[(size_t)QKVW * DD];   // [n][k] qkv weights
__device__ __align__(16) __nv_bfloat16 g_wtlo[(size_t)QKVW * DD];
__device__ __align__(16) __nv_bfloat16 g_wothi[(size_t)DD * DD];    // [n][k] wo
__device__ __align__(16) __nv_bfloat16 g_wotlo[(size_t)DD * DD];
__device__ __align__(16) float g_rsin[(size_t)TOK * 64];            // rope tables
__device__ __align__(16) float g_rcos[(size_t)TOK * 64];

extern __shared__ char dyn_smem[];

// ---------------------------------------------------------------------------
// PTX helpers (family-portable: cp.async / ldmatrix / mma.sync)
// ---------------------------------------------------------------------------
__device__ __forceinline__ uint32_t smem_u32(const void* p) {
    uint32_t a;
    asm("{ .reg .u64 t; cvta.to.shared.u64 t, %1; cvt.u32.u64 %0, t; }"
        : "=r"(a) : "l"(p));
    return a;
}

__device__ __forceinline__ void cp16(uint32_t dst, const void* src) {
    asm volatile("cp.async.cg.shared.global [%0], [%1], 16;" :: "r"(dst), "l"(src));
}
#define CP_COMMIT() asm volatile("cp.async.commit_group;" ::: "memory")
#define CP_WAIT(N)  asm volatile("cp.async.wait_group %0;" :: "n"(N) : "memory")

__device__ __forceinline__ void ldsm4(uint32_t* r, uint32_t a) {
    asm volatile("ldmatrix.sync.aligned.m8n8.x4.shared.b16 {%0,%1,%2,%3}, [%4];"
        : "=r"(r[0]), "=r"(r[1]), "=r"(r[2]), "=r"(r[3]) : "r"(a));
}
__device__ __forceinline__ void ldsm4t(uint32_t* r, uint32_t a) {
    asm volatile("ldmatrix.sync.aligned.m8n8.x4.trans.shared.b16 {%0,%1,%2,%3}, [%4];"
        : "=r"(r[0]), "=r"(r[1]), "=r"(r[2]), "=r"(r[3]) : "r"(a));
}

__device__ __forceinline__ void mma_bf16(float* c, const uint32_t* a, const uint32_t* b) {
    asm volatile(
        "mma.sync.aligned.m16n8k16.row.col.f32.bf16.bf16.f32 "
        "{%0,%1,%2,%3}, {%4,%5,%6,%7}, {%8,%9}, {%0,%1,%2,%3};"
        : "+f"(c[0]), "+f"(c[1]), "+f"(c[2]), "+f"(c[3])
        : "r"(a[0]), "r"(a[1]), "r"(a[2]), "r"(a[3]), "r"(b[0]), "r"(b[1]));
}

__device__ __forceinline__ uint32_t pack_bf2(float x, float y) {
    __nv_bfloat162 t;
    t.x = __float2bfloat16(x);
    t.y = __float2bfloat16(y);
    return *(uint32_t*)&t;
}

// ---------------------------------------------------------------------------
// Conversion / table kernels
// ---------------------------------------------------------------------------
__global__ void __launch_bounds__(256) transpose_convert_all_kernel(
    const float* __restrict__ wq, const float* __restrict__ wk,
    const float* __restrict__ wv, const float* __restrict__ wo)
{
    const int z = blockIdx.z;
    const float* src;
    int C, row_off;
    __nv_bfloat16 *dhi, *dlo;
    if (z == 0)      { src = wq; C = 2048; row_off = 0;    dhi = g_wthi;  dlo = g_wtlo;  }
    else if (z == 1) { if (blockIdx.x >= 32) return;
                       src = wk; C = 1024; row_off = 2048; dhi = g_wthi;  dlo = g_wtlo;  }
    else if (z == 2) { if (blockIdx.x >= 32) return;
                       src = wv; C = 1024; row_off = 3072; dhi = g_wthi;  dlo = g_wtlo;  }
    else             { src = wo; C = 2048; row_off = 0;    dhi = g_wothi; dlo = g_wotlo; }

    __shared__ float t[32][33];
    const int c0 = blockIdx.x * 32;
    const int r0 = blockIdx.y * 32;
    const int tx = threadIdx.x;
    const int ty = threadIdx.y;

#pragma unroll
    for (int j = 0; j < 4; j++)
        t[ty + j * 8][tx] = src[(size_t)(r0 + ty + j * 8) * C + c0 + tx];
    __syncthreads();

#pragma unroll
    for (int j = 0; j < 4; j++) {
        const int i = ty + j * 8;
        const float v = t[tx][i];
        const __nv_bfloat16 h = __float2bfloat16(v);
        const __nv_bfloat16 l = __float2bfloat16(v - __bfloat162float(h));
        const size_t off = (size_t)(row_off + c0 + i) * DD + r0 + tx;
        dhi[off] = h;
        dlo[off] = l;
    }
}

__global__ void __launch_bounds__(256) convert_split_x_kernel(const float* __restrict__ src)
{
    const size_t i = (size_t)blockIdx.x * blockDim.x + threadIdx.x;
    const size_t n4 = (size_t)TOK * DD / 4;
    if (i >= n4) return;
    const float4 v = ((const float4*)src)[i];
    __nv_bfloat16 h0 = __float2bfloat16(v.x);
    __nv_bfloat16 h1 = __float2bfloat16(v.y);
    __nv_bfloat16 h2 = __float2bfloat16(v.z);
    __nv_bfloat16 h3 = __float2bfloat16(v.w);
    uint2 hp, lp;
    hp.x = pack_bf2(v.x, v.y);
    hp.y = pack_bf2(v.z, v.w);
    lp.x = pack_bf2(v.x - __bfloat162float(h0), v.y - __bfloat162float(h1));
    lp.y = pack_bf2(v.z - __bfloat162float(h2), v.w - __bfloat162float(h3));
    ((uint2*)g_xhi)[i] = hp;
    ((uint2*)g_xlo)[i] = lp;
}

// RoPE tables: sin/cos per (token, freq-pair). One-time, full-precision.
__global__ void __launch_bounds__(256) rope_table_kernel(const int* __restrict__ pos_ids)
{
    const int idx = blockIdx.x * 256 + threadIdx.x;
    if (idx >= TOK * 64) return;
    const int token = idx >> 6;
    const int p = idx & 63;
    const double L2T = 19.931568569324174;   // log2(1e6)
    const float inv_ts = exp2f((float)(-(double)p * L2T / 64.0));
    const float ang = (float)pos_ids[token] * inv_ts;
    float sv, cv;
    sincosf(ang, &sv, &cv);
    g_rsin[idx] = sv;
    g_rcos[idx] = cv;
}

// ---------------------------------------------------------------------------
// split-bf16 warp-MMA GEMM (R15 exact): C = A * B^T, 128x128 tile, BK=32,
// 8 warps (2m x 4n), XOR swizzle, 3-stage ring, SPREAD prefetch.
// ---------------------------------------------------------------------------
#define BK 32
#define PITCH 64
#define MAT_BYTES (128 * PITCH)           // 8192 per split
#define STAGE_BYTES (4 * MAT_BYTES)       // 32768
#define GEMM_SMEM_BYTES (3 * STAGE_BYTES) // 98304 (x2 CTAs = 196KB)
#define EPI_PITCH 132                     // fp32 words per row in epilogue buffer

__device__ __forceinline__ uint32_t gswz(int r, int c) {
    return (uint32_t)(r * PITCH + ((c ^ ((r >> 1) & 3)) << 4));
}

__device__ __forceinline__ void prefetch_A(
    uint32_t sbase, const __nv_bfloat16* __restrict__ Ahi,
    const __nv_bfloat16* __restrict__ Alo, int m0, int k0, int j, int tid)
{
    const int id = tid * 2 + j;
    const int r = id >> 2;
    const int c = id & 3;
    const uint32_t soff = gswz(r, c);
    const size_t ga = (size_t)(m0 + r) * DD + k0 + c * 8;
    cp16(sbase + soff,             Ahi + ga);
    cp16(sbase + MAT_BYTES + soff, Alo + ga);
}
__device__ __forceinline__ void prefetch_B(
    uint32_t sbase, const __nv_bfloat16* __restrict__ Bhi,
    const __nv_bfloat16* __restrict__ Blo, int n0, int k0, int j, int tid)
{
    const int id = tid * 2 + j;
    const int r = id >> 2;
    const int c = id & 3;
    const uint32_t soff = gswz(r, c);
    const size_t gb = (size_t)(n0 + r) * DD + k0 + c * 8;
    cp16(sbase + 2 * MAT_BYTES + soff, Bhi + gb);
    cp16(sbase + 3 * MAT_BYTES + soff, Blo + gb);
}

__device__ __forceinline__ void prefetch_stage_full(
    uint32_t sbase,
    const __nv_bfloat16* __restrict__ Ahi, const __nv_bfloat16* __restrict__ Alo,
    const __nv_bfloat16* __restrict__ Bhi, const __nv_bfloat16* __restrict__ Blo,
    int m0, int n0, int k0, int tid)
{
    prefetch_A(sbase, Ahi, Alo, m0, k0, 0, tid);
    prefetch_B(sbase, Bhi, Blo, n0, k0, 0, tid);
    prefetch_A(sbase, Ahi, Alo, m0, k0, 1, tid);
    prefetch_B(sbase, Bhi, Blo, n0, k0, 1, tid);
}

template <int FUSED>
__device__ __forceinline__ void gemm_tile(
    const __nv_bfloat16* __restrict__ Ahi, const __nv_bfloat16* __restrict__ Alo,
    const __nv_bfloat16* __restrict__ Bhi, const __nv_bfloat16* __restrict__ Blo,
    float* __restrict__ Cc, int ldC, int m0, int n0,
    const float* __restrict__ qnw, const float* __restrict__ knw)
{
    const int tid  = threadIdx.x;             // 256 threads
    const int lane = tid & 31;
    const int wid  = tid >> 5;                // 0..7
    const int wm   = wid & 1;
    const int wn   = wid >> 1;
    const uint32_t smem_base = smem_u32(dyn_smem);

    float c[4][4][4];
#pragma unroll
    for (int i = 0; i < 4; i++)
#pragma unroll
        for (int j = 0; j < 4; j++)
#pragma unroll
            for (int k = 0; k < 4; k++) c[i][j][k] = 0.f;

    const int a_row  = wm * 64 + (lane & 15);
    const int a_swz  = (a_row >> 1) & 3;
    const uint32_t a_base = (uint32_t)(a_row * PITCH);
    const int a_c0   = lane >> 4;
    const int b_row  = wn * 32 + (lane & 7) + ((lane >> 4) << 3);
    const int b_swz  = (b_row >> 1) & 3;
    const uint32_t b_base = (uint32_t)(b_row * PITCH);
    const int b_c0   = (lane >> 3) & 1;

    const int nk = DD / BK;

    prefetch_stage_full(smem_base, Ahi, Alo, Bhi, Blo, m0, n0, 0, tid);
    CP_COMMIT();
    prefetch_stage_full(smem_base + STAGE_BYTES, Ahi, Alo, Bhi, Blo, m0, n0, BK, tid);
    CP_COMMIT();

    int slot = 0;
    for (int it = 0; it < nk; it++) {
        if (it < nk - 1) { CP_WAIT(1); } else { CP_WAIT(0); }
        __syncthreads();

        const bool pf = (it + 2 < nk);
        int ps = slot + 2;
        if (ps >= 3) ps -= 3;
        const uint32_t pbase = smem_base + ps * STAGE_BYTES;
        const int pk = (it + 2) * BK;

        const uint32_t sA = smem_base + slot * STAGE_BYTES;
        const uint32_t sB = sA + 2 * MAT_BYTES;

#pragma unroll
        for (int kf = 0; kf < 2; kf++) {
            uint32_t b[2][2][4];
            const uint32_t a_coff = (uint32_t)(((a_c0 + kf * 2) ^ a_swz) << 4);
            const uint32_t b_coff = (uint32_t)(((b_c0 + kf * 2) ^ b_swz) << 4);
#pragma unroll
            for (int nf2 = 0; nf2 < 2; nf2++) {
                const uint32_t bd = sB + b_base + nf2 * (16 * PITCH) + b_coff;
                ldsm4(b[0][nf2], bd);
                ldsm4(b[1][nf2], bd + MAT_BYTES);
            }
            if (pf) prefetch_A(pbase, Ahi, Alo, m0, pk, kf, tid);
#pragma unroll
            for (int mf = 0; mf < 4; mf++) {
                uint32_t ah[4], al[4];
                const uint32_t ad = sA + a_base + mf * (16 * PITCH) + a_coff;
                ldsm4(ah, ad);
                ldsm4(al, ad + MAT_BYTES);
                if (pf && mf == 2) prefetch_B(pbase, Bhi, Blo, n0, pk, kf, tid);
#pragma unroll
                for (int nf = 0; nf < 4; nf++)
                    mma_bf16(c[mf][nf], ah, &b[0][nf >> 1][(nf & 1) * 2]);
#pragma unroll
                for (int nf = 0; nf < 4; nf++)
                    mma_bf16(c[mf][nf], ah, &b[1][nf >> 1][(nf & 1) * 2]);
#pragma unroll
                for (int nf = 0; nf < 4; nf++)
                    mma_bf16(c[mf][nf], al, &b[0][nf >> 1][(nf & 1) * 2]);
            }
        }
        if (pf) CP_COMMIT();

        if (++slot == 3) slot = 0;
    }

    const int gr = lane >> 2;
    const int gc = (lane & 3) * 2;

    if (FUSED == 0) {
        const int row0 = m0 + wm * 64;
        const int col0 = n0 + wn * 32;
#pragma unroll
        for (int mf = 0; mf < 4; mf++)
#pragma unroll
            for (int nf = 0; nf < 4; nf++) {
                float* cc = c[mf][nf];
                const int r = row0 + mf * 16 + gr;
                const int cl = col0 + nf * 8 + gc;
                *(float2*)&Cc[(size_t)r * ldC + cl]       = make_float2(cc[0], cc[1]);
                *(float2*)&Cc[(size_t)(r + 8) * ldC + cl] = make_float2(cc[2], cc[3]);
            }
        return;
    }

    // --- FUSED epilogue: SMEM bounce + RMSNorm + RoPE + hi/lo split ---
    float* Sb = (float*)dyn_smem;
    __syncthreads();
    {
        const int row0 = wm * 64;
        const int col0 = wn * 32;
#pragma unroll
        for (int mf = 0; mf < 4; mf++)
#pragma unroll
            for (int nf = 0; nf < 4; nf++) {
                float* cc = c[mf][nf];
                const int r = row0 + mf * 16 + gr;
                const int cl = col0 + nf * 8 + gc;
                *(float2*)&Sb[r * EPI_PITCH + cl]       = make_float2(cc[0], cc[1]);
                *(float2*)&Sb[(r + 8) * EPI_PITCH + cl] = make_float2(cc[2], cc[3]);
            }
    }
    __syncthreads();

    const bool isq = (n0 < 2048);
    const bool isv = (n0 >= 3072);
    __nv_bfloat16 *dhi, *dlo;
    int colbase, ldd;
    if (isq)              { dhi = g_qhi; dlo = g_qlo; colbase = n0;        ldd = 2048; }
    else if (n0 < 3072)   { dhi = g_khi; dlo = g_klo; colbase = n0 - 2048; ldd = 1024; }
    else                  { dhi = g_vhi; dlo = g_vlo; colbase = n0 - 3072; ldd = 1024; }

    const float QS = isq ? 0.08838834764831845f * 1.4426950408889634f : 1.0f;
    const bool firsthalf = lane < 16;
    const int pbase2 = (lane & 15) * 4;

    float4 w4 = make_float4(1.f, 1.f, 1.f, 1.f);
    if (!isv) {
        const float* nw = isq ? qnw : knw;
        w4 = *(const float4*)&nw[lane * 4];
    }

#pragma unroll 1
    for (int i = 0; i < 16; i++) {
        const int row = wid * 16 + i;
        const int token = m0 + row;
        float4 xv = *(float4*)&Sb[row * EPI_PITCH + lane * 4];
        float r0, r1, r2, r3;
        if (!isv) {
            float ss = xv.x * xv.x + xv.y * xv.y + xv.z * xv.z + xv.w * xv.w;
#pragma unroll
            for (int m = 16; m; m >>= 1) ss += __shfl_xor_sync(0xffffffffu, ss, m);
            const float rinv = rsqrtf(ss * (1.0f / HDIM) + EPSV);
            const float nn0 = xv.x * w4.x * rinv;
            const float nn1 = xv.y * w4.y * rinv;
            const float nn2 = xv.z * w4.z * rinv;
            const float nn3 = xv.w * w4.w * rinv;
            const float pp0 = __shfl_xor_sync(0xffffffffu, nn0, 16);
            const float pp1 = __shfl_xor_sync(0xffffffffu, nn1, 16);
            const float pp2 = __shfl_xor_sync(0xffffffffu, nn2, 16);
            const float pp3 = __shfl_xor_sync(0xffffffffu, nn3, 16);
            const float4 sn = *(const float4*)&g_rsin[(size_t)token * 64 + pbase2];
            const float4 cs = *(const float4*)&g_rcos[(size_t)token * 64 + pbase2];
            if (firsthalf) {
                r0 = (nn0 * cs.x - pp0 * sn.x) * QS;
                r1 = (nn1 * cs.y - pp1 * sn.y) * QS;
                r2 = (nn2 * cs.z - pp2 * sn.z) * QS;
                r3 = (nn3 * cs.w - pp3 * sn.w) * QS;
            } else {
                r0 = (nn0 * cs.x + pp0 * sn.x) * QS;
                r1 = (nn1 * cs.y + pp1 * sn.y) * QS;
                r2 = (nn2 * cs.z + pp2 * sn.z) * QS;
                r3 = (nn3 * cs.w + pp3 * sn.w) * QS;
            }
        } else {
            r0 = xv.x; r1 = xv.y; r2 = xv.z; r3 = xv.w;
        }
        const __nv_bfloat16 h0 = __float2bfloat16(r0);
        const __nv_bfloat16 h1 = __float2bfloat16(r1);
        const __nv_bfloat16 h2 = __float2bfloat16(r2);
        const __nv_bfloat16 h3 = __float2bfloat16(r3);
        uint2 hp, lp;
        hp.x = pack_bf2(r0, r1);
        hp.y = pack_bf2(r2, r3);
        lp.x = pack_bf2(r0 - __bfloat162float(h0), r1 - __bfloat162float(h1));
        lp.y = pack_bf2(r2 - __bfloat162float(h2), r3 - __bfloat162float(h3));
        const size_t off = (size_t)token * ldd + colbase + lane * 4;
        *(uint2*)&dhi[off] = hp;
        *(uint2*)&dlo[off] = lp;
    }
}

// qkv: wave-launched
__global__ void __launch_bounds__(256, 2) gemm_qkv_kernel(
    const float* __restrict__ qnw, const float* __restrict__ knw) {
    gemm_tile<1>(g_xhi, g_xlo, g_wthi, g_wtlo, nullptr, 0,
                 blockIdx.y * 128, blockIdx.x * 128, qnw, knw);
}

// out: persistent
__global__ void __launch_bounds__(256, 2) gemm_out_kernel(float* __restrict__ out) {
    for (int t = blockIdx.x; t < 512; t += gridDim.x) {
        const int m0 = (t / 16) * 128;
        const int n0 = (t % 16) * 128;
        __syncthreads();   // previous tile's smem reads complete
        gemm_tile<0>(g_ohi, g_olo, g_wothi, g_wotlo, out, DD, m0, n0,
                     nullptr, nullptr);
    }
}

// ---------------------------------------------------------------------------
// Flash attention. R16: distance-2 waits — K(it+2) committed EARLY in iter,
// V(it+2) LATE; CP_WAIT(1) at iter top (leaves only V(it+2) in flight).
// QK-ahead kept (double score buffer). lsum lane-reduction deferred to end.
// ---------------------------------------------------------------------------
#define FLP 272
#define FL_KVSZ (64 * FLP)          // 17408
#define FL_STAGE (4 * FL_KVSZ)      // 69632
#define FL_SMEM (3 * FL_STAGE)      // 208896

// quarter p of KV prefetch (p=0:Khi 1:Klo 2:Vhi 3:Vlo), 4 cp16/thread
__device__ __forceinline__ void fl_prefetch_part(
    uint32_t sbase, int b, int kvh, int kv0, int tid, int p)
{
    const __nv_bfloat16* gb;
    if (p == 0)      gb = g_khi;
    else if (p == 1) gb = g_klo;
    else if (p == 2) gb = g_vhi;
    else             gb = g_vlo;
#pragma unroll
    for (int u = 0; u < 4; u++) {
        const int row = (u << 4) + (tid >> 4);       // 0..63
        const int ch = tid & 15;
        const __nv_bfloat16* g = gb +
            (size_t)(b * LL + kv0 + row) * 1024 + kvh * HDIM + ch * 8;
        cp16(sbase + p * FL_KVSZ + row * FLP + ch * 16, g);
    }
}

__device__ __forceinline__ void fl_qk(
    float (&s)[8][4],
    const uint32_t (&qh)[8][4], const uint32_t (&ql)[8][4],
    uint32_t sK, uint32_t bk_off)
{
#pragma unroll
    for (int i = 0; i < 8; i++)
#pragma unroll
        for (int j = 0; j < 4; j++) s[i][j] = 0.f;
#pragma unroll
    for (int kf = 0; kf < 8; kf++) {
        uint32_t bh[4][4], bl[4][4];
#pragma unroll
        for (int p2 = 0; p2 < 4; p2++) {
            ldsm4(bh[p2], sK + bk_off + p2 * 16 * FLP + kf * 32);
            ldsm4(bl[p2], sK + FL_KVSZ + bk_off + p2 * 16 * FLP + kf * 32);
        }
#pragma unroll
        for (int p2 = 0; p2 < 4; p2++) {
            mma_bf16(s[2 * p2],     qh[kf], bh[p2]);
            mma_bf16(s[2 * p2 + 1], qh[kf], bh[p2] + 2);
        }
#pragma unroll
        for (int p2 = 0; p2 < 4; p2++) {
            mma_bf16(s[2 * p2],     qh[kf], bl[p2]);
            mma_bf16(s[2 * p2 + 1], qh[kf], bl[p2] + 2);
        }
#pragma unroll
        for (int p2 = 0; p2 < 4; p2++) {
            mma_bf16(s[2 * p2],     ql[kf], bh[p2]);
            mma_bf16(s[2 * p2 + 1], ql[kf], bh[p2] + 2);
        }
    }
}

__device__ __forceinline__ void fl_pv(
    float (&acc)[16][4], const float (&p)[8][4], uint32_t sVhi, uint32_t v_off)
{
    const uint32_t sVlo = sVhi + FL_KVSZ;
#pragma unroll
    for (int j = 0; j < 4; j++) {
        uint32_t ph[4], pl[4];
#pragma unroll
        for (int q = 0; q < 4; q++) {
            const int nf = 2 * j + (q >> 1);
            const int rb = (q & 1) * 2;
            const float v0 = p[nf][rb], v1 = p[nf][rb + 1];
            const __nv_bfloat16 h0 = __float2bfloat16(v0);
            const __nv_bfloat16 h1 = __float2bfloat16(v1);
            ph[q] = pack_bf2(v0, v1);
            pl[q] = pack_bf2(v0 - __bfloat162float(h0), v1 - __bfloat162float(h1));
        }
#pragma unroll
        for (int t2 = 0; t2 < 4; t2++) {
            uint32_t vh0[4], vl0[4], vh1[4], vl1[4];
            const uint32_t vb = sVhi + v_off + j * 16 * FLP;
            const uint32_t lb = sVlo + v_off + j * 16 * FLP;
            ldsm4t(vh0, vb + (2 * t2) * 32);
            ldsm4t(vl0, lb + (2 * t2) * 32);
            ldsm4t(vh1, vb + (2 * t2 + 1) * 32);
            ldsm4t(vl1, lb + (2 * t2 + 1) * 32);
            float* a0 = acc[4 * t2];
            float* a1 = acc[4 * t2 + 1];
            float* a2 = acc[4 * t2 + 2];
            float* a3 = acc[4 * t2 + 3];
            mma_bf16(a0, ph, vh0); mma_bf16(a1, ph, vh0 + 2);
            mma_bf16(a2, ph, vh1); mma_bf16(a3, ph, vh1 + 2);
            mma_bf16(a0, ph, vl0); mma_bf16(a1, ph, vl0 + 2);
            mma_bf16(a2, ph, vl1); mma_bf16(a3, ph, vl1 + 2);
            mma_bf16(a0, pl, vh0); mma_bf16(a1, pl, vh0 + 2);
            mma_bf16(a2, pl, vh1); mma_bf16(a3, pl, vh1 + 2);
        }
    }
}

// mask + online softmax; lsum kept as per-lane partial (reduced at finalize)
__device__ __forceinline__ void fl_softmax(
    float (&sfr)[8][4], float (&acc)[16][4], float (&m2)[2], float (&lsum)[2],
    int it, int m0, int wid, int lane)
{
    const int rbase = m0 + wid * 16 + (lane >> 2);
    if (it * 64 + 63 > m0 + wid * 16) {
#pragma unroll
        for (int nf = 0; nf < 8; nf++) {
            const int cg = it * 64 + nf * 8 + 2 * (lane & 3);
#pragma unroll
            for (int rg = 0; rg < 4; rg++) {
                const int row = rbase + (rg >> 1) * 8;
                const int col = cg + (rg & 1);
                if (col > row) sfr[nf][rg] = -1e30f;
            }
        }
    }
#pragma unroll
    for (int h = 0; h < 2; h++) {
        float tm = -1e30f;
#pragma unroll
        for (int nf = 0; nf < 8; nf++)
            tm = fmaxf(tm, fmaxf(sfr[nf][2 * h], sfr[nf][2 * h + 1]));
        tm = fmaxf(tm, __shfl_xor_sync(0xffffffffu, tm, 1));
        tm = fmaxf(tm, __shfl_xor_sync(0xffffffffu, tm, 2));
        const float mn = fmaxf(m2[h], tm);
        const float corr = exp2f(m2[h] - mn);
        m2[h] = mn;
        float rs = 0.f;
#pragma unroll
        for (int nf = 0; nf < 8; nf++) {
            const float e0 = exp2f(sfr[nf][2 * h] - mn);
            const float e1 = exp2f(sfr[nf][2 * h + 1] - mn);
            sfr[nf][2 * h] = e0;
            sfr[nf][2 * h + 1] = e1;
            rs += e0 + e1;
        }
        // per-lane partial sum only; cross-lane reduction deferred to finalize
        lsum[h] = lsum[h] * corr + rs;
#pragma unroll
        for (int nf = 0; nf < 16; nf++) {
            acc[nf][2 * h] *= corr;
            acc[nf][2 * h + 1] *= corr;
        }
    }
}

__global__ void __launch_bounds__(256, 1) flash_kernel()
{
    const int tid = threadIdx.x;
    const int lane = tid & 31;
    const int wid = tid >> 5;
    const int b = blockIdx.z;
    const int n = blockIdx.y;
    const int mt = (int)gridDim.x - 1 - (int)blockIdx.x;  // big tiles launch first
    const int kvh = n >> 1;
    const int m0 = mt * 128;

    const uint32_t sb = smem_u32(dyn_smem);

    // group 0: Q (hi at stage0+0, lo at stage0+34816)
#pragma unroll
    for (int u = 0; u < 16; u++) {
        const int mtx = u >> 3;
        const int row = ((u & 7) << 4) + (tid >> 4);
        const int ch = tid & 15;
        const __nv_bfloat16* g = (mtx ? g_qlo : g_qhi) +
            (size_t)(b * LL + m0 + row) * 2048 + n * HDIM + ch * 8;
        cp16(sb + mtx * 34816 + row * FLP + ch * 16, g);
    }
    CP_COMMIT();
    // group 1: KV0 (stage 1)
    fl_prefetch_part(sb + 1 * FL_STAGE, b, kvh, 0, tid, 0);
    fl_prefetch_part(sb + 1 * FL_STAGE, b, kvh, 0, tid, 1);
    fl_prefetch_part(sb + 1 * FL_STAGE, b, kvh, 0, tid, 2);
    fl_prefetch_part(sb + 1 * FL_STAGE, b, kvh, 0, tid, 3);
    CP_COMMIT();
    // group 2: K1 (stage 2)
    fl_prefetch_part(sb + 2 * FL_STAGE, b, kvh, 64, tid, 0);
    fl_prefetch_part(sb + 2 * FL_STAGE, b, kvh, 64, tid, 1);
    CP_COMMIT();
    // group 3: V1 (stage 2)
    fl_prefetch_part(sb + 2 * FL_STAGE, b, kvh, 64, tid, 2);
    fl_prefetch_part(sb + 2 * FL_STAGE, b, kvh, 64, tid, 3);
    CP_COMMIT();

    const uint32_t a_off = (uint32_t)((wid * 16 + (lane & 15)) * FLP + (lane >> 4) * 16);
    const uint32_t bk_off = (uint32_t)(((lane & 7) + ((lane >> 4) << 3)) * FLP +
                                       ((lane >> 3) & 1) * 16);
    const uint32_t v_off = (uint32_t)(((lane & 7) + ((lane >> 3) & 1) * 8) * FLP +
                                      (lane >> 4) * 16);

    CP_WAIT(2);          // Q + KV0 landed (K1, V1 may be in flight)
    __syncthreads();
    uint32_t qh[8][4], ql[8][4];
#pragma unroll
    for (int kf = 0; kf < 8; kf++) {
        ldsm4(qh[kf], sb + a_off + kf * 32);
        ldsm4(ql[kf], sb + 34816 + a_off + kf * 32);
    }

    float acc[16][4];
#pragma unroll
    for (int i = 0; i < 16; i++)
#pragma unroll
        for (int j = 0; j < 4; j++) acc[i][j] = 0.f;
    float m2[2] = {-1e30f, -1e30f};
    float lsum[2] = {0.f, 0.f};

    float sA[8][4], sB[8][4];
    const int nkv = 2 * (mt + 1);    // always even

    // prologue: QK(0) from stage 1 (KV0 landed)
    fl_qk(sA, qh, ql, sb + 1 * FL_STAGE, bk_off);

    // Loop invariant at iter top: groups outstanding = {V(it+1)} at most after
    // CP_WAIT(1): K(it+1) (committed early in iter it-1) and V(it) (committed
    // late in iter it-2) are landed. Iter it commits K(it+2) early (before
    // softmax) and V(it+2) late (after QK) — giving K ~1 iter and V ~2 iters
    // of transfer lead.
#define FL_ITER(IT, CUR, NXT)                                                  \
    {                                                                          \
        if ((IT) + 1 < nkv) { CP_WAIT(1); } else { CP_WAIT(0); }               \
        __syncthreads();     /* visibility + stage (IT)%3 free for refill */   \
        const bool pf = ((IT) + 2 < nkv);                                      \
        const uint32_t ns = sb + ((IT) % 3) * FL_STAGE;                        \
        const int nkv0 = ((IT) + 2) * 64;                                      \
        if (pf) {                                                              \
            fl_prefetch_part(ns, b, kvh, nkv0, tid, 0);                        \
            fl_prefetch_part(ns, b, kvh, nkv0, tid, 1);                        \
            CP_COMMIT();     /* K(IT+2) group — EARLY */                       \
        }                                                                      \
        fl_softmax(CUR, acc, m2, lsum, (IT), m0, wid, lane);                   \
        if (pf) fl_prefetch_part(ns, b, kvh, nkv0, tid, 2);                    \
        if ((IT) + 1 < nkv)                                                    \
            fl_qk(NXT, qh, ql, sb + (((IT) + 2) % 3) * FL_STAGE, bk_off);      \
        if (pf) {                                                              \
            fl_prefetch_part(ns, b, kvh, nkv0, tid, 3);                        \
            CP_COMMIT();     /* V(IT+2) group — LATE */                        \
        }                                                                      \
        fl_pv(acc, CUR, sb + (((IT) + 1) % 3) * FL_STAGE + 2 * FL_KVSZ,        \
              v_off);                                                          \
    }

    for (int it = 0; it < nkv; it += 2) {
        FL_ITER(it, sA, sB);
        FL_ITER(it + 1, sB, sA);
    }
#undef FL_ITER

    // --- finalize: reduce lsum across the 4 lanes of each row, /l, split ---
#pragma unroll
    for (int h = 0; h < 2; h++) {
        float ls = lsum[h];
        ls += __shfl_xor_sync(0xffffffffu, ls, 1);
        ls += __shfl_xor_sync(0xffffffffu, ls, 2);
        const float inv = 1.0f / ls;
        const int row = m0 + wid * 16 + (lane >> 2) + h * 8;
        const size_t base = (size_t)(b * LL + row) * 2048 + n * HDIM + 2 * (lane & 3);
#pragma unroll
        for (int nf = 0; nf < 16; nf++) {
            const float v0 = acc[nf][2 * h] * inv;
            const float v1 = acc[nf][2 * h + 1] * inv;
            const __nv_bfloat16 h0 = __float2bfloat16(v0);
            const __nv_bfloat16 h1 = __float2bfloat16(v1);
            *(uint32_t*)&g_ohi[base + nf * 8] = pack_bf2(v0, v1);
            *(uint32_t*)&g_olo[base + nf * 8] =
                pack_bf2(v0 - __bfloat162float(h0), v1 - __bfloat162float(h1));
        }
    }
}

// ---------------------------------------------------------------------------
// Launch
// ---------------------------------------------------------------------------
extern "C" void kernel_launch(void* const* d_in, const int* in_sizes, int n_in,
                              void* d_out, int out_size)
{
    const float* x   = (const float*)d_in[0];
    const int*   pos = (const int*)d_in[1];
    // d_in[2] = attn_mask (causal tril) — implied analytically, unused
    const float* wq  = (const float*)d_in[3];
    const float* wk  = (const float*)d_in[4];
    const float* wv  = (const float*)d_in[5];
    const float* wo  = (const float*)d_in[6];
    const float* qnw = (const float*)d_in[7];
    const float* knw = (const float*)d_in[8];
    float* out = (float*)d_out;

    cudaFuncSetAttribute(gemm_qkv_kernel,
                         cudaFuncAttributeMaxDynamicSharedMemorySize, GEMM_SMEM_BYTES);
    cudaFuncSetAttribute(gemm_out_kernel,
                         cudaFuncAttributeMaxDynamicSharedMemorySize, GEMM_SMEM_BYTES);
    cudaFuncSetAttribute(flash_kernel,
                         cudaFuncAttributeMaxDynamicSharedMemorySize, FL_SMEM);

    int dev = 0, sms = 148;
    cudaGetDevice(&dev);
    cudaDeviceGetAttribute(&sms, cudaDevAttrMultiProcessorCount, dev);

    // 1. weights -> transposed bf16 hi/lo + rope tables + split X
    transpose_convert_all_kernel<<<dim3(64, 64, 4), dim3(32, 8)>>>(wq, wk, wv, wo);
    rope_table_kernel<<<(TOK * 64 + 255) / 256, 256>>>(pos);
    convert_split_x_kernel<<<(TOK * DD / 4 + 255) / 256, 256>>>(x);

    // 2. QKV projection (wave-launched, fused epilogue, spread prefetch)
    gemm_qkv_kernel<<<dim3(QKVW / 128, TOK / 128), 256, GEMM_SMEM_BYTES>>>(qnw, knw);

    // 3. Flash attention (distance-2 waits, split K/V commits)
    flash_kernel<<<dim3(LL / 128, NHEADS, BB), 256, FL_SMEM>>>();

    // 4. output projection (persistent, spread prefetch)
    gemm_out_kernel<<<sms * 2, 256, GEMM_SMEM_BYTES>>>(out);
}

// round 17
// speedup vs baseline: 1.2863x; 1.0967x over previous
#include <cuda_runtime.h>
#include <cuda_bf16.h>
#include <cuda_fp16.h>
#include <math.h>
#include <stdint.h>

// Problem constants
#define BB 2
#define LL 2048
#define DD 2048
#define NHEADS 16
#define KHEADS 8
#define HDIM 128
#define TOK (BB * LL)        // 4096
#define EPSV 1e-6f
#define QKVW 4096            // concatenated qkv col space (q:0..2047, k:..3071, v:..4095)

// ---------------------------------------------------------------------------
// Scratch (device globals — no runtime allocation allowed)
// ---------------------------------------------------------------------------
__device__ __align__(16) __nv_bfloat16 g_xhi[(size_t)TOK * DD];
__device__ __align__(16) __nv_bfloat16 g_xlo[(size_t)TOK * DD];
__device__ __align__(16) __half        g_q16[(size_t)TOK * DD];     // fp16 q (normed/roped/scaled)
__device__ __align__(16) __half        g_k16[(size_t)TOK * KHEADS * HDIM];  // fp16 k
__device__ __align__(16) __nv_bfloat16 g_vhi[(size_t)TOK * KHEADS * HDIM];
__device__ __align__(16) __nv_bfloat16 g_vlo[(size_t)TOK * KHEADS * HDIM];
__device__ __align__(16) __nv_bfloat16 g_ohi[(size_t)TOK * DD];     // attention out
__device__ __align__(16) __nv_bfloat16 g_olo[(size_t)TOK * DD];
__device__ __align__(16) __nv_bfloat16 g_wthi[(size_t)QKVW * DD];   // [n][k] qkv weights
__device__ __align__(16) __nv_bfloat16 g_wtlo[(size_t)QKVW * DD];
__device__ __align__(16) __nv_bfloat16 g_wothi[(size_t)DD * DD];    // [n][k] wo
__device__ __align__(16) __nv_bfloat16 g_wotlo[(size_t)DD * DD];
__device__ __align__(16) float g_rsin[(size_t)TOK * 64];            // rope tables
__device__ __align__(16) float g_rcos[(size_t)TOK * 64];

extern __shared__ char dyn_smem[];

// ---------------------------------------------------------------------------
// PTX helpers (family-portable: cp.async / ldmatrix / mma.sync)
// ---------------------------------------------------------------------------
__device__ __forceinline__ uint32_t smem_u32(const void* p) {
    uint32_t a;
    asm("{ .reg .u64 t; cvta.to.shared.u64 t, %1; cvt.u32.u64 %0, t; }"
        : "=r"(a) : "l"(p));
    return a;
}

__device__ __forceinline__ void cp16(uint32_t dst, const void* src) {
    asm volatile("cp.async.cg.shared.global [%0], [%1], 16;" :: "r"(dst), "l"(src));
}
#define CP_COMMIT() asm volatile("cp.async.commit_group;" ::: "memory")
#define CP_WAIT(N)  asm volatile("cp.async.wait_group %0;" :: "n"(N) : "memory")

__device__ __forceinline__ void ldsm4(uint32_t* r, uint32_t a) {
    asm volatile("ldmatrix.sync.aligned.m8n8.x4.shared.b16 {%0,%1,%2,%3}, [%4];"
        : "=r"(r[0]), "=r"(r[1]), "=r"(r[2]), "=r"(r[3]) : "r"(a));
}
__device__ __forceinline__ void ldsm4t(uint32_t* r, uint32_t a) {
    asm volatile("ldmatrix.sync.aligned.m8n8.x4.trans.shared.b16 {%0,%1,%2,%3}, [%4];"
        : "=r"(r[0]), "=r"(r[1]), "=r"(r[2]), "=r"(r[3]) : "r"(a));
}

__device__ __forceinline__ void mma_bf16(float* c, const uint32_t* a, const uint32_t* b) {
    asm volatile(
        "mma.sync.aligned.m16n8k16.row.col.f32.bf16.bf16.f32 "
        "{%0,%1,%2,%3}, {%4,%5,%6,%7}, {%8,%9}, {%0,%1,%2,%3};"
        : "+f"(c[0]), "+f"(c[1]), "+f"(c[2]), "+f"(c[3])
        : "r"(a[0]), "r"(a[1]), "r"(a[2]), "r"(a[3]), "r"(b[0]), "r"(b[1]));
}
__device__ __forceinline__ void mma_f16(float* c, const uint32_t* a, const uint32_t* b) {
    asm volatile(
        "mma.sync.aligned.m16n8k16.row.col.f32.f16.f16.f32 "
        "{%0,%1,%2,%3}, {%4,%5,%6,%7}, {%8,%9}, {%0,%1,%2,%3};"
        : "+f"(c[0]), "+f"(c[1]), "+f"(c[2]), "+f"(c[3])
        : "r"(a[0]), "r"(a[1]), "r"(a[2]), "r"(a[3]), "r"(b[0]), "r"(b[1]));
}

__device__ __forceinline__ uint32_t pack_bf2(float x, float y) {
    __nv_bfloat162 t;
    t.x = __float2bfloat16(x);
    t.y = __float2bfloat16(y);
    return *(uint32_t*)&t;
}
__device__ __forceinline__ uint32_t pack_h2(float x, float y) {
    __half2 t = __floats2half2_rn(x, y);
    return *(uint32_t*)&t;
}

// ---------------------------------------------------------------------------
// Conversion / table kernels
// ---------------------------------------------------------------------------
__global__ void __launch_bounds__(256) transpose_convert_all_kernel(
    const float* __restrict__ wq, const float* __restrict__ wk,
    const float* __restrict__ wv, const float* __restrict__ wo)
{
    const int z = blockIdx.z;
    const float* src;
    int C, row_off;
    __nv_bfloat16 *dhi, *dlo;
    if (z == 0)      { src = wq; C = 2048; row_off = 0;    dhi = g_wthi;  dlo = g_wtlo;  }
    else if (z == 1) { if (blockIdx.x >= 32) return;
                       src = wk; C = 1024; row_off = 2048; dhi = g_wthi;  dlo = g_wtlo;  }
    else if (z == 2) { if (blockIdx.x >= 32) return;
                       src = wv; C = 1024; row_off = 3072; dhi = g_wthi;  dlo = g_wtlo;  }
    else             { src = wo; C = 2048; row_off = 0;    dhi = g_wothi; dlo = g_wotlo; }

    __shared__ float t[32][33];
    const int c0 = blockIdx.x * 32;
    const int r0 = blockIdx.y * 32;
    const int tx = threadIdx.x;
    const int ty = threadIdx.y;

#pragma unroll
    for (int j = 0; j < 4; j++)
        t[ty + j * 8][tx] = src[(size_t)(r0 + ty + j * 8) * C + c0 + tx];
    __syncthreads();

#pragma unroll
    for (int j = 0; j < 4; j++) {
        const int i = ty + j * 8;
        const float v = t[tx][i];
        const __nv_bfloat16 h = __float2bfloat16(v);
        const __nv_bfloat16 l = __float2bfloat16(v - __bfloat162float(h));
        const size_t off = (size_t)(row_off + c0 + i) * DD + r0 + tx;
        dhi[off] = h;
        dlo[off] = l;
    }
}

__global__ void __launch_bounds__(256) convert_split_x_kernel(const float* __restrict__ src)
{
    const size_t i = (size_t)blockIdx.x * blockDim.x + threadIdx.x;
    const size_t n4 = (size_t)TOK * DD / 4;
    if (i >= n4) return;
    const float4 v = ((const float4*)src)[i];
    __nv_bfloat16 h0 = __float2bfloat16(v.x);
    __nv_bfloat16 h1 = __float2bfloat16(v.y);
    __nv_bfloat16 h2 = __float2bfloat16(v.z);
    __nv_bfloat16 h3 = __float2bfloat16(v.w);
    uint2 hp, lp;
    hp.x = pack_bf2(v.x, v.y);
    hp.y = pack_bf2(v.z, v.w);
    lp.x = pack_bf2(v.x - __bfloat162float(h0), v.y - __bfloat162float(h1));
    lp.y = pack_bf2(v.z - __bfloat162float(h2), v.w - __bfloat162float(h3));
    ((uint2*)g_xhi)[i] = hp;
    ((uint2*)g_xlo)[i] = lp;
}

// RoPE tables: sin/cos per (token, freq-pair). One-time, full-precision.
__global__ void __launch_bounds__(256) rope_table_kernel(const int* __restrict__ pos_ids)
{
    const int idx = blockIdx.x * 256 + threadIdx.x;
    if (idx >= TOK * 64) return;
    const int token = idx >> 6;
    const int p = idx & 63;
    const double L2T = 19.931568569324174;   // log2(1e6)
    const float inv_ts = exp2f((float)(-(double)p * L2T / 64.0));
    const float ang = (float)pos_ids[token] * inv_ts;
    float sv, cv;
    sincosf(ang, &sv, &cv);
    g_rsin[idx] = sv;
    g_rcos[idx] = cv;
}

// ---------------------------------------------------------------------------
// split-bf16 warp-MMA GEMM (R15 exact): C = A * B^T, 128x128 tile, BK=32,
// 8 warps (2m x 4n), XOR swizzle, 3-stage ring, SPREAD prefetch.
// ---------------------------------------------------------------------------
#define BK 32
#define PITCH 64
#define MAT_BYTES (128 * PITCH)           // 8192 per split
#define STAGE_BYTES (4 * MAT_BYTES)       // 32768
#define GEMM_SMEM_BYTES (3 * STAGE_BYTES) // 98304 (x2 CTAs = 196KB)
#define EPI_PITCH 132                     // fp32 words per row in epilogue buffer

__device__ __forceinline__ uint32_t gswz(int r, int c) {
    return (uint32_t)(r * PITCH + ((c ^ ((r >> 1) & 3)) << 4));
}

__device__ __forceinline__ void prefetch_A(
    uint32_t sbase, const __nv_bfloat16* __restrict__ Ahi,
    const __nv_bfloat16* __restrict__ Alo, int m0, int k0, int j, int tid)
{
    const int id = tid * 2 + j;
    const int r = id >> 2;
    const int c = id & 3;
    const uint32_t soff = gswz(r, c);
    const size_t ga = (size_t)(m0 + r) * DD + k0 + c * 8;
    cp16(sbase + soff,             Ahi + ga);
    cp16(sbase + MAT_BYTES + soff, Alo + ga);
}
__device__ __forceinline__ void prefetch_B(
    uint32_t sbase, const __nv_bfloat16* __restrict__ Bhi,
    const __nv_bfloat16* __restrict__ Blo, int n0, int k0, int j, int tid)
{
    const int id = tid * 2 + j;
    const int r = id >> 2;
    const int c = id & 3;
    const uint32_t soff = gswz(r, c);
    const size_t gb = (size_t)(n0 + r) * DD + k0 + c * 8;
    cp16(sbase + 2 * MAT_BYTES + soff, Bhi + gb);
    cp16(sbase + 3 * MAT_BYTES + soff, Blo + gb);
}

__device__ __forceinline__ void prefetch_stage_full(
    uint32_t sbase,
    const __nv_bfloat16* __restrict__ Ahi, const __nv_bfloat16* __restrict__ Alo,
    const __nv_bfloat16* __restrict__ Bhi, const __nv_bfloat16* __restrict__ Blo,
    int m0, int n0, int k0, int tid)
{
    prefetch_A(sbase, Ahi, Alo, m0, k0, 0, tid);
    prefetch_B(sbase, Bhi, Blo, n0, k0, 0, tid);
    prefetch_A(sbase, Ahi, Alo, m0, k0, 1, tid);
    prefetch_B(sbase, Bhi, Blo, n0, k0, 1, tid);
}

template <int FUSED>
__device__ __forceinline__ void gemm_tile(
    const __nv_bfloat16* __restrict__ Ahi, const __nv_bfloat16* __restrict__ Alo,
    const __nv_bfloat16* __restrict__ Bhi, const __nv_bfloat16* __restrict__ Blo,
    float* __restrict__ Cc, int ldC, int m0, int n0,
    const float* __restrict__ qnw, const float* __restrict__ knw)
{
    const int tid  = threadIdx.x;             // 256 threads
    const int lane = tid & 31;
    const int wid  = tid >> 5;                // 0..7
    const int wm   = wid & 1;
    const int wn   = wid >> 1;
    const uint32_t smem_base = smem_u32(dyn_smem);

    float c[4][4][4];
#pragma unroll
    for (int i = 0; i < 4; i++)
#pragma unroll
        for (int j = 0; j < 4; j++)
#pragma unroll
            for (int k = 0; k < 4; k++) c[i][j][k] = 0.f;

    const int a_row  = wm * 64 + (lane & 15);
    const int a_swz  = (a_row >> 1) & 3;
    const uint32_t a_base = (uint32_t)(a_row * PITCH);
    const int a_c0   = lane >> 4;
    const int b_row  = wn * 32 + (lane & 7) + ((lane >> 4) << 3);
    const int b_swz  = (b_row >> 1) & 3;
    const uint32_t b_base = (uint32_t)(b_row * PITCH);
    const int b_c0   = (lane >> 3) & 1;

    const int nk = DD / BK;

    prefetch_stage_full(smem_base, Ahi, Alo, Bhi, Blo, m0, n0, 0, tid);
    CP_COMMIT();
    prefetch_stage_full(smem_base + STAGE_BYTES, Ahi, Alo, Bhi, Blo, m0, n0, BK, tid);
    CP_COMMIT();

    int slot = 0;
    for (int it = 0; it < nk; it++) {
        if (it < nk - 1) { CP_WAIT(1); } else { CP_WAIT(0); }
        __syncthreads();

        const bool pf = (it + 2 < nk);
        int ps = slot + 2;
        if (ps >= 3) ps -= 3;
        const uint32_t pbase = smem_base + ps * STAGE_BYTES;
        const int pk = (it + 2) * BK;

        const uint32_t sA = smem_base + slot * STAGE_BYTES;
        const uint32_t sB = sA + 2 * MAT_BYTES;

#pragma unroll
        for (int kf = 0; kf < 2; kf++) {
            uint32_t b[2][2][4];
            const uint32_t a_coff = (uint32_t)(((a_c0 + kf * 2) ^ a_swz) << 4);
            const uint32_t b_coff = (uint32_t)(((b_c0 + kf * 2) ^ b_swz) << 4);
#pragma unroll
            for (int nf2 = 0; nf2 < 2; nf2++) {
                const uint32_t bd = sB + b_base + nf2 * (16 * PITCH) + b_coff;
                ldsm4(b[0][nf2], bd);
                ldsm4(b[1][nf2], bd + MAT_BYTES);
            }
            if (pf) prefetch_A(pbase, Ahi, Alo, m0, pk, kf, tid);
#pragma unroll
            for (int mf = 0; mf < 4; mf++) {
                uint32_t ah[4], al[4];
                const uint32_t ad = sA + a_base + mf * (16 * PITCH) + a_coff;
                ldsm4(ah, ad);
                ldsm4(al, ad + MAT_BYTES);
                if (pf && mf == 2) prefetch_B(pbase, Bhi, Blo, n0, pk, kf, tid);
#pragma unroll
                for (int nf = 0; nf < 4; nf++)
                    mma_bf16(c[mf][nf], ah, &b[0][nf >> 1][(nf & 1) * 2]);
#pragma unroll
                for (int nf = 0; nf < 4; nf++)
                    mma_bf16(c[mf][nf], ah, &b[1][nf >> 1][(nf & 1) * 2]);
#pragma unroll
                for (int nf = 0; nf < 4; nf++)
                    mma_bf16(c[mf][nf], al, &b[0][nf >> 1][(nf & 1) * 2]);
            }
        }
        if (pf) CP_COMMIT();

        if (++slot == 3) slot = 0;
    }

    const int gr = lane >> 2;
    const int gc = (lane & 3) * 2;

    if (FUSED == 0) {
        const int row0 = m0 + wm * 64;
        const int col0 = n0 + wn * 32;
#pragma unroll
        for (int mf = 0; mf < 4; mf++)
#pragma unroll
            for (int nf = 0; nf < 4; nf++) {
                float* cc = c[mf][nf];
                const int r = row0 + mf * 16 + gr;
                const int cl = col0 + nf * 8 + gc;
                *(float2*)&Cc[(size_t)r * ldC + cl]       = make_float2(cc[0], cc[1]);
                *(float2*)&Cc[(size_t)(r + 8) * ldC + cl] = make_float2(cc[2], cc[3]);
            }
        return;
    }

    // --- FUSED epilogue: SMEM bounce + RMSNorm + RoPE + q/k->fp16, v->split ---
    float* Sb = (float*)dyn_smem;
    __syncthreads();
    {
        const int row0 = wm * 64;
        const int col0 = wn * 32;
#pragma unroll
        for (int mf = 0; mf < 4; mf++)
#pragma unroll
            for (int nf = 0; nf < 4; nf++) {
                float* cc = c[mf][nf];
                const int r = row0 + mf * 16 + gr;
                const int cl = col0 + nf * 8 + gc;
                *(float2*)&Sb[r * EPI_PITCH + cl]       = make_float2(cc[0], cc[1]);
                *(float2*)&Sb[(r + 8) * EPI_PITCH + cl] = make_float2(cc[2], cc[3]);
            }
    }
    __syncthreads();

    const bool isq = (n0 < 2048);
    const bool isv = (n0 >= 3072);
    int colbase, ldd;
    __half* d16 = nullptr;
    if (isq)              { d16 = g_q16; colbase = n0;        ldd = 2048; }
    else if (n0 < 3072)   { d16 = g_k16; colbase = n0 - 2048; ldd = 1024; }
    else                  { colbase = n0 - 3072; ldd = 1024; }

    const float QS = isq ? 0.08838834764831845f * 1.4426950408889634f : 1.0f;
    const bool firsthalf = lane < 16;
    const int pbase2 = (lane & 15) * 4;

    float4 w4 = make_float4(1.f, 1.f, 1.f, 1.f);
    if (!isv) {
        const float* nw = isq ? qnw : knw;
        w4 = *(const float4*)&nw[lane * 4];
    }

#pragma unroll 1
    for (int i = 0; i < 16; i++) {
        const int row = wid * 16 + i;
        const int token = m0 + row;
        float4 xv = *(float4*)&Sb[row * EPI_PITCH + lane * 4];
        if (!isv) {
            float ss = xv.x * xv.x + xv.y * xv.y + xv.z * xv.z + xv.w * xv.w;
#pragma unroll
            for (int m = 16; m; m >>= 1) ss += __shfl_xor_sync(0xffffffffu, ss, m);
            const float rinv = rsqrtf(ss * (1.0f / HDIM) + EPSV);
            const float nn0 = xv.x * w4.x * rinv;
            const float nn1 = xv.y * w4.y * rinv;
            const float nn2 = xv.z * w4.z * rinv;
            const float nn3 = xv.w * w4.w * rinv;
            const float pp0 = __shfl_xor_sync(0xffffffffu, nn0, 16);
            const float pp1 = __shfl_xor_sync(0xffffffffu, nn1, 16);
            const float pp2 = __shfl_xor_sync(0xffffffffu, nn2, 16);
            const float pp3 = __shfl_xor_sync(0xffffffffu, nn3, 16);
            const float4 sn = *(const float4*)&g_rsin[(size_t)token * 64 + pbase2];
            const float4 cs = *(const float4*)&g_rcos[(size_t)token * 64 + pbase2];
            float r0, r1, r2, r3;
            if (firsthalf) {
                r0 = (nn0 * cs.x - pp0 * sn.x) * QS;
                r1 = (nn1 * cs.y - pp1 * sn.y) * QS;
                r2 = (nn2 * cs.z - pp2 * sn.z) * QS;
                r3 = (nn3 * cs.w - pp3 * sn.w) * QS;
            } else {
                r0 = (nn0 * cs.x + pp0 * sn.x) * QS;
                r1 = (nn1 * cs.y + pp1 * sn.y) * QS;
                r2 = (nn2 * cs.z + pp2 * sn.z) * QS;
                r3 = (nn3 * cs.w + pp3 * sn.w) * QS;
            }
            uint2 hv;
            hv.x = pack_h2(r0, r1);
            hv.y = pack_h2(r2, r3);
            *(uint2*)&d16[(size_t)token * ldd + colbase + lane * 4] = hv;
        } else {
            const __nv_bfloat16 h0 = __float2bfloat16(xv.x);
            const __nv_bfloat16 h1 = __float2bfloat16(xv.y);
            const __nv_bfloat16 h2 = __float2bfloat16(xv.z);
            const __nv_bfloat16 h3 = __float2bfloat16(xv.w);
            uint2 hp, lp;
            hp.x = pack_bf2(xv.x, xv.y);
            hp.y = pack_bf2(xv.z, xv.w);
            lp.x = pack_bf2(xv.x - __bfloat162float(h0), xv.y - __bfloat162float(h1));
            lp.y = pack_bf2(xv.z - __bfloat162float(h2), xv.w - __bfloat162float(h3));
            const size_t off = (size_t)token * ldd + colbase + lane * 4;
            *(uint2*)&g_vhi[off] = hp;
            *(uint2*)&g_vlo[off] = lp;
        }
    }
}

// qkv: wave-launched
__global__ void __launch_bounds__(256, 2) gemm_qkv_kernel(
    const float* __restrict__ qnw, const float* __restrict__ knw) {
    gemm_tile<1>(g_xhi, g_xlo, g_wthi, g_wtlo, nullptr, 0,
                 blockIdx.y * 128, blockIdx.x * 128, qnw, knw);
}

// out: persistent
__global__ void __launch_bounds__(256, 2) gemm_out_kernel(float* __restrict__ out) {
    for (int t = blockIdx.x; t < 512; t += gridDim.x) {
        const int m0 = (t / 16) * 128;
        const int n0 = (t % 16) * 128;
        __syncthreads();   // previous tile's smem reads complete
        gemm_tile<0>(g_ohi, g_olo, g_wothi, g_wotlo, out, DD, m0, n0,
                     nullptr, nullptr);
    }
}

// ---------------------------------------------------------------------------
// Flash attention. R17: QK path in single fp16 (q,k fp16 -> 1 MMA per frag
// pair, 1/3 the QK MMAs; K smem/traffic halves). PV stays split-bf16 x3.
// Software-pipelined QK-ahead, 3-stage ring (52KB/stage), distance-2 waits.
// Stage layout: K16 | Vhi | Vlo (17408B each).
// ---------------------------------------------------------------------------
#define FLP 272
#define FL_KSZ (64 * FLP)           // 17408 per matrix
#define FL_STAGE (3 * FL_KSZ)       // 52224
#define FL_SMEM (3 * FL_STAGE)      // 156672

// part p of KV prefetch (p=0:K16 1:Vhi 2:Vlo), 4 cp16/thread
__device__ __forceinline__ void fl_prefetch_part(
    uint32_t sbase, int b, int kvh, int kv0, int tid, int p)
{
#pragma unroll
    for (int u = 0; u < 4; u++) {
        const int row = (u << 4) + (tid >> 4);       // 0..63
        const int ch = tid & 15;
        const void* g;
        const size_t eoff = (size_t)(b * LL + kv0 + row) * 1024 + kvh * HDIM + ch * 8;
        if (p == 0)      g = g_k16 + eoff;
        else if (p == 1) g = g_vhi + eoff;
        else             g = g_vlo + eoff;
        cp16(sbase + p * FL_KSZ + row * FLP + ch * 16, g);
    }
}

// S = Q K^T, single fp16 product
__device__ __forceinline__ void fl_qk(
    float (&s)[8][4], const uint32_t (&qf)[8][4], uint32_t sK, uint32_t bk_off)
{
#pragma unroll
    for (int i = 0; i < 8; i++)
#pragma unroll
        for (int j = 0; j < 4; j++) s[i][j] = 0.f;
#pragma unroll
    for (int kf = 0; kf < 8; kf++) {
        uint32_t bh[4][4];
#pragma unroll
        for (int p2 = 0; p2 < 4; p2++)
            ldsm4(bh[p2], sK + bk_off + p2 * 16 * FLP + kf * 32);
#pragma unroll
        for (int p2 = 0; p2 < 4; p2++) {
            mma_f16(s[2 * p2],     qf[kf], bh[p2]);
            mma_f16(s[2 * p2 + 1], qf[kf], bh[p2] + 2);
        }
    }
}

__device__ __forceinline__ void fl_pv(
    float (&acc)[16][4], const float (&p)[8][4], uint32_t sVhi, uint32_t v_off)
{
    const uint32_t sVlo = sVhi + FL_KSZ;
#pragma unroll
    for (int j = 0; j < 4; j++) {
        uint32_t ph[4], pl[4];
#pragma unroll
        for (int q = 0; q < 4; q++) {
            const int nf = 2 * j + (q >> 1);
            const int rb = (q & 1) * 2;
            const float v0 = p[nf][rb], v1 = p[nf][rb + 1];
            const __nv_bfloat16 h0 = __float2bfloat16(v0);
            const __nv_bfloat16 h1 = __float2bfloat16(v1);
            ph[q] = pack_bf2(v0, v1);
            pl[q] = pack_bf2(v0 - __bfloat162float(h0), v1 - __bfloat162float(h1));
        }
#pragma unroll
        for (int t2 = 0; t2 < 4; t2++) {
            uint32_t vh0[4], vl0[4], vh1[4], vl1[4];
            const uint32_t vb = sVhi + v_off + j * 16 * FLP;
            const uint32_t lb = sVlo + v_off + j * 16 * FLP;
            ldsm4t(vh0, vb + (2 * t2) * 32);
            ldsm4t(vl0, lb + (2 * t2) * 32);
            ldsm4t(vh1, vb + (2 * t2 + 1) * 32);
            ldsm4t(vl1, lb + (2 * t2 + 1) * 32);
            float* a0 = acc[4 * t2];
            float* a1 = acc[4 * t2 + 1];
            float* a2 = acc[4 * t2 + 2];
            float* a3 = acc[4 * t2 + 3];
            mma_bf16(a0, ph, vh0); mma_bf16(a1, ph, vh0 + 2);
            mma_bf16(a2, ph, vh1); mma_bf16(a3, ph, vh1 + 2);
            mma_bf16(a0, ph, vl0); mma_bf16(a1, ph, vl0 + 2);
            mma_bf16(a2, ph, vl1); mma_bf16(a3, ph, vl1 + 2);
            mma_bf16(a0, pl, vh0); mma_bf16(a1, pl, vh0 + 2);
            mma_bf16(a2, pl, vh1); mma_bf16(a3, pl, vh1 + 2);
        }
    }
}

// mask + online softmax; lsum kept as per-lane partial (reduced at finalize)
__device__ __forceinline__ void fl_softmax(
    float (&sfr)[8][4], float (&acc)[16][4], float (&m2)[2], float (&lsum)[2],
    int it, int m0, int wid, int lane)
{
    const int rbase = m0 + wid * 16 + (lane >> 2);
    if (it * 64 + 63 > m0 + wid * 16) {
#pragma unroll
        for (int nf = 0; nf < 8; nf++) {
            const int cg = it * 64 + nf * 8 + 2 * (lane & 3);
#pragma unroll
            for (int rg = 0; rg < 4; rg++) {
                const int row = rbase + (rg >> 1) * 8;
                const int col = cg + (rg & 1);
                if (col > row) sfr[nf][rg] = -1e30f;
            }
        }
    }
#pragma unroll
    for (int h = 0; h < 2; h++) {
        float tm = -1e30f;
#pragma unroll
        for (int nf = 0; nf < 8; nf++)
            tm = fmaxf(tm, fmaxf(sfr[nf][2 * h], sfr[nf][2 * h + 1]));
        tm = fmaxf(tm, __shfl_xor_sync(0xffffffffu, tm, 1));
        tm = fmaxf(tm, __shfl_xor_sync(0xffffffffu, tm, 2));
        const float mn = fmaxf(m2[h], tm);
        const float corr = exp2f(m2[h] - mn);
        m2[h] = mn;
        float rs = 0.f;
#pragma unroll
        for (int nf = 0; nf < 8; nf++) {
            const float e0 = exp2f(sfr[nf][2 * h] - mn);
            const float e1 = exp2f(sfr[nf][2 * h + 1] - mn);
            sfr[nf][2 * h] = e0;
            sfr[nf][2 * h + 1] = e1;
            rs += e0 + e1;
        }
        lsum[h] = lsum[h] * corr + rs;
#pragma unroll
        for (int nf = 0; nf < 16; nf++) {
            acc[nf][2 * h] *= corr;
            acc[nf][2 * h + 1] *= corr;
        }
    }
}

__global__ void __launch_bounds__(256, 1) flash_kernel()
{
    const int tid = threadIdx.x;
    const int lane = tid & 31;
    const int wid = tid >> 5;
    const int b = blockIdx.z;
    const int n = blockIdx.y;
    const int mt = (int)gridDim.x - 1 - (int)blockIdx.x;  // big tiles launch first
    const int kvh = n >> 1;
    const int m0 = mt * 128;

    const uint32_t sb = smem_u32(dyn_smem);

    // group 0: Q (fp16, 128 rows x 128 cols, staged through stage 0)
#pragma unroll
    for (int u = 0; u < 8; u++) {
        const int row = (u << 4) + (tid >> 4);
        const int ch = tid & 15;
        const __half* g = g_q16 +
            (size_t)(b * LL + m0 + row) * 2048 + n * HDIM + ch * 8;
        cp16(sb + row * FLP + ch * 16, g);
    }
    CP_COMMIT();
    // group 1: KV0 (stage 1, all three parts)
    fl_prefetch_part(sb + 1 * FL_STAGE, b, kvh, 0, tid, 0);
    fl_prefetch_part(sb + 1 * FL_STAGE, b, kvh, 0, tid, 1);
    fl_prefetch_part(sb + 1 * FL_STAGE, b, kvh, 0, tid, 2);
    CP_COMMIT();
    // group 2: K1 (stage 2)
    fl_prefetch_part(sb + 2 * FL_STAGE, b, kvh, 64, tid, 0);
    CP_COMMIT();
    // group 3: V1 (stage 2)
    fl_prefetch_part(sb + 2 * FL_STAGE, b, kvh, 64, tid, 1);
    fl_prefetch_part(sb + 2 * FL_STAGE, b, kvh, 64, tid, 2);
    CP_COMMIT();

    const uint32_t a_off = (uint32_t)((wid * 16 + (lane & 15)) * FLP + (lane >> 4) * 16);
    const uint32_t bk_off = (uint32_t)(((lane & 7) + ((lane >> 4) << 3)) * FLP +
                                       ((lane >> 3) & 1) * 16);
    const uint32_t v_off = (uint32_t)(((lane & 7) + ((lane >> 3) & 1) * 8) * FLP +
                                      (lane >> 4) * 16);

    CP_WAIT(2);          // Q + KV0 landed (K1, V1 may be in flight)
    __syncthreads();
    uint32_t qf[8][4];
#pragma unroll
    for (int kf = 0; kf < 8; kf++)
        ldsm4(qf[kf], sb + a_off + kf * 32);

    float acc[16][4];
#pragma unroll
    for (int i = 0; i < 16; i++)
#pragma unroll
        for (int j = 0; j < 4; j++) acc[i][j] = 0.f;
    float m2[2] = {-1e30f, -1e30f};
    float lsum[2] = {0.f, 0.f};

    float sA[8][4], sB[8][4];
    const int nkv = 2 * (mt + 1);    // always even

    // prologue: QK(0) from stage 1 (KV0 landed)
    fl_qk(sA, qf, sb + 1 * FL_STAGE, bk_off);

#define FL_ITER(IT, CUR, NXT)                                                  \
    {                                                                          \
        if ((IT) + 1 < nkv) { CP_WAIT(1); } else { CP_WAIT(0); }               \
        __syncthreads();     /* visibility + stage (IT)%3 free for refill */   \
        const bool pf = ((IT) + 2 < nkv);                                      \
        const uint32_t ns = sb + ((IT) % 3) * FL_STAGE;                        \
        const int nkv0 = ((IT) + 2) * 64;                                      \
        if (pf) {                                                              \
            fl_prefetch_part(ns, b, kvh, nkv0, tid, 0);                        \
            CP_COMMIT();     /* K(IT+2) group — EARLY */                       \
        }                                                                      \
        fl_softmax(CUR, acc, m2, lsum, (IT), m0, wid, lane);                   \
        if (pf) fl_prefetch_part(ns, b, kvh, nkv0, tid, 1);                    \
        if ((IT) + 1 < nkv)                                                    \
            fl_qk(NXT, qf, sb + (((IT) + 2) % 3) * FL_STAGE, bk_off);          \
        if (pf) {                                                              \
            fl_prefetch_part(ns, b, kvh, nkv0, tid, 2);                        \
            CP_COMMIT();     /* V(IT+2) group — LATE */                        \
        }                                                                      \
        fl_pv(acc, CUR, sb + (((IT) + 1) % 3) * FL_STAGE + FL_KSZ, v_off);     \
    }

    for (int it = 0; it < nkv; it += 2) {
        FL_ITER(it, sA, sB);
        FL_ITER(it + 1, sB, sA);
    }
#undef FL_ITER

    // --- finalize: reduce lsum across the 4 lanes of each row, /l, split ---
#pragma unroll
    for (int h = 0; h < 2; h++) {
        float ls = lsum[h];
        ls += __shfl_xor_sync(0xffffffffu, ls, 1);
        ls += __shfl_xor_sync(0xffffffffu, ls, 2);
        const float inv = 1.0f / ls;
        const int row = m0 + wid * 16 + (lane >> 2) + h * 8;
        const size_t base = (size_t)(b * LL + row) * 2048 + n * HDIM + 2 * (lane & 3);
#pragma unroll
        for (int nf = 0; nf < 16; nf++) {
            const float v0 = acc[nf][2 * h] * inv;
            const float v1 = acc[nf][2 * h + 1] * inv;
            const __nv_bfloat16 h0 = __float2bfloat16(v0);
            const __nv_bfloat16 h1 = __float2bfloat16(v1);
            *(uint32_t*)&g_ohi[base + nf * 8] = pack_bf2(v0, v1);
            *(uint32_t*)&g_olo[base + nf * 8] =
                pack_bf2(v0 - __bfloat162float(h0), v1 - __bfloat162float(h1));
        }
    }
}

// ---------------------------------------------------------------------------
// Launch
// ---------------------------------------------------------------------------
extern "C" void kernel_launch(void* const* d_in, const int* in_sizes, int n_in,
                              void* d_out, int out_size)
{
    const float* x   = (const float*)d_in[0];
    const int*   pos = (const int*)d_in[1];
    // d_in[2] = attn_mask (causal tril) — implied analytically, unused
    const float* wq  = (const float*)d_in[3];
    const float* wk  = (const float*)d_in[4];
    const float* wv  = (const float*)d_in[5];
    const float* wo  = (const float*)d_in[6];
    const float* qnw = (const float*)d_in[7];
    const float* knw = (const float*)d_in[8];
    float* out = (float*)d_out;

    cudaFuncSetAttribute(gemm_qkv_kernel,
                         cudaFuncAttributeMaxDynamicSharedMemorySize, GEMM_SMEM_BYTES);
    cudaFuncSetAttribute(gemm_out_kernel,
                         cudaFuncAttributeMaxDynamicSharedMemorySize, GEMM_SMEM_BYTES);
    cudaFuncSetAttribute(flash_kernel,
                         cudaFuncAttributeMaxDynamicSharedMemorySize, FL_SMEM);

    int dev = 0, sms = 148;
    cudaGetDevice(&dev);
    cudaDeviceGetAttribute(&sms, cudaDevAttrMultiProcessorCount, dev);

    // 1. weights -> transposed bf16 hi/lo + rope tables + split X
    transpose_convert_all_kernel<<<dim3(64, 64, 4), dim3(32, 8)>>>(wq, wk, wv, wo);
    rope_table_kernel<<<(TOK * 64 + 255) / 256, 256>>>(pos);
    convert_split_x_kernel<<<(TOK * DD / 4 + 255) / 256, 256>>>(x);

    // 2. QKV projection (wave-launched, fused epilogue -> fp16 q/k, split v)
    gemm_qkv_kernel<<<dim3(QKVW / 128, TOK / 128), 256, GEMM_SMEM_BYTES>>>(qnw, knw);

    // 3. Flash attention (fp16 QK, split-bf16 PV)
    flash_kernel<<<dim3(LL / 128, NHEADS, BB), 256, FL_SMEM>>>();

    // 4. output projection (persistent, spread prefetch)
    gemm_out_kernel<<<sms * 2, 256, GEMM_SMEM_BYTES>>>(out);
}